// round 2
// baseline (speedup 1.0000x reference)
#include <cuda_runtime.h>
#include <math.h>

// Problem constants
#define BB 4
#define HH 16
#define NN 4096
#define DD 64
#define MM 256
#define BH 64            // B*H
#define NSPLIT 8
#define NCHUNK 512       // NN / NSPLIT
#define TN 32            // n-tile inside kernel1
#define TNQ 128          // q rows per block in kernel2
#define EPSF 1e-6f

typedef unsigned long long ull;

// ---------------- scratch (no allocations allowed) ----------------
__device__ float g_ctxp[(size_t)BH * NSPLIT * MM * DD];   // partial contexts, 32 MB
__device__ float g_ksump[(size_t)BH * NSPLIT * MM];       // partial k-sums
__device__ float g_ctx[(size_t)BH * MM * DD];             // reduced contexts, 4 MB
__device__ float g_ksum[(size_t)BH * MM];                 // reduced k-sums

// ---------------- f32x2 helpers (2x fp32 FMA throughput on sm_103a) ----------------
__device__ __forceinline__ ull pack2(float x, float y) {
    ull r; asm("mov.b64 %0, {%1, %2};" : "=l"(r) : "f"(x), "f"(y)); return r;
}
__device__ __forceinline__ void unpack2(ull u, float& x, float& y) {
    asm("mov.b64 {%0, %1}, %2;" : "=f"(x), "=f"(y) : "l"(u));
}
__device__ __forceinline__ ull fma2(ull a, ull b, ull c) {
    ull d; asm("fma.rn.f32x2 %0, %1, %2, %3;" : "=l"(d) : "l"(a), "l"(b), "l"(c)); return d;
}
__device__ __forceinline__ ull mul2(ull a, ull b) {
    ull d; asm("mul.rn.f32x2 %0, %1, %2;" : "=l"(d) : "l"(a), "l"(b)); return d;
}

__device__ __forceinline__ float gelu_eps(float x) {
    // exact (erf-based) GELU, matching jax.nn.gelu(approximate=False), plus EPS
    return 0.5f * x * (1.0f + erff(x * 0.70710678118654752f)) + EPSF;
}

// =====================================================================
// Kernel 1: per (bh, split): kp = gelu(K @ P^T)+eps;
//           ctx_partial += kp^T @ V;  ksum_partial += colsum(kp)
// =====================================================================
__global__ __launch_bounds__(256) void perf_ctx_kernel(
    const float* __restrict__ Kg_, const float* __restrict__ Vg_,
    const float* __restrict__ Pg)
{
    extern __shared__ float sm[];
    float* Pt  = sm;                   // [DD][MM]  P transposed: Pt[d][m]
    float* Ks  = Pt + DD * MM;         // [TN][DD]
    float* Vs  = Ks + TN * DD;         // [TN][DD]
    float* KPs = Vs + TN * DD;         // [TN][MM]

    const int tid = threadIdx.x;
    const int bh = blockIdx.y, sp = blockIdx.x;
    const float* Kg = Kg_ + ((size_t)bh * NN + (size_t)sp * NCHUNK) * DD;
    const float* Vg = Vg_ + ((size_t)bh * NN + (size_t)sp * NCHUNK) * DD;

    // Build Pt (transposed projection) once
    for (int i = tid; i < MM * DD; i += 256) {
        int m = i >> 6, d = i & 63;
        Pt[d * MM + m] = Pg[i];
    }

    // GEMM1 mapping: whole warp shares one n-group (broadcast K loads)
    const int mg1 = tid & 31, ng1 = tid >> 5;
    const int m0a = mg1 * 8, n0a = ng1 * 4;
    // GEMM2 mapping: 8x8 ctx tile per thread (packed along d)
    const int dg2 = tid & 7, mg2 = tid >> 3;
    const int d0b = dg2 * 8, m0b = mg2 * 8;

    ull ctx2[8][4];
    float ksum_l[8];
    #pragma unroll
    for (int i = 0; i < 8; i++) {
        ksum_l[i] = 0.0f;
        #pragma unroll
        for (int j = 0; j < 4; j++) ctx2[i][j] = 0ull;  // two packed +0.0f
    }

    for (int nt = 0; nt < NCHUNK / TN; nt++) {
        const float4* Kg4 = reinterpret_cast<const float4*>(Kg + (size_t)nt * TN * DD);
        const float4* Vg4 = reinterpret_cast<const float4*>(Vg + (size_t)nt * TN * DD);
        for (int i = tid; i < TN * DD / 4; i += 256) {
            reinterpret_cast<float4*>(Ks)[i] = Kg4[i];
            reinterpret_cast<float4*>(Vs)[i] = Vg4[i];
        }
        __syncthreads();

        // ---- GEMM1: kp[TN][MM] = K[TN][DD] @ Pt ----
        ull a2[4][4];
        #pragma unroll
        for (int i = 0; i < 4; i++)
            #pragma unroll
            for (int j = 0; j < 4; j++) a2[i][j] = 0ull;

        #pragma unroll 8
        for (int d = 0; d < DD; d++) {
            ull kb[4];
            #pragma unroll
            for (int i = 0; i < 4; i++) {
                float kv = Ks[(n0a + i) * DD + d];   // warp-broadcast
                kb[i] = pack2(kv, kv);
            }
            ull p2[4];
            #pragma unroll
            for (int j = 0; j < 4; j++)
                p2[j] = *reinterpret_cast<const ull*>(&Pt[d * MM + m0a + 2 * j]);
            #pragma unroll
            for (int i = 0; i < 4; i++)
                #pragma unroll
                for (int j = 0; j < 4; j++)
                    a2[i][j] = fma2(kb[i], p2[j], a2[i][j]);
        }
        // gelu + eps, store kp tile
        #pragma unroll
        for (int i = 0; i < 4; i++) {
            #pragma unroll
            for (int j = 0; j < 4; j++) {
                float x0, x1; unpack2(a2[i][j], x0, x1);
                *reinterpret_cast<ull*>(&KPs[(n0a + i) * MM + m0a + 2 * j]) =
                    pack2(gelu_eps(x0), gelu_eps(x1));
            }
        }
        __syncthreads();

        // ---- GEMM2: ctx += kp^T @ V ; ksum += colsum(kp) ----
        #pragma unroll 2
        for (int n = 0; n < TN; n++) {
            float kpv[8];
            #pragma unroll
            for (int j = 0; j < 4; j++) {
                ull t = *reinterpret_cast<const ull*>(&KPs[n * MM + m0b + 2 * j]);
                unpack2(t, kpv[2 * j], kpv[2 * j + 1]);
            }
            ull v2[4];
            #pragma unroll
            for (int j = 0; j < 4; j++)
                v2[j] = *reinterpret_cast<const ull*>(&Vs[n * DD + d0b + 2 * j]);
            if (dg2 == 0) {
                #pragma unroll
                for (int mi = 0; mi < 8; mi++) ksum_l[mi] += kpv[mi];
            }
            #pragma unroll
            for (int mi = 0; mi < 8; mi++) {
                ull kb = pack2(kpv[mi], kpv[mi]);
                #pragma unroll
                for (int j = 0; j < 4; j++)
                    ctx2[mi][j] = fma2(kb, v2[j], ctx2[mi][j]);
            }
        }
        __syncthreads();
    }

    // write partials
    float* op = g_ctxp + ((size_t)(bh * NSPLIT) + sp) * MM * DD;
    #pragma unroll
    for (int mi = 0; mi < 8; mi++)
        #pragma unroll
        for (int j = 0; j < 4; j++)
            *reinterpret_cast<ull*>(&op[(m0b + mi) * DD + d0b + 2 * j]) = ctx2[mi][j];
    if (dg2 == 0) {
        float* kp_ = g_ksump + ((size_t)bh * NSPLIT + sp) * MM;
        #pragma unroll
        for (int mi = 0; mi < 8; mi++) kp_[m0b + mi] = ksum_l[mi];
    }
}

// =====================================================================
// Kernel R: deterministic reduction of split partials
// =====================================================================
__global__ __launch_bounds__(256) void perf_reduce_kernel()
{
    const int bh = blockIdx.x, tid = threadIdx.x;
    const float* src = g_ctxp + (size_t)bh * NSPLIT * MM * DD;
    float* dst = g_ctx + (size_t)bh * MM * DD;
    for (int i = tid; i < MM * DD; i += 256) {
        float s = 0.0f;
        #pragma unroll
        for (int sp = 0; sp < NSPLIT; sp++) s += src[(size_t)sp * MM * DD + i];
        dst[i] = s;
    }
    const float* srck = g_ksump + (size_t)bh * NSPLIT * MM;
    float* dstk = g_ksum + (size_t)bh * MM;
    for (int i = tid; i < MM; i += 256) {
        float s = 0.0f;
        #pragma unroll
        for (int sp = 0; sp < NSPLIT; sp++) s += srck[sp * MM + i];
        dstk[i] = s;
    }
}

// =====================================================================
// Kernel 2: qp = gelu(Q @ P^T)+eps; denom = qp.ksum; out = (qp @ ctx) / denom
// =====================================================================
#define QS_STRIDE 70   // padded row (conflict-free broadcast, 8B aligned)

__global__ __launch_bounds__(256) void perf_out_kernel(
    const float* __restrict__ Qg_, const float* __restrict__ Pg,
    float* __restrict__ Og_)
{
    extern __shared__ float sm[];
    float* Qs     = sm;                           // [TNQ][QS_STRIDE]
    float* QPs    = Qs + TNQ * QS_STRIDE;         // [TNQ][QS_STRIDE] (64 cols used)
    float* Ptc    = QPs + TNQ * QS_STRIDE;        // [DD][64]  chunk of P, transposed
    float* Cs     = Ptc + DD * 64;                // [64][DD]  chunk of ctx
    float* ksum_s = Cs + 64 * DD;                 // [64]
    float* denomS = ksum_s + 64;                  // [TNQ]

    const int tid = threadIdx.x;
    const int bh = blockIdx.y, qt = blockIdx.x;
    const float* Qg = Qg_ + ((size_t)bh * NN + (size_t)qt * TNQ) * DD;
    float* Og = Og_ + ((size_t)bh * NN + (size_t)qt * TNQ) * DD;
    const float* Cg  = g_ctx + (size_t)bh * MM * DD;
    const float* KSg = g_ksum + (size_t)bh * MM;

    for (int i = tid; i < TNQ * DD; i += 256) {
        int n = i >> 6, d = i & 63;
        Qs[n * QS_STRIDE + d] = Qg[i];
    }

    const int ng = tid >> 3, xg = tid & 7;
    const int n0 = ng * 4, x0 = xg * 8;   // x0: m-offset in GEMM1, d-offset in GEMM2

    ull outa[4][4];
    float dena[4] = {0.f, 0.f, 0.f, 0.f};
    #pragma unroll
    for (int i = 0; i < 4; i++)
        #pragma unroll
        for (int j = 0; j < 4; j++) outa[i][j] = 0ull;

    for (int mc = 0; mc < MM / 64; mc++) {
        for (int i = tid; i < 64 * DD; i += 256) {
            int m = i >> 6, d = i & 63;
            Ptc[d * 64 + m] = Pg[(mc * 64 + m) * DD + d];
            Cs[i] = Cg[(size_t)mc * 64 * DD + i];
        }
        if (tid < 64) ksum_s[tid] = KSg[mc * 64 + tid];
        __syncthreads();

        // ---- GEMM1: qp[TNQ][64] = Q @ Ptc ----
        ull b2[4][4];
        #pragma unroll
        for (int i = 0; i < 4; i++)
            #pragma unroll
            for (int j = 0; j < 4; j++) b2[i][j] = 0ull;

        #pragma unroll 8
        for (int d = 0; d < DD; d++) {
            ull qb[4];
            #pragma unroll
            for (int i = 0; i < 4; i++) {
                float qv = Qs[(n0 + i) * QS_STRIDE + d];
                qb[i] = pack2(qv, qv);
            }
            ull p2[4];
            #pragma unroll
            for (int j = 0; j < 4; j++)
                p2[j] = *reinterpret_cast<const ull*>(&Ptc[d * 64 + x0 + 2 * j]);
            #pragma unroll
            for (int i = 0; i < 4; i++)
                #pragma unroll
                for (int j = 0; j < 4; j++)
                    b2[i][j] = fma2(qb[i], p2[j], b2[i][j]);
        }
        #pragma unroll
        for (int i = 0; i < 4; i++) {
            #pragma unroll
            for (int j = 0; j < 4; j++) {
                float x0v, x1v; unpack2(b2[i][j], x0v, x1v);
                *reinterpret_cast<ull*>(&QPs[(n0 + i) * QS_STRIDE + x0 + 2 * j]) =
                    pack2(gelu_eps(x0v), gelu_eps(x1v));
            }
        }
        __syncthreads();

        // ---- GEMM2: out += qp @ ctx_chunk ; denom += qp . ksum_chunk ----
        #pragma unroll 2
        for (int mp = 0; mp < 64; mp++) {
            float qp[4];
            #pragma unroll
            for (int i = 0; i < 4; i++) qp[i] = QPs[(n0 + i) * QS_STRIDE + mp];
            ull c2[4];
            #pragma unroll
            for (int j = 0; j < 4; j++)
                c2[j] = *reinterpret_cast<const ull*>(&Cs[mp * 64 + x0 + 2 * j]);
            if (xg == 0) {
                float ks = ksum_s[mp];
                #pragma unroll
                for (int i = 0; i < 4; i++) dena[i] = fmaf(qp[i], ks, dena[i]);
            }
            #pragma unroll
            for (int i = 0; i < 4; i++) {
                ull qb = pack2(qp[i], qp[i]);
                #pragma unroll
                for (int j = 0; j < 4; j++)
                    outa[i][j] = fma2(qb, c2[j], outa[i][j]);
            }
        }
        __syncthreads();
    }

    if (xg == 0) {
        #pragma unroll
        for (int i = 0; i < 4; i++) denomS[n0 + i] = dena[i];
    }
    __syncthreads();

    #pragma unroll
    for (int i = 0; i < 4; i++) {
        float dinv = 1.0f / denomS[n0 + i];
        ull dv = pack2(dinv, dinv);
        #pragma unroll
        for (int j = 0; j < 4; j++)
            *reinterpret_cast<ull*>(&Og[(n0 + i) * DD + x0 + 2 * j]) = mul2(outa[i][j], dv);
    }
}

// =====================================================================
// launch
// =====================================================================
extern "C" void kernel_launch(void* const* d_in, const int* in_sizes, int n_in,
                              void* d_out, int out_size)
{
    const float* q    = (const float*)d_in[0];
    const float* k    = (const float*)d_in[1];
    const float* v    = (const float*)d_in[2];
    const float* proj = (const float*)d_in[3];
    float* out = (float*)d_out;

    const int SMEM1 = (DD * MM + 2 * TN * DD + TN * MM) * (int)sizeof(float);       // 112 KB
    const int SMEM2 = (2 * TNQ * QS_STRIDE + 2 * 64 * DD + 64 + TNQ) * (int)sizeof(float); // ~103 KB

    cudaFuncSetAttribute(perf_ctx_kernel, cudaFuncAttributeMaxDynamicSharedMemorySize, SMEM1);
    cudaFuncSetAttribute(perf_out_kernel, cudaFuncAttributeMaxDynamicSharedMemorySize, SMEM2);

    perf_ctx_kernel<<<dim3(NSPLIT, BH), 256, SMEM1>>>(k, v, proj);
    perf_reduce_kernel<<<BH, 256>>>();
    perf_out_kernel<<<dim3(NN / TNQ, BH), 256, SMEM2>>>(q, proj, out);
}

// round 4
// speedup vs baseline: 4.1149x; 4.1149x over previous
#include <cuda_runtime.h>
#include <cstdint>
#include <math.h>

// ---------------- problem constants ----------------
#define NN 4096
#define DD 64
#define MM 256
#define BH 64
#define NSPLIT 8
#define NCHUNK 512        // tokens per CTA (4 tiles of 128)
#define CW 72             // ctx width: 64 e-cols + ksum col + 7 pad (9 n8-frags)

typedef unsigned long long ull;

// ---------------- scratch (no allocs allowed) ----------------
__device__ float g_ctxp[(size_t)BH * NSPLIT * MM * CW];   // partials
__device__ float g_ctx [(size_t)BH * MM * CW];            // reduced

// ---------------- helpers ----------------
__device__ __forceinline__ float tf32r(float x) {
    uint32_t u; asm("cvt.rna.tf32.f32 %0, %1;" : "=r"(u) : "f"(x));
    return __uint_as_float(u);
}
__device__ __forceinline__ void mma8(float c[4],
    uint32_t a0, uint32_t a1, uint32_t a2, uint32_t a3,
    uint32_t b0, uint32_t b1)
{
    asm volatile("mma.sync.aligned.m16n8k8.row.col.f32.tf32.tf32.f32 "
        "{%0,%1,%2,%3}, {%4,%5,%6,%7}, {%8,%9}, {%0,%1,%2,%3};"
        : "+f"(c[0]), "+f"(c[1]), "+f"(c[2]), "+f"(c[3])
        : "r"(a0), "r"(a1), "r"(a2), "r"(a3), "r"(b0), "r"(b1));
}
__device__ __forceinline__ uint32_t f2u(float x) { return __float_as_uint(x); }

__device__ __forceinline__ float gelu_eps(float x) {
    return 0.5f * x * (1.0f + erff(x * 0.70710678118654752f)) + 1e-6f;
}

// ---------------- smem layouts (float indices) ----------------
// Phase 1: Ks[128][68] | Vs[128][76] | Ps[256][68] | kps[32][264]
#define P1_KS   0
#define P1_VS   8704
#define P1_PS   18432
#define P1_KP   35840
#define P1_TOT  44288            // 177152 bytes
// Phase 2: Qs[128][68] | Ps[256][68] | Cs[256][76] | qps[128][68] | denom[128]
#define P2_QS   0
#define P2_PS   8704
#define P2_CS   26112
#define P2_QP   45568
#define P2_DN   54272
#define P2_TOT  54400            // 217600 bytes

// =====================================================================
// Phase 1: kp = gelu(K@P^T)+eps ; ctx_partial = kp^T @ [V | 1 | 0]
// =====================================================================
__global__ __launch_bounds__(256, 1) void ph1_kernel(
    const float* __restrict__ Kg, const float* __restrict__ Vg,
    const float* __restrict__ Pg)
{
    extern __shared__ __align__(16) float sm[];
    float* Ks  = sm + P1_KS;
    float* Vs  = sm + P1_VS;
    float* Ps  = sm + P1_PS;
    float* kps = sm + P1_KP;

    const int tid = threadIdx.x;
    const int w = tid >> 5, l = tid & 31;
    const int g = l >> 2, tg = l & 3;
    const int bh = blockIdx.y, sp = blockIdx.x;

    // load P [256][64] -> Ps[m][d], tf32 rounded
    {
        const float4* P4 = reinterpret_cast<const float4*>(Pg);
        for (int i = tid; i < 4096; i += 256) {
            int m = i >> 4, d4 = i & 15;
            float4 x = P4[i];
            float4 t = make_float4(tf32r(x.x), tf32r(x.y), tf32r(x.z), tf32r(x.w));
            *reinterpret_cast<float4*>(&Ps[m * 68 + d4 * 4]) = t;
        }
    }
    // Vs constant columns: col 64 = 1.0 (ksum), 65..71 = 0
    for (int i = tid; i < 128 * 8; i += 256) {
        int n = i >> 3, e = 64 + (i & 7);
        Vs[n * 76 + e] = (e == 64) ? 1.0f : 0.0f;
    }

    // persistent ctx accumulators: warp w owns m-rows [32w, 32w+32)
    float ctx[2][9][4];
    #pragma unroll
    for (int mf = 0; mf < 2; mf++)
        #pragma unroll
        for (int j = 0; j < 9; j++)
            #pragma unroll
            for (int c = 0; c < 4; c++) ctx[mf][j][c] = 0.0f;

    const int rt = (w >> 2) * 16;    // G1 row offset within 32-token chunk
    const int cw = (w & 3) * 64;     // G1 feature-col base

    for (int t = 0; t < 4; t++) {
        // ---- load K,V tiles [128][64] ----
        const float4* Kb = reinterpret_cast<const float4*>(
            Kg + ((size_t)bh * NN + (size_t)sp * NCHUNK + (size_t)t * 128) * DD);
        const float4* Vb = reinterpret_cast<const float4*>(
            Vg + ((size_t)bh * NN + (size_t)sp * NCHUNK + (size_t)t * 128) * DD);
        for (int i = tid; i < 2048; i += 256) {
            int n = i >> 4, d4 = i & 15;
            float4 x = Kb[i];
            *reinterpret_cast<float4*>(&Ks[n * 68 + d4 * 4]) =
                make_float4(tf32r(x.x), tf32r(x.y), tf32r(x.z), tf32r(x.w));
            float4 y = Vb[i];
            *reinterpret_cast<float4*>(&Vs[n * 76 + d4 * 4]) =
                make_float4(tf32r(y.x), tf32r(y.y), tf32r(y.z), tf32r(y.w));
        }
        __syncthreads();

        for (int c = 0; c < 4; c++) {        // 32-token sub-chunks
            const int tok0 = c * 32;

            // ---- G1: S[32 tok][256 m] ; this warp: rows rt..rt+15, cols cw..cw+63 ----
            float S[8][4];
            #pragma unroll
            for (int j = 0; j < 8; j++)
                #pragma unroll
                for (int q = 0; q < 4; q++) S[j][q] = 0.0f;

            #pragma unroll
            for (int k8 = 0; k8 < 8; k8++) {
                const int kb = k8 * 8;
                uint32_t a0 = f2u(Ks[(tok0 + rt + g) * 68 + kb + tg]);
                uint32_t a1 = f2u(Ks[(tok0 + rt + g + 8) * 68 + kb + tg]);
                uint32_t a2 = f2u(Ks[(tok0 + rt + g) * 68 + kb + tg + 4]);
                uint32_t a3 = f2u(Ks[(tok0 + rt + g + 8) * 68 + kb + tg + 4]);
                #pragma unroll
                for (int j = 0; j < 8; j++) {
                    uint32_t b0 = f2u(Ps[(cw + j * 8 + g) * 68 + kb + tg]);
                    uint32_t b1 = f2u(Ps[(cw + j * 8 + g) * 68 + kb + tg + 4]);
                    mma8(S[j], a0, a1, a2, a3, b0, b1);
                }
            }
            // gelu + tf32, stage kp chunk [32 tok][256 m] (stride 264)
            #pragma unroll
            for (int j = 0; j < 8; j++) {
                int col = cw + j * 8 + 2 * tg;
                float2 v0 = make_float2(tf32r(gelu_eps(S[j][0])), tf32r(gelu_eps(S[j][1])));
                float2 v1 = make_float2(tf32r(gelu_eps(S[j][2])), tf32r(gelu_eps(S[j][3])));
                *reinterpret_cast<float2*>(&kps[(rt + g) * 264 + col]) = v0;
                *reinterpret_cast<float2*>(&kps[(rt + g + 8) * 264 + col]) = v1;
            }
            __syncthreads();

            // ---- MMA2: ctx[32w..][72] += kp^T @ V  (k = 32 tokens) ----
            #pragma unroll
            for (int k8 = 0; k8 < 4; k8++) {
                const int kb = k8 * 8;
                const int vrow = tok0 + kb;
                uint32_t a[2][4];
                #pragma unroll
                for (int mf = 0; mf < 2; mf++) {
                    int m = 32 * w + 16 * mf + g;
                    a[mf][0] = f2u(kps[(kb + tg) * 264 + m]);
                    a[mf][1] = f2u(kps[(kb + tg) * 264 + m + 8]);
                    a[mf][2] = f2u(kps[(kb + tg + 4) * 264 + m]);
                    a[mf][3] = f2u(kps[(kb + tg + 4) * 264 + m + 8]);
                }
                #pragma unroll
                for (int j = 0; j < 9; j++) {
                    uint32_t b0 = f2u(Vs[(vrow + tg) * 76 + j * 8 + g]);
                    uint32_t b1 = f2u(Vs[(vrow + tg + 4) * 76 + j * 8 + g]);
                    mma8(ctx[0][j], a[0][0], a[0][1], a[0][2], a[0][3], b0, b1);
                    mma8(ctx[1][j], a[1][0], a[1][1], a[1][2], a[1][3], b0, b1);
                }
            }
            __syncthreads();
        }
    }

    // ---- epilogue: write ctx partial [256][72] (full f32) ----
    float* dst = g_ctxp + ((size_t)(bh * NSPLIT + sp)) * MM * CW;
    #pragma unroll
    for (int mf = 0; mf < 2; mf++) {
        int m = 32 * w + 16 * mf + g;
        #pragma unroll
        for (int j = 0; j < 9; j++) {
            int col = j * 8 + 2 * tg;
            *reinterpret_cast<float2*>(&dst[(size_t)m * CW + col]) =
                make_float2(ctx[mf][j][0], ctx[mf][j][1]);
            *reinterpret_cast<float2*>(&dst[(size_t)(m + 8) * CW + col]) =
                make_float2(ctx[mf][j][2], ctx[mf][j][3]);
        }
    }
}

// =====================================================================
// Reduce: fixed-order sum of 8 split partials (deterministic)
// =====================================================================
__global__ __launch_bounds__(256) void reduce_kernel()
{
    const int bh = blockIdx.x, tid = threadIdx.x;
    const float* src = g_ctxp + (size_t)bh * NSPLIT * MM * CW;
    float* dst = g_ctx + (size_t)bh * MM * CW;
    for (int i = tid; i < MM * CW; i += 256) {
        float s = 0.0f;
        #pragma unroll
        for (int sp = 0; sp < NSPLIT; sp++) s += src[(size_t)sp * MM * CW + i];
        dst[i] = s;
    }
}

// =====================================================================
// Phase 2: qp = gelu(Q@P^T)+eps ; out' = qp @ [ctx|ksum] ; out = out'/denom
// =====================================================================
__global__ __launch_bounds__(256, 1) void ph2_kernel(
    const float* __restrict__ Qg, const float* __restrict__ Pg,
    float* __restrict__ Og)
{
    extern __shared__ __align__(16) float sm[];
    float* Qs  = sm + P2_QS;
    float* Ps  = sm + P2_PS;
    float* Cs  = sm + P2_CS;
    float* qps = sm + P2_QP;
    float* dnm = sm + P2_DN;

    const int tid = threadIdx.x;
    const int w = tid >> 5, l = tid & 31;
    const int g = l >> 2, tg = l & 3;
    const int bh = blockIdx.y, sp = blockIdx.x;

    // load P
    {
        const float4* P4 = reinterpret_cast<const float4*>(Pg);
        for (int i = tid; i < 4096; i += 256) {
            int m = i >> 4, d4 = i & 15;
            float4 x = P4[i];
            *reinterpret_cast<float4*>(&Ps[m * 68 + d4 * 4]) =
                make_float4(tf32r(x.x), tf32r(x.y), tf32r(x.z), tf32r(x.w));
        }
    }
    // load ctx [256][72] -> Cs (tf32)
    {
        const float* Cg = g_ctx + (size_t)bh * MM * CW;
        for (int i = tid; i < MM * CW; i += 256) {
            int m = i / CW, e = i - m * CW;
            Cs[m * 76 + e] = tf32r(Cg[i]);
        }
    }

    for (int t = 0; t < 4; t++) {
        // load Q tile [128][64]
        const float4* Qb = reinterpret_cast<const float4*>(
            Qg + ((size_t)bh * NN + (size_t)sp * NCHUNK + (size_t)t * 128) * DD);
        for (int i = tid; i < 2048; i += 256) {
            int n = i >> 4, d4 = i & 15;
            float4 x = Qb[i];
            *reinterpret_cast<float4*>(&Qs[n * 68 + d4 * 4]) =
                make_float4(tf32r(x.x), tf32r(x.y), tf32r(x.z), tf32r(x.w));
        }
        __syncthreads();

        // out frags: warp w owns token rows [16w, 16w+16)
        float out[9][4];
        #pragma unroll
        for (int j = 0; j < 9; j++)
            #pragma unroll
            for (int q = 0; q < 4; q++) out[j][q] = 0.0f;

        for (int c = 0; c < 4; c++) {      // 64-feature chunks
            // ---- G3: S[128 tok][64 feat] ; warp rows 16w.. ----
            float S[8][4];
            #pragma unroll
            for (int j = 0; j < 8; j++)
                #pragma unroll
                for (int q = 0; q < 4; q++) S[j][q] = 0.0f;

            #pragma unroll
            for (int k8 = 0; k8 < 8; k8++) {
                const int kb = k8 * 8;
                uint32_t a0 = f2u(Qs[(16 * w + g) * 68 + kb + tg]);
                uint32_t a1 = f2u(Qs[(16 * w + g + 8) * 68 + kb + tg]);
                uint32_t a2 = f2u(Qs[(16 * w + g) * 68 + kb + tg + 4]);
                uint32_t a3 = f2u(Qs[(16 * w + g + 8) * 68 + kb + tg + 4]);
                #pragma unroll
                for (int j = 0; j < 8; j++) {
                    uint32_t b0 = f2u(Ps[(c * 64 + j * 8 + g) * 68 + kb + tg]);
                    uint32_t b1 = f2u(Ps[(c * 64 + j * 8 + g) * 68 + kb + tg + 4]);
                    mma8(S[j], a0, a1, a2, a3, b0, b1);
                }
            }
            // gelu + stage qp chunk [128 tok][64]
            #pragma unroll
            for (int j = 0; j < 8; j++) {
                int col = j * 8 + 2 * tg;
                *reinterpret_cast<float2*>(&qps[(16 * w + g) * 68 + col]) =
                    make_float2(tf32r(gelu_eps(S[j][0])), tf32r(gelu_eps(S[j][1])));
                *reinterpret_cast<float2*>(&qps[(16 * w + g + 8) * 68 + col]) =
                    make_float2(tf32r(gelu_eps(S[j][2])), tf32r(gelu_eps(S[j][3])));
            }
            __syncthreads();

            // ---- G4: out += qp_chunk @ Cs[c*64.., 0..72) ----
            #pragma unroll
            for (int k8 = 0; k8 < 8; k8++) {
                const int kb = k8 * 8;
                uint32_t a0 = f2u(qps[(16 * w + g) * 68 + kb + tg]);
                uint32_t a1 = f2u(qps[(16 * w + g + 8) * 68 + kb + tg]);
                uint32_t a2 = f2u(qps[(16 * w + g) * 68 + kb + tg + 4]);
                uint32_t a3 = f2u(qps[(16 * w + g + 8) * 68 + kb + tg + 4]);
                #pragma unroll
                for (int j = 0; j < 9; j++) {
                    uint32_t b0 = f2u(Cs[(c * 64 + kb + tg) * 76 + j * 8 + g]);
                    uint32_t b1 = f2u(Cs[(c * 64 + kb + tg + 4) * 76 + j * 8 + g]);
                    mma8(out[j], a0, a1, a2, a3, b0, b1);
                }
            }
            __syncthreads();
        }

        // ---- epilogue: divide by denom (col 64) and store ----
        if (tg == 0) {
            dnm[16 * w + g] = out[8][0];
            dnm[16 * w + g + 8] = out[8][2];
        }
        __syncthreads();
        float di0 = 1.0f / dnm[16 * w + g];
        float di1 = 1.0f / dnm[16 * w + g + 8];
        float* dst = Og + ((size_t)bh * NN + (size_t)sp * NCHUNK + (size_t)t * 128 + 16 * w + g) * DD;
        #pragma unroll
        for (int j = 0; j < 8; j++) {
            int col = j * 8 + 2 * tg;
            *reinterpret_cast<float2*>(&dst[col]) =
                make_float2(out[j][0] * di0, out[j][1] * di0);
            *reinterpret_cast<float2*>(&dst[(size_t)8 * DD + col]) =
                make_float2(out[j][2] * di1, out[j][3] * di1);
        }
        __syncthreads();
    }
}

// =====================================================================
// launch
// =====================================================================
extern "C" void kernel_launch(void* const* d_in, const int* in_sizes, int n_in,
                              void* d_out, int out_size)
{
    const float* q    = (const float*)d_in[0];
    const float* k    = (const float*)d_in[1];
    const float* v    = (const float*)d_in[2];
    const float* proj = (const float*)d_in[3];
    float* out = (float*)d_out;

    cudaFuncSetAttribute(ph1_kernel, cudaFuncAttributeMaxDynamicSharedMemorySize, P1_TOT * 4);
    cudaFuncSetAttribute(ph2_kernel, cudaFuncAttributeMaxDynamicSharedMemorySize, P2_TOT * 4);

    ph1_kernel<<<dim3(NSPLIT, BH), 256, P1_TOT * 4>>>(k, v, proj);
    reduce_kernel<<<BH, 256>>>();
    ph2_kernel<<<dim3(NSPLIT, BH), 256, P2_TOT * 4>>>(q, proj, out);
}

// round 7
// speedup vs baseline: 4.1459x; 1.0075x over previous
#include <cuda_runtime.h>
#include <cstdint>
#include <math.h>

// ---------------- problem constants ----------------
#define NN 4096
#define DD 64
#define MM 256
#define BH 64
#define NSPLIT 8
#define NCHUNK 512        // tokens per CTA (4 tiles of 128)
#define CW 72             // ctx width: 64 e-cols + ksum col + 7 pad (9 n8-frags)

typedef unsigned long long ull;

// ---------------- scratch (no allocs allowed) ----------------
__device__ float g_ctxp[(size_t)BH * NSPLIT * MM * CW];   // partials
__device__ float g_ctx [(size_t)BH * MM * CW];            // reduced (tf32-rounded)

// ---------------- helpers ----------------
__device__ __forceinline__ float tf32r(float x) {
    uint32_t u; asm("cvt.rna.tf32.f32 %0, %1;" : "=r"(u) : "f"(x));
    return __uint_as_float(u);
}
__device__ __forceinline__ void mma8(float c[4],
    uint32_t a0, uint32_t a1, uint32_t a2, uint32_t a3,
    uint32_t b0, uint32_t b1)
{
    asm volatile("mma.sync.aligned.m16n8k8.row.col.f32.tf32.tf32.f32 "
        "{%0,%1,%2,%3}, {%4,%5,%6,%7}, {%8,%9}, {%0,%1,%2,%3};"
        : "+f"(c[0]), "+f"(c[1]), "+f"(c[2]), "+f"(c[3])
        : "r"(a0), "r"(a1), "r"(a2), "r"(a3), "r"(b0), "r"(b1));
}
__device__ __forceinline__ uint32_t f2u(float x) { return __float_as_uint(x); }

__device__ __forceinline__ float gelu_eps(float x) {
    return 0.5f * x * (1.0f + erff(x * 0.70710678118654752f)) + 1e-6f;
}

// ---------------- smem layouts (float indices) ----------------
// Phase 1: Ks[128][68] | Vs[128][72] | Ps[256][68] | kps[32][264]
#define P1_KS   0
#define P1_VS   8704
#define P1_PS   (8704 + 9216)
#define P1_KP   (8704 + 9216 + 17408)
#define P1_TOT  (8704 + 9216 + 17408 + 8448)      // 43776 fl = 175104 B
// Phase 2: Qs[128][68] | Ps[256][68] | Cs[256][72] | qps[128][68] | denom[128]
#define P2_QS   0
#define P2_PS   8704
#define P2_CS   (8704 + 17408)
#define P2_QP   (8704 + 17408 + 18432)
#define P2_DN   (8704 + 17408 + 18432 + 8704)
#define P2_TOT  (8704 + 17408 + 18432 + 8704 + 128)  // 53376 fl = 213504 B

// =====================================================================
// Phase 1: kp = gelu(K@P^T)+eps ; ctx_partial = kp^T @ [V | 1 | 0]
// 512 threads: 16 warps. G1: warp tile 16tok x 32feat. MMA2: 16 m-rows/warp.
// =====================================================================
__global__ __launch_bounds__(512, 1) void ph1_kernel(
    const float* __restrict__ Kg, const float* __restrict__ Vg,
    const float* __restrict__ Pg)
{
    extern __shared__ __align__(16) float sm[];
    float* Ks  = sm + P1_KS;
    float* Vs  = sm + P1_VS;
    float* Ps  = sm + P1_PS;
    float* kps = sm + P1_KP;

    const int tid = threadIdx.x;
    const int w = tid >> 5, l = tid & 31;
    const int g = l >> 2, tg = l & 3;
    const int bh = blockIdx.y, sp = blockIdx.x;

    // load P [256][64] -> Ps (tf32)
    {
        const float4* P4 = reinterpret_cast<const float4*>(Pg);
        for (int i = tid; i < 4096; i += 512) {
            int m = i >> 4, d4 = i & 15;
            float4 x = P4[i];
            *reinterpret_cast<float4*>(&Ps[m * 68 + d4 * 4]) =
                make_float4(tf32r(x.x), tf32r(x.y), tf32r(x.z), tf32r(x.w));
        }
    }
    // Vs constant columns: col 64 = 1.0 (ksum), 65..71 = 0
    for (int i = tid; i < 128 * 8; i += 512) {
        int n = i >> 3, e = 64 + (i & 7);
        Vs[n * 72 + e] = (e == 64) ? 1.0f : 0.0f;
    }

    // persistent ctx accumulators: warp w owns m-rows [16w, 16w+16)
    float ctx[9][4];
    #pragma unroll
    for (int j = 0; j < 9; j++)
        #pragma unroll
        for (int c = 0; c < 4; c++) ctx[j][c] = 0.0f;

    const int rg = (w >> 3) * 16;    // G1 token-row offset within 32-chunk
    const int cg = (w & 7) * 32;     // G1 feature-col base

    for (int t = 0; t < 4; t++) {
        // ---- load K,V tiles [128][64] ----
        const float4* Kb = reinterpret_cast<const float4*>(
            Kg + ((size_t)bh * NN + (size_t)sp * NCHUNK + (size_t)t * 128) * DD);
        const float4* Vb = reinterpret_cast<const float4*>(
            Vg + ((size_t)bh * NN + (size_t)sp * NCHUNK + (size_t)t * 128) * DD);
        for (int i = tid; i < 2048; i += 512) {
            int n = i >> 4, d4 = i & 15;
            float4 x = Kb[i];
            *reinterpret_cast<float4*>(&Ks[n * 68 + d4 * 4]) =
                make_float4(tf32r(x.x), tf32r(x.y), tf32r(x.z), tf32r(x.w));
            float4 y = Vb[i];
            *reinterpret_cast<float4*>(&Vs[n * 72 + d4 * 4]) =
                make_float4(tf32r(y.x), tf32r(y.y), tf32r(y.z), tf32r(y.w));
        }
        __syncthreads();

        for (int c = 0; c < 4; c++) {        // 32-token sub-chunks
            const int tok0 = c * 32;

            // ---- G1: S[32 tok][256 m] ; this warp: rows rg..rg+15, cols cg..cg+31 ----
            float S[4][4];
            #pragma unroll
            for (int j = 0; j < 4; j++)
                #pragma unroll
                for (int q = 0; q < 4; q++) S[j][q] = 0.0f;

            #pragma unroll
            for (int k8 = 0; k8 < 8; k8++) {
                const int kb = k8 * 8;
                const float* Ka = &Ks[(tok0 + rg + g) * 68 + kb + tg];
                uint32_t a0 = f2u(Ka[0]);
                uint32_t a1 = f2u(Ka[8 * 68]);
                uint32_t a2 = f2u(Ka[4]);
                uint32_t a3 = f2u(Ka[8 * 68 + 4]);
                #pragma unroll
                for (int j = 0; j < 4; j++) {
                    const float* Pb = &Ps[(cg + j * 8 + g) * 68 + kb + tg];
                    mma8(S[j], a0, a1, a2, a3, f2u(Pb[0]), f2u(Pb[4]));
                }
            }
            // gelu + tf32, stage kp chunk [32 tok][256 m] (stride 264)
            #pragma unroll
            for (int j = 0; j < 4; j++) {
                int col = cg + j * 8 + 2 * tg;
                *reinterpret_cast<float2*>(&kps[(rg + g) * 264 + col]) =
                    make_float2(tf32r(gelu_eps(S[j][0])), tf32r(gelu_eps(S[j][1])));
                *reinterpret_cast<float2*>(&kps[(rg + g + 8) * 264 + col]) =
                    make_float2(tf32r(gelu_eps(S[j][2])), tf32r(gelu_eps(S[j][3])));
            }
            __syncthreads();

            // ---- MMA2: ctx[16w..][72] += kp^T @ V  (k = 32 tokens) ----
            #pragma unroll
            for (int k8 = 0; k8 < 4; k8++) {
                const int kb = k8 * 8;
                const int vrow = tok0 + kb;
                const float* Aa = &kps[(kb + tg) * 264 + 16 * w + g];
                uint32_t a0 = f2u(Aa[0]);
                uint32_t a1 = f2u(Aa[8]);
                uint32_t a2 = f2u(Aa[4 * 264]);
                uint32_t a3 = f2u(Aa[4 * 264 + 8]);
                const float* Vbp = &Vs[(vrow + tg) * 72 + g];
                #pragma unroll
                for (int j = 0; j < 9; j++) {
                    mma8(ctx[j], a0, a1, a2, a3,
                         f2u(Vbp[j * 8]), f2u(Vbp[4 * 72 + j * 8]));
                }
            }
            __syncthreads();
        }
    }

    // ---- epilogue: write ctx partial [256][72] (full f32) ----
    float* dst = g_ctxp + ((size_t)(bh * NSPLIT + sp)) * MM * CW;
    {
        int m = 16 * w + g;
        #pragma unroll
        for (int j = 0; j < 9; j++) {
            int col = j * 8 + 2 * tg;
            *reinterpret_cast<float2*>(&dst[(size_t)m * CW + col]) =
                make_float2(ctx[j][0], ctx[j][1]);
            *reinterpret_cast<float2*>(&dst[(size_t)(m + 8) * CW + col]) =
                make_float2(ctx[j][2], ctx[j][3]);
        }
    }
}

// =====================================================================
// Reduce: fixed-order sum of 8 split partials; output tf32-rounded
// =====================================================================
__global__ __launch_bounds__(256) void reduce_kernel()
{
    const int bh = blockIdx.x, tid = threadIdx.x;
    const float* src = g_ctxp + (size_t)bh * NSPLIT * MM * CW;
    float* dst = g_ctx + (size_t)bh * MM * CW;
    for (int i = tid; i < MM * CW; i += 256) {
        float s = 0.0f;
        #pragma unroll
        for (int sp = 0; sp < NSPLIT; sp++) s += src[(size_t)sp * MM * CW + i];
        dst[i] = tf32r(s);
    }
}

// =====================================================================
// Phase 2: qp = gelu(Q@P^T)+eps ; out' = qp @ [ctx|ksum] ; out = out'/denom
// 512 threads: G3 tile 16tok x 32feat; G4: 8 row-groups x 2 col-groups.
// =====================================================================
__global__ __launch_bounds__(512, 1) void ph2_kernel(
    const float* __restrict__ Qg, const float* __restrict__ Pg,
    float* __restrict__ Og)
{
    extern __shared__ __align__(16) float sm[];
    float* Qs  = sm + P2_QS;
    float* Ps  = sm + P2_PS;
    float* Cs  = sm + P2_CS;
    float* qps = sm + P2_QP;
    float* dnm = sm + P2_DN;

    const int tid = threadIdx.x;
    const int w = tid >> 5, l = tid & 31;
    const int g = l >> 2, tg = l & 3;
    const int bh = blockIdx.y, sp = blockIdx.x;

    // load P (tf32)
    {
        const float4* P4 = reinterpret_cast<const float4*>(Pg);
        for (int i = tid; i < 4096; i += 512) {
            int m = i >> 4, d4 = i & 15;
            float4 x = P4[i];
            *reinterpret_cast<float4*>(&Ps[m * 68 + d4 * 4]) =
                make_float4(tf32r(x.x), tf32r(x.y), tf32r(x.z), tf32r(x.w));
        }
    }
    // load ctx [256][72] -> Cs (already tf32-rounded)
    {
        const float4* Cg = reinterpret_cast<const float4*>(g_ctx + (size_t)bh * MM * CW);
        for (int i = tid; i < MM * CW / 4; i += 512)
            *reinterpret_cast<float4*>(&Cs[i * 4]) = Cg[i];
    }

    const int rw3 = (w & 7) * 16;   // G3 token rows
    const int fg  = (w >> 3) * 32;  // G3 feature cols
    const int rw  = (w & 7) * 16;   // G4 token rows
    const int cgr = w >> 3;         // G4 col group: 0 -> j 0..4, 1 -> j 5..8
    const int joff = cgr ? 5 : 0;
    const int jcnt = cgr ? 4 : 5;

    for (int t = 0; t < 4; t++) {
        // load Q tile [128][64]
        const float4* Qb = reinterpret_cast<const float4*>(
            Qg + ((size_t)bh * NN + (size_t)sp * NCHUNK + (size_t)t * 128) * DD);
        for (int i = tid; i < 2048; i += 512) {
            int n = i >> 4, d4 = i & 15;
            float4 x = Qb[i];
            *reinterpret_cast<float4*>(&Qs[n * 68 + d4 * 4]) =
                make_float4(tf32r(x.x), tf32r(x.y), tf32r(x.z), tf32r(x.w));
        }
        __syncthreads();

        float out[5][4];
        #pragma unroll
        for (int j = 0; j < 5; j++)
            #pragma unroll
            for (int q = 0; q < 4; q++) out[j][q] = 0.0f;

        for (int c = 0; c < 4; c++) {      // 64-feature chunks
            // ---- G3: S[128 tok][64 feat] ; warp tile rw3 x fg ----
            float S[4][4];
            #pragma unroll
            for (int j = 0; j < 4; j++)
                #pragma unroll
                for (int q = 0; q < 4; q++) S[j][q] = 0.0f;

            #pragma unroll
            for (int k8 = 0; k8 < 8; k8++) {
                const int kb = k8 * 8;
                const float* Qa = &Qs[(rw3 + g) * 68 + kb + tg];
                uint32_t a0 = f2u(Qa[0]);
                uint32_t a1 = f2u(Qa[8 * 68]);
                uint32_t a2 = f2u(Qa[4]);
                uint32_t a3 = f2u(Qa[8 * 68 + 4]);
                #pragma unroll
                for (int j = 0; j < 4; j++) {
                    const float* Pb = &Ps[(c * 64 + fg + j * 8 + g) * 68 + kb + tg];
                    mma8(S[j], a0, a1, a2, a3, f2u(Pb[0]), f2u(Pb[4]));
                }
            }
            // gelu + stage qp chunk [128 tok][64]
            #pragma unroll
            for (int j = 0; j < 4; j++) {
                int col = fg + j * 8 + 2 * tg;
                *reinterpret_cast<float2*>(&qps[(rw3 + g) * 68 + col]) =
                    make_float2(tf32r(gelu_eps(S[j][0])), tf32r(gelu_eps(S[j][1])));
                *reinterpret_cast<float2*>(&qps[(rw3 + g + 8) * 68 + col]) =
                    make_float2(tf32r(gelu_eps(S[j][2])), tf32r(gelu_eps(S[j][3])));
            }
            __syncthreads();

            // ---- G4: out += qp_chunk @ Cs[c*64.., joff*8..] ----
            #pragma unroll
            for (int k8 = 0; k8 < 8; k8++) {
                const int kb = k8 * 8;
                const float* Qa = &qps[(rw + g) * 68 + kb + tg];
                uint32_t a0 = f2u(Qa[0]);
                uint32_t a1 = f2u(Qa[8 * 68]);
                uint32_t a2 = f2u(Qa[4]);
                uint32_t a3 = f2u(Qa[8 * 68 + 4]);
                const float* Cb = &Cs[(c * 64 + kb + tg) * 72 + joff * 8 + g];
                #pragma unroll
                for (int j = 0; j < 5; j++) {
                    if (j < jcnt)
                        mma8(out[j], a0, a1, a2, a3,
                             f2u(Cb[j * 8]), f2u(Cb[4 * 72 + j * 8]));
                }
            }
            __syncthreads();
        }

        // ---- epilogue: divide by denom (col 64 = j global 8 = cgr1 j=3) ----
        if (cgr == 1 && tg == 0) {
            dnm[rw + g] = out[3][0];
            dnm[rw + g + 8] = out[3][2];
        }
        __syncthreads();
        float di0 = 1.0f / dnm[rw + g];
        float di1 = 1.0f / dnm[rw + g + 8];
        float* dst = Og + ((size_t)bh * NN + (size_t)sp * NCHUNK + (size_t)t * 128 + rw + g) * DD;
        #pragma unroll
        for (int j = 0; j < 5; j++) {
            int jg = joff + j;
            if (jg < 8) {
                int col = jg * 8 + 2 * tg;
                *reinterpret_cast<float2*>(&dst[col]) =
                    make_float2(out[j][0] * di0, out[j][1] * di0);
                *reinterpret_cast<float2*>(&dst[(size_t)8 * DD + col]) =
                    make_float2(out[j][2] * di1, out[j][3] * di1);
            }
        }
        __syncthreads();
    }
}

// =====================================================================
// launch
// =====================================================================
extern "C" void kernel_launch(void* const* d_in, const int* in_sizes, int n_in,
                              void* d_out, int out_size)
{
    const float* q    = (const float*)d_in[0];
    const float* k    = (const float*)d_in[1];
    const float* v    = (const float*)d_in[2];
    const float* proj = (const float*)d_in[3];
    float* out = (float*)d_out;

    cudaFuncSetAttribute(ph1_kernel, cudaFuncAttributeMaxDynamicSharedMemorySize, P1_TOT * 4);
    cudaFuncSetAttribute(ph2_kernel, cudaFuncAttributeMaxDynamicSharedMemorySize, P2_TOT * 4);

    ph1_kernel<<<dim3(NSPLIT, BH), 512, P1_TOT * 4>>>(k, v, proj);
    reduce_kernel<<<BH, 256>>>();
    ph2_kernel<<<dim3(NSPLIT, BH), 512, P2_TOT * 4>>>(q, proj, out);
}

// round 8
// speedup vs baseline: 4.2726x; 1.0306x over previous
#include <cuda_runtime.h>
#include <cstdint>
#include <math.h>

// ---------------- problem constants ----------------
#define NN 4096
#define DD 64
#define MM 256
#define BH 64
#define NSPLIT 8
#define NCHUNK 512        // tokens per CTA (4 tiles of 128)
#define CW 72             // ctx width: 64 e-cols + ksum col + 7 pad (9 n8-frags)

typedef unsigned long long ull;

// ---------------- scratch (no allocs allowed) ----------------
__device__ float g_ctxp[(size_t)BH * NSPLIT * MM * CW];   // partials
__device__ float g_ctx [(size_t)BH * MM * CW];            // reduced (tf32-rounded)

// ---------------- helpers ----------------
__device__ __forceinline__ float tf32r(float x) {
    uint32_t u; asm("cvt.rna.tf32.f32 %0, %1;" : "=r"(u) : "f"(x));
    return __uint_as_float(u);
}
__device__ __forceinline__ void mma8(float c[4],
    uint32_t a0, uint32_t a1, uint32_t a2, uint32_t a3,
    uint32_t b0, uint32_t b1)
{
    asm volatile("mma.sync.aligned.m16n8k8.row.col.f32.tf32.tf32.f32 "
        "{%0,%1,%2,%3}, {%4,%5,%6,%7}, {%8,%9}, {%0,%1,%2,%3};"
        : "+f"(c[0]), "+f"(c[1]), "+f"(c[2]), "+f"(c[3])
        : "r"(a0), "r"(a1), "r"(a2), "r"(a3), "r"(b0), "r"(b1));
}
__device__ __forceinline__ uint32_t f2u(float x) { return __float_as_uint(x); }

__device__ __forceinline__ float gelu_eps(float x) {
    return 0.5f * x * (1.0f + erff(x * 0.70710678118654752f)) + 1e-6f;
}

// ---------------- ph1 smem layout (float indices) ----------------
// Ps[256][68] | Kf: 64 blocks x 132 | Vf: 144 blocks x 66 | Af: 8 warps x 1280
#define F_PS 0
#define F_KF 17408
#define F_VF (17408 + 8448)
#define F_AF (17408 + 8448 + 9504)
#define F_TOT (17408 + 8448 + 9504 + 10240)   // 45600 floats = 182400 B

// ---------------- ph2 smem layout (unchanged from R7) ----------------
#define P2_QS   0
#define P2_PS   8704
#define P2_CS   (8704 + 17408)
#define P2_QP   (8704 + 17408 + 18432)
#define P2_DN   (8704 + 17408 + 18432 + 8704)
#define P2_TOT  (8704 + 17408 + 18432 + 8704 + 128)  // 53376 fl = 213504 B

// =====================================================================
// Phase 1 (warp-autonomous): each warp owns m-block [32w, 32w+32).
// G1: kp_blk = gelu(K_chunk @ P_blk^T)  (P frags in registers)
// MMA2: ctx_blk += kp_blk^T @ [V | 1 | 0]  (A staged via per-warp scratch)
// No __syncthreads inside the chunk loop.
// =====================================================================
__global__ __launch_bounds__(256, 1) void ph1_kernel(
    const float* __restrict__ Kg, const float* __restrict__ Vg,
    const float* __restrict__ Pg)
{
    extern __shared__ __align__(16) float sm[];
    float* Ps = sm + F_PS;
    float* Kf = sm + F_KF;
    float* Vf = sm + F_VF;
    float* Af = sm + F_AF;

    const int tid = threadIdx.x;
    const int w = tid >> 5, l = tid & 31;
    const int g = l >> 2, tg = l & 3;
    const int bh = blockIdx.y, sp = blockIdx.x;

    // ---- load P [256][64] -> Ps (tf32) ----
    {
        const float4* P4 = reinterpret_cast<const float4*>(Pg);
        for (int i = tid; i < 4096; i += 256) {
            int m = i >> 4, d4 = i & 15;
            float4 x = P4[i];
            *reinterpret_cast<float4*>(&Ps[m * 68 + d4 * 4]) =
                make_float4(tf32r(x.x), tf32r(x.y), tf32r(x.z), tf32r(x.w));
        }
    }
    // ---- prefill Vf j=8 blocks (ksum column: e=64 -> 1.0, e=65..71 -> 0) ----
    for (int i = tid; i < 512; i += 256) {
        int blk = i >> 5, ll = i & 31, gg = ll >> 2;
        float vv = (gg == 0) ? 1.0f : 0.0f;
        *reinterpret_cast<float2*>(&Vf[(blk * 9 + 8) * 66 + ll * 2]) = make_float2(vv, vv);
    }
    __syncthreads();

    // ---- P fragments for this warp's m-block, in registers ----
    float Pf[8][4][2];
    #pragma unroll
    for (int k8 = 0; k8 < 8; k8++)
        #pragma unroll
        for (int j = 0; j < 4; j++) {
            const float* p = &Ps[(32 * w + 8 * j + g) * 68 + 8 * k8 + tg];
            Pf[k8][j][0] = p[0];
            Pf[k8][j][1] = p[4];
        }

    // ---- persistent ctx accumulators: [mf 2][j 9][4] ----
    float ctx[2][9][4];
    #pragma unroll
    for (int mf = 0; mf < 2; mf++)
        #pragma unroll
        for (int j = 0; j < 9; j++)
            #pragma unroll
            for (int q = 0; q < 4; q++) ctx[mf][j][q] = 0.0f;

    const float4* Kb = reinterpret_cast<const float4*>(
        Kg + ((size_t)bh * NN + (size_t)sp * NCHUNK) * DD);
    const float4* Vb = reinterpret_cast<const float4*>(
        Vg + ((size_t)bh * NN + (size_t)sp * NCHUNK) * DD);

    for (int t = 0; t < 4; t++) {
        __syncthreads();    // all warps done reading previous tile's Kf/Vf

        // ---- stage K,V tiles [128][64] into fragment-ordered smem ----
        for (int i = tid; i < 2048; i += 256) {
            int n = i >> 4, d4 = i & 15;
            int c = n >> 5, tok = n & 31;
            int tf = tok >> 4, gg = tok & 7, rhi = (tok >> 3) & 1;
            float4 kx = Kb[t * 2048 + i];
            float kv[4] = { kx.x, kx.y, kx.z, kx.w };
            #pragma unroll
            for (int e = 0; e < 4; e++) {
                int dd = 4 * d4 + e;
                int k8 = dd >> 3, tgg = dd & 3, khi = (dd >> 2) & 1;
                Kf[((c * 8 + k8) * 2 + tf) * 132 + (gg * 4 + tgg) * 4 + rhi + 2 * khi]
                    = tf32r(kv[e]);
            }
            int r = n & 31;
            int k8v = r >> 3, rr = r & 7;
            int half = rr >> 2, tgv = rr & 3;
            float4 vx = Vb[t * 2048 + i];
            float vv[4] = { vx.x, vx.y, vx.z, vx.w };
            #pragma unroll
            for (int e = 0; e < 4; e++) {
                int ee = 4 * d4 + e;
                int j = ee >> 3, ge = ee & 7;
                Vf[((c * 4 + k8v) * 9 + j) * 66 + (ge * 4 + tgv) * 2 + half]
                    = tf32r(vv[e]);
            }
        }
        __syncthreads();

        for (int c = 0; c < 4; c++) {
            // ---- G1: S[2 tokfrag][4 j][4] = K_chunk @ P_blk^T ----
            float S[2][4][4];
            #pragma unroll
            for (int tf = 0; tf < 2; tf++)
                #pragma unroll
                for (int j = 0; j < 4; j++)
                    #pragma unroll
                    for (int q = 0; q < 4; q++) S[tf][j][q] = 0.0f;

            #pragma unroll
            for (int k8 = 0; k8 < 8; k8++) {
                #pragma unroll
                for (int tf = 0; tf < 2; tf++) {
                    float4 av = *reinterpret_cast<const float4*>(
                        &Kf[((c * 8 + k8) * 2 + tf) * 132 + l * 4]);
                    uint32_t a0 = f2u(av.x), a1 = f2u(av.y), a2 = f2u(av.z), a3 = f2u(av.w);
                    #pragma unroll
                    for (int j = 0; j < 4; j++)
                        mma8(S[tf][j], a0, a1, a2, a3,
                             f2u(Pf[k8][j][0]), f2u(Pf[k8][j][1]));
                }
            }
            __syncwarp();

            // ---- gelu + scatter into per-warp A-fragment scratch ----
            #pragma unroll
            for (int tf = 0; tf < 2; tf++)
                #pragma unroll
                for (int mf = 0; mf < 2; mf++)
                    #pragma unroll
                    for (int e = 0; e < 4; e++) {
                        float x0 = tf32r(gelu_eps(S[tf][2 * mf][e]));
                        float x1 = tf32r(gelu_eps(S[tf][2 * mf + 1][e]));
                        int k8p = 2 * tf + (e >> 1);
                        int gc = 2 * tg + (e & 1);
                        *reinterpret_cast<float2*>(
                            &Af[w * 1280 + k8p * 320 + g * 40 + mf * 16 + gc * 2]) =
                            make_float2(x0, x1);
                    }
            __syncwarp();

            // ---- MMA2: ctx += kp_blk^T @ [V | 1 | 0]  (k = 32 tokens) ----
            #pragma unroll
            for (int k8p = 0; k8p < 4; k8p++) {
                const float* ab = &Af[w * 1280 + k8p * 320 + g * 2];
                float2 a01_0 = *reinterpret_cast<const float2*>(&ab[tg * 40]);
                float2 a23_0 = *reinterpret_cast<const float2*>(&ab[(tg + 4) * 40]);
                float2 a01_1 = *reinterpret_cast<const float2*>(&ab[tg * 40 + 16]);
                float2 a23_1 = *reinterpret_cast<const float2*>(&ab[(tg + 4) * 40 + 16]);
                const float* vbase = &Vf[((c * 4 + k8p) * 9) * 66 + l * 2];
                #pragma unroll
                for (int j = 0; j < 9; j++) {
                    float2 b = *reinterpret_cast<const float2*>(&vbase[j * 66]);
                    uint32_t b0 = f2u(b.x), b1 = f2u(b.y);
                    mma8(ctx[0][j], f2u(a01_0.x), f2u(a01_0.y), f2u(a23_0.x), f2u(a23_0.y), b0, b1);
                    mma8(ctx[1][j], f2u(a01_1.x), f2u(a01_1.y), f2u(a23_1.x), f2u(a23_1.y), b0, b1);
                }
            }
            __syncwarp();
        }
    }

    // ---- epilogue: write ctx partial [256][72] ----
    float* dst = g_ctxp + ((size_t)(bh * NSPLIT + sp)) * MM * CW;
    #pragma unroll
    for (int mf = 0; mf < 2; mf++) {
        int m = 32 * w + 16 * mf + g;
        #pragma unroll
        for (int j = 0; j < 9; j++) {
            int col = j * 8 + 2 * tg;
            *reinterpret_cast<float2*>(&dst[(size_t)m * CW + col]) =
                make_float2(ctx[mf][j][0], ctx[mf][j][1]);
            *reinterpret_cast<float2*>(&dst[(size_t)(m + 8) * CW + col]) =
                make_float2(ctx[mf][j][2], ctx[mf][j][3]);
        }
    }
}

// =====================================================================
// Reduce: fixed-order sum of 8 split partials; output tf32-rounded
// =====================================================================
__global__ __launch_bounds__(256) void reduce_kernel()
{
    const int bh = blockIdx.x, tid = threadIdx.x;
    const float* src = g_ctxp + (size_t)bh * NSPLIT * MM * CW;
    float* dst = g_ctx + (size_t)bh * MM * CW;
    for (int i = tid; i < MM * CW; i += 256) {
        float s = 0.0f;
        #pragma unroll
        for (int sp = 0; sp < NSPLIT; sp++) s += src[(size_t)sp * MM * CW + i];
        dst[i] = tf32r(s);
    }
}

// =====================================================================
// Phase 2 (unchanged from R7): qp = gelu(Q@P^T)+eps ; out = (qp@[ctx|ksum])/denom
// =====================================================================
__global__ __launch_bounds__(512, 1) void ph2_kernel(
    const float* __restrict__ Qg, const float* __restrict__ Pg,
    float* __restrict__ Og)
{
    extern __shared__ __align__(16) float sm[];
    float* Qs  = sm + P2_QS;
    float* Ps  = sm + P2_PS;
    float* Cs  = sm + P2_CS;
    float* qps = sm + P2_QP;
    float* dnm = sm + P2_DN;

    const int tid = threadIdx.x;
    const int w = tid >> 5, l = tid & 31;
    const int g = l >> 2, tg = l & 3;
    const int bh = blockIdx.y, sp = blockIdx.x;

    {
        const float4* P4 = reinterpret_cast<const float4*>(Pg);
        for (int i = tid; i < 4096; i += 512) {
            int m = i >> 4, d4 = i & 15;
            float4 x = P4[i];
            *reinterpret_cast<float4*>(&Ps[m * 68 + d4 * 4]) =
                make_float4(tf32r(x.x), tf32r(x.y), tf32r(x.z), tf32r(x.w));
        }
    }
    {
        const float4* Cg = reinterpret_cast<const float4*>(g_ctx + (size_t)bh * MM * CW);
        for (int i = tid; i < MM * CW / 4; i += 512)
            *reinterpret_cast<float4*>(&Cs[i * 4]) = Cg[i];
    }

    const int rw3 = (w & 7) * 16;
    const int fg  = (w >> 3) * 32;
    const int rw  = (w & 7) * 16;
    const int cgr = w >> 3;
    const int joff = cgr ? 5 : 0;
    const int jcnt = cgr ? 4 : 5;

    for (int t = 0; t < 4; t++) {
        const float4* Qb = reinterpret_cast<const float4*>(
            Qg + ((size_t)bh * NN + (size_t)sp * NCHUNK + (size_t)t * 128) * DD);
        for (int i = tid; i < 2048; i += 512) {
            int n = i >> 4, d4 = i & 15;
            float4 x = Qb[i];
            *reinterpret_cast<float4*>(&Qs[n * 68 + d4 * 4]) =
                make_float4(tf32r(x.x), tf32r(x.y), tf32r(x.z), tf32r(x.w));
        }
        __syncthreads();

        float out[5][4];
        #pragma unroll
        for (int j = 0; j < 5; j++)
            #pragma unroll
            for (int q = 0; q < 4; q++) out[j][q] = 0.0f;

        for (int c = 0; c < 4; c++) {
            float S[4][4];
            #pragma unroll
            for (int j = 0; j < 4; j++)
                #pragma unroll
                for (int q = 0; q < 4; q++) S[j][q] = 0.0f;

            #pragma unroll
            for (int k8 = 0; k8 < 8; k8++) {
                const int kb = k8 * 8;
                const float* Qa = &Qs[(rw3 + g) * 68 + kb + tg];
                uint32_t a0 = f2u(Qa[0]);
                uint32_t a1 = f2u(Qa[8 * 68]);
                uint32_t a2 = f2u(Qa[4]);
                uint32_t a3 = f2u(Qa[8 * 68 + 4]);
                #pragma unroll
                for (int j = 0; j < 4; j++) {
                    const float* Pb = &Ps[(c * 64 + fg + j * 8 + g) * 68 + kb + tg];
                    mma8(S[j], a0, a1, a2, a3, f2u(Pb[0]), f2u(Pb[4]));
                }
            }
            #pragma unroll
            for (int j = 0; j < 4; j++) {
                int col = fg + j * 8 + 2 * tg;
                *reinterpret_cast<float2*>(&qps[(rw3 + g) * 68 + col]) =
                    make_float2(tf32r(gelu_eps(S[j][0])), tf32r(gelu_eps(S[j][1])));
                *reinterpret_cast<float2*>(&qps[(rw3 + g + 8) * 68 + col]) =
                    make_float2(tf32r(gelu_eps(S[j][2])), tf32r(gelu_eps(S[j][3])));
            }
            __syncthreads();

            #pragma unroll
            for (int k8 = 0; k8 < 8; k8++) {
                const int kb = k8 * 8;
                const float* Qa = &qps[(rw + g) * 68 + kb + tg];
                uint32_t a0 = f2u(Qa[0]);
                uint32_t a1 = f2u(Qa[8 * 68]);
                uint32_t a2 = f2u(Qa[4]);
                uint32_t a3 = f2u(Qa[8 * 68 + 4]);
                const float* Cb = &Cs[(c * 64 + kb + tg) * 72 + joff * 8 + g];
                #pragma unroll
                for (int j = 0; j < 5; j++) {
                    if (j < jcnt)
                        mma8(out[j], a0, a1, a2, a3,
                             f2u(Cb[j * 8]), f2u(Cb[4 * 72 + j * 8]));
                }
            }
            __syncthreads();
        }

        if (cgr == 1 && tg == 0) {
            dnm[rw + g] = out[3][0];
            dnm[rw + g + 8] = out[3][2];
        }
        __syncthreads();
        float di0 = 1.0f / dnm[rw + g];
        float di1 = 1.0f / dnm[rw + g + 8];
        float* dst = Og + ((size_t)bh * NN + (size_t)sp * NCHUNK + (size_t)t * 128 + rw + g) * DD;
        #pragma unroll
        for (int j = 0; j < 5; j++) {
            int jg = joff + j;
            if (jg < 8) {
                int col = jg * 8 + 2 * tg;
                *reinterpret_cast<float2*>(&dst[col]) =
                    make_float2(out[j][0] * di0, out[j][1] * di0);
                *reinterpret_cast<float2*>(&dst[(size_t)8 * DD + col]) =
                    make_float2(out[j][2] * di1, out[j][3] * di1);
            }
        }
        __syncthreads();
    }
}

// =====================================================================
// launch
// =====================================================================
extern "C" void kernel_launch(void* const* d_in, const int* in_sizes, int n_in,
                              void* d_out, int out_size)
{
    const float* q    = (const float*)d_in[0];
    const float* k    = (const float*)d_in[1];
    const float* v    = (const float*)d_in[2];
    const float* proj = (const float*)d_in[3];
    float* out = (float*)d_out;

    cudaFuncSetAttribute(ph1_kernel, cudaFuncAttributeMaxDynamicSharedMemorySize, F_TOT * 4);
    cudaFuncSetAttribute(ph2_kernel, cudaFuncAttributeMaxDynamicSharedMemorySize, P2_TOT * 4);

    ph1_kernel<<<dim3(NSPLIT, BH), 256, F_TOT * 4>>>(k, v, proj);
    reduce_kernel<<<BH, 256>>>();
    ph2_kernel<<<dim3(NSPLIT, BH), 512, P2_TOT * 4>>>(q, proj, out);
}

// round 10
// speedup vs baseline: 4.3194x; 1.0110x over previous
#include <cuda_runtime.h>
#include <cstdint>
#include <math.h>

// ---------------- problem constants ----------------
#define NN 4096
#define DD 64
#define MM 256
#define BH 64
#define NSPLIT 8
#define NCHUNK 512        // tokens per CTA (4 tiles of 128)
#define CW 72             // ctx width: 64 e-cols + ksum col + 7 pad (9 n8-frags)

typedef unsigned long long ull;

// ---------------- scratch (no allocs allowed) ----------------
__device__ float g_ctxp[(size_t)BH * NSPLIT * MM * CW];   // partials
__device__ float g_ctx [(size_t)BH * MM * CW];            // reduced (tf32-rounded)

// ---------------- helpers ----------------
__device__ __forceinline__ float tf32r(float x) {
    uint32_t u; asm("cvt.rna.tf32.f32 %0, %1;" : "=r"(u) : "f"(x));
    return __uint_as_float(u);
}
__device__ __forceinline__ void mma8(float c[4],
    uint32_t a0, uint32_t a1, uint32_t a2, uint32_t a3,
    uint32_t b0, uint32_t b1)
{
    asm volatile("mma.sync.aligned.m16n8k8.row.col.f32.tf32.tf32.f32 "
        "{%0,%1,%2,%3}, {%4,%5,%6,%7}, {%8,%9}, {%0,%1,%2,%3};"
        : "+f"(c[0]), "+f"(c[1]), "+f"(c[2]), "+f"(c[3])
        : "r"(a0), "r"(a1), "r"(a2), "r"(a3), "r"(b0), "r"(b1));
}
__device__ __forceinline__ uint32_t f2u(float x) { return __float_as_uint(x); }

__device__ __forceinline__ float fast_rcp(float x) {
    float r; asm("rcp.approx.f32 %0, %1;" : "=f"(r) : "f"(x)); return r;
}
__device__ __forceinline__ float fast_ex2(float x) {
    float r; asm("ex2.approx.f32 %0, %1;" : "=f"(r) : "f"(x)); return r;
}

// Branchless gelu(x)+eps via Abramowitz-Stegun 7.1.26 (abs err ~1.5e-7):
//   erf(t) = 1 - P(k) e^{-t^2},  k = 1/(1 + 0.3275911 t),  t = |x|/sqrt(2)
//   gelu(x) = 0.5x + 0.5|x| - 0.5|x| P(k) e^{-x^2/2}
__device__ __forceinline__ float gelu_eps(float x) {
    float ax = fabsf(x);
    float t  = ax * 0.70710678118654752f;
    float k  = fast_rcp(fmaf(0.3275911f, t, 1.0f));
    float p  = fmaf(1.061405429f, k, -1.453152027f);
    p = fmaf(p, k, 1.421413741f);
    p = fmaf(p, k, -0.284496736f);
    p = fmaf(p, k, 0.254829592f);
    p = p * k;
    float e  = fast_ex2(-1.4426950408889634f * t * t);   // exp(-t^2)
    float h  = 0.5f * ax;
    float base = fmaf(0.5f, x, h) + 1e-6f;               // 0.5x + 0.5|x| + eps
    return fmaf(-h, p * e, base);
}

// ---------------- ph1 smem layout (float indices) ----------------
// Ps[256][68] | Kf: 64 blocks x 132 | Vf: 144 blocks x 66 | Af: 8 warps x 1280
#define F_PS 0
#define F_KF 17408
#define F_VF (17408 + 8448)
#define F_AF (17408 + 8448 + 9504)
#define F_TOT (17408 + 8448 + 9504 + 10240)   // 45600 floats = 182400 B

// ---------------- ph2 smem layout ----------------
#define P2_QS   0
#define P2_PS   8704
#define P2_CS   (8704 + 17408)
#define P2_QP   (8704 + 17408 + 18432)
#define P2_DN   (8704 + 17408 + 18432 + 8704)
#define P2_TOT  (8704 + 17408 + 18432 + 8704 + 128)  // 53376 fl = 213504 B

// =====================================================================
// Phase 1 (warp-autonomous): each warp owns m-block [32w, 32w+32).
// =====================================================================
__global__ __launch_bounds__(256, 1) void ph1_kernel(
    const float* __restrict__ Kg, const float* __restrict__ Vg,
    const float* __restrict__ Pg)
{
    extern __shared__ __align__(16) float sm[];
    float* Ps = sm + F_PS;
    float* Kf = sm + F_KF;
    float* Vf = sm + F_VF;
    float* Af = sm + F_AF;

    const int tid = threadIdx.x;
    const int w = tid >> 5, l = tid & 31;
    const int g = l >> 2, tg = l & 3;
    const int bh = blockIdx.y, sp = blockIdx.x;

    // ---- load P [256][64] -> Ps (tf32) ----
    {
        const float4* P4 = reinterpret_cast<const float4*>(Pg);
        for (int i = tid; i < 4096; i += 256) {
            int m = i >> 4, d4 = i & 15;
            float4 x = P4[i];
            *reinterpret_cast<float4*>(&Ps[m * 68 + d4 * 4]) =
                make_float4(tf32r(x.x), tf32r(x.y), tf32r(x.z), tf32r(x.w));
        }
    }
    // ---- prefill Vf j=8 blocks (ksum column: e=64 -> 1.0, e=65..71 -> 0) ----
    for (int i = tid; i < 512; i += 256) {
        int blk = i >> 5, ll = i & 31, gg = ll >> 2;
        float vv = (gg == 0) ? 1.0f : 0.0f;
        *reinterpret_cast<float2*>(&Vf[(blk * 9 + 8) * 66 + ll * 2]) = make_float2(vv, vv);
    }
    __syncthreads();

    // ---- P fragments for this warp's m-block, in registers ----
    float Pf[8][4][2];
    #pragma unroll
    for (int k8 = 0; k8 < 8; k8++)
        #pragma unroll
        for (int j = 0; j < 4; j++) {
            const float* p = &Ps[(32 * w + 8 * j + g) * 68 + 8 * k8 + tg];
            Pf[k8][j][0] = p[0];
            Pf[k8][j][1] = p[4];
        }

    // ---- persistent ctx accumulators: [mf 2][j 9][4] ----
    float ctx[2][9][4];
    #pragma unroll
    for (int mf = 0; mf < 2; mf++)
        #pragma unroll
        for (int j = 0; j < 9; j++)
            #pragma unroll
            for (int q = 0; q < 4; q++) ctx[mf][j][q] = 0.0f;

    const float4* Kb = reinterpret_cast<const float4*>(
        Kg + ((size_t)bh * NN + (size_t)sp * NCHUNK) * DD);
    const float4* Vb = reinterpret_cast<const float4*>(
        Vg + ((size_t)bh * NN + (size_t)sp * NCHUNK) * DD);

    for (int t = 0; t < 4; t++) {
        __syncthreads();    // all warps done reading previous tile's Kf/Vf

        // ---- stage K,V tiles [128][64] into fragment-ordered smem ----
        for (int i = tid; i < 2048; i += 256) {
            int n = i >> 4, d4 = i & 15;
            int c = n >> 5, tok = n & 31;
            int tf = tok >> 4, gg = tok & 7, rhi = (tok >> 3) & 1;
            float4 kx = Kb[t * 2048 + i];
            float kv[4] = { kx.x, kx.y, kx.z, kx.w };
            #pragma unroll
            for (int e = 0; e < 4; e++) {
                int dd = 4 * d4 + e;
                int k8 = dd >> 3, tgg = dd & 3, khi = (dd >> 2) & 1;
                Kf[((c * 8 + k8) * 2 + tf) * 132 + (gg * 4 + tgg) * 4 + rhi + 2 * khi]
                    = tf32r(kv[e]);
            }
            int r = n & 31;
            int k8v = r >> 3, rr = r & 7;
            int half = rr >> 2, tgv = rr & 3;
            float4 vx = Vb[t * 2048 + i];
            float vv[4] = { vx.x, vx.y, vx.z, vx.w };
            #pragma unroll
            for (int e = 0; e < 4; e++) {
                int ee = 4 * d4 + e;
                int j = ee >> 3, ge = ee & 7;
                Vf[((c * 4 + k8v) * 9 + j) * 66 + (ge * 4 + tgv) * 2 + half]
                    = tf32r(vv[e]);
            }
        }
        __syncthreads();

        for (int c = 0; c < 4; c++) {
            // ---- G1: S[2 tokfrag][4 j][4] = K_chunk @ P_blk^T ----
            float S[2][4][4];
            #pragma unroll
            for (int tf = 0; tf < 2; tf++)
                #pragma unroll
                for (int j = 0; j < 4; j++)
                    #pragma unroll
                    for (int q = 0; q < 4; q++) S[tf][j][q] = 0.0f;

            #pragma unroll
            for (int k8 = 0; k8 < 8; k8++) {
                #pragma unroll
                for (int tf = 0; tf < 2; tf++) {
                    float4 av = *reinterpret_cast<const float4*>(
                        &Kf[((c * 8 + k8) * 2 + tf) * 132 + l * 4]);
                    uint32_t a0 = f2u(av.x), a1 = f2u(av.y), a2 = f2u(av.z), a3 = f2u(av.w);
                    #pragma unroll
                    for (int j = 0; j < 4; j++)
                        mma8(S[tf][j], a0, a1, a2, a3,
                             f2u(Pf[k8][j][0]), f2u(Pf[k8][j][1]));
                }
            }
            __syncwarp();

            // ---- gelu + scatter into per-warp A-fragment scratch ----
            #pragma unroll
            for (int tf = 0; tf < 2; tf++)
                #pragma unroll
                for (int mf = 0; mf < 2; mf++)
                    #pragma unroll
                    for (int e = 0; e < 4; e++) {
                        float x0 = tf32r(gelu_eps(S[tf][2 * mf][e]));
                        float x1 = tf32r(gelu_eps(S[tf][2 * mf + 1][e]));
                        int k8p = 2 * tf + (e >> 1);
                        int gc = 2 * tg + (e & 1);
                        *reinterpret_cast<float2*>(
                            &Af[w * 1280 + k8p * 320 + g * 40 + mf * 16 + gc * 2]) =
                            make_float2(x0, x1);
                    }
            __syncwarp();

            // ---- MMA2: ctx += kp_blk^T @ [V | 1 | 0]  (k = 32 tokens) ----
            #pragma unroll
            for (int k8p = 0; k8p < 4; k8p++) {
                const float* ab = &Af[w * 1280 + k8p * 320 + g * 2];
                float2 a01_0 = *reinterpret_cast<const float2*>(&ab[tg * 40]);
                float2 a23_0 = *reinterpret_cast<const float2*>(&ab[(tg + 4) * 40]);
                float2 a01_1 = *reinterpret_cast<const float2*>(&ab[tg * 40 + 16]);
                float2 a23_1 = *reinterpret_cast<const float2*>(&ab[(tg + 4) * 40 + 16]);
                const float* vbase = &Vf[((c * 4 + k8p) * 9) * 66 + l * 2];
                #pragma unroll
                for (int j = 0; j < 9; j++) {
                    float2 b = *reinterpret_cast<const float2*>(&vbase[j * 66]);
                    uint32_t b0 = f2u(b.x), b1 = f2u(b.y);
                    mma8(ctx[0][j], f2u(a01_0.x), f2u(a01_0.y), f2u(a23_0.x), f2u(a23_0.y), b0, b1);
                    mma8(ctx[1][j], f2u(a01_1.x), f2u(a01_1.y), f2u(a23_1.x), f2u(a23_1.y), b0, b1);
                }
            }
            __syncwarp();
        }
    }

    // ---- epilogue: write ctx partial [256][72] ----
    float* dst = g_ctxp + ((size_t)(bh * NSPLIT + sp)) * MM * CW;
    #pragma unroll
    for (int mf = 0; mf < 2; mf++) {
        int m = 32 * w + 16 * mf + g;
        #pragma unroll
        for (int j = 0; j < 9; j++) {
            int col = j * 8 + 2 * tg;
            *reinterpret_cast<float2*>(&dst[(size_t)m * CW + col]) =
                make_float2(ctx[mf][j][0], ctx[mf][j][1]);
            *reinterpret_cast<float2*>(&dst[(size_t)(m + 8) * CW + col]) =
                make_float2(ctx[mf][j][2], ctx[mf][j][3]);
        }
    }
}

// =====================================================================
// Reduce: fixed-order sum of 8 split partials; output tf32-rounded
// =====================================================================
__global__ __launch_bounds__(256) void reduce_kernel()
{
    const int bh = blockIdx.x, tid = threadIdx.x;
    const float* src = g_ctxp + (size_t)bh * NSPLIT * MM * CW;
    float* dst = g_ctx + (size_t)bh * MM * CW;
    for (int i = tid; i < MM * CW; i += 256) {
        float s = 0.0f;
        #pragma unroll
        for (int sp = 0; sp < NSPLIT; sp++) s += src[(size_t)sp * MM * CW + i];
        dst[i] = tf32r(s);
    }
}

// =====================================================================
// Phase 2: qp = gelu(Q@P^T)+eps ; out = (qp@[ctx|ksum])/denom
// =====================================================================
__global__ __launch_bounds__(512, 1) void ph2_kernel(
    const float* __restrict__ Qg, const float* __restrict__ Pg,
    float* __restrict__ Og)
{
    extern __shared__ __align__(16) float sm[];
    float* Qs  = sm + P2_QS;
    float* Ps  = sm + P2_PS;
    float* Cs  = sm + P2_CS;
    float* qps = sm + P2_QP;
    float* dnm = sm + P2_DN;

    const int tid = threadIdx.x;
    const int w = tid >> 5, l = tid & 31;
    const int g = l >> 2, tg = l & 3;
    const int bh = blockIdx.y, sp = blockIdx.x;

    {
        const float4* P4 = reinterpret_cast<const float4*>(Pg);
        for (int i = tid; i < 4096; i += 512) {
            int m = i >> 4, d4 = i & 15;
            float4 x = P4[i];
            *reinterpret_cast<float4*>(&Ps[m * 68 + d4 * 4]) =
                make_float4(tf32r(x.x), tf32r(x.y), tf32r(x.z), tf32r(x.w));
        }
    }
    {
        const float4* Cg = reinterpret_cast<const float4*>(g_ctx + (size_t)bh * MM * CW);
        for (int i = tid; i < MM * CW / 4; i += 512)
            *reinterpret_cast<float4*>(&Cs[i * 4]) = Cg[i];
    }

    const int rw3 = (w & 7) * 16;
    const int fg  = (w >> 3) * 32;
    const int rw  = (w & 7) * 16;
    const int cgr = w >> 3;
    const int joff = cgr ? 5 : 0;
    const int jcnt = cgr ? 4 : 5;

    for (int t = 0; t < 4; t++) {
        const float4* Qb = reinterpret_cast<const float4*>(
            Qg + ((size_t)bh * NN + (size_t)sp * NCHUNK + (size_t)t * 128) * DD);
        for (int i = tid; i < 2048; i += 512) {
            int n = i >> 4, d4 = i & 15;
            float4 x = Qb[i];
            *reinterpret_cast<float4*>(&Qs[n * 68 + d4 * 4]) =
                make_float4(tf32r(x.x), tf32r(x.y), tf32r(x.z), tf32r(x.w));
        }
        __syncthreads();

        float out[5][4];
        #pragma unroll
        for (int j = 0; j < 5; j++)
            #pragma unroll
            for (int q = 0; q < 4; q++) out[j][q] = 0.0f;

        for (int c = 0; c < 4; c++) {
            float S[4][4];
            #pragma unroll
            for (int j = 0; j < 4; j++)
                #pragma unroll
                for (int q = 0; q < 4; q++) S[j][q] = 0.0f;

            #pragma unroll
            for (int k8 = 0; k8 < 8; k8++) {
                const int kb = k8 * 8;
                const float* Qa = &Qs[(rw3 + g) * 68 + kb + tg];
                uint32_t a0 = f2u(Qa[0]);
                uint32_t a1 = f2u(Qa[8 * 68]);
                uint32_t a2 = f2u(Qa[4]);
                uint32_t a3 = f2u(Qa[8 * 68 + 4]);
                #pragma unroll
                for (int j = 0; j < 4; j++) {
                    const float* Pb = &Ps[(c * 64 + fg + j * 8 + g) * 68 + kb + tg];
                    mma8(S[j], a0, a1, a2, a3, f2u(Pb[0]), f2u(Pb[4]));
                }
            }
            #pragma unroll
            for (int j = 0; j < 4; j++) {
                int col = fg + j * 8 + 2 * tg;
                *reinterpret_cast<float2*>(&qps[(rw3 + g) * 68 + col]) =
                    make_float2(tf32r(gelu_eps(S[j][0])), tf32r(gelu_eps(S[j][1])));
                *reinterpret_cast<float2*>(&qps[(rw3 + g + 8) * 68 + col]) =
                    make_float2(tf32r(gelu_eps(S[j][2])), tf32r(gelu_eps(S[j][3])));
            }
            __syncthreads();

            #pragma unroll
            for (int k8 = 0; k8 < 8; k8++) {
                const int kb = k8 * 8;
                const float* Qa = &qps[(rw + g) * 68 + kb + tg];
                uint32_t a0 = f2u(Qa[0]);
                uint32_t a1 = f2u(Qa[8 * 68]);
                uint32_t a2 = f2u(Qa[4]);
                uint32_t a3 = f2u(Qa[8 * 68 + 4]);
                const float* Cb = &Cs[(c * 64 + kb + tg) * 72 + joff * 8 + g];
                #pragma unroll
                for (int j = 0; j < 5; j++) {
                    if (j < jcnt)
                        mma8(out[j], a0, a1, a2, a3,
                             f2u(Cb[j * 8]), f2u(Cb[4 * 72 + j * 8]));
                }
            }
            __syncthreads();
        }

        if (cgr == 1 && tg == 0) {
            dnm[rw + g] = out[3][0];
            dnm[rw + g + 8] = out[3][2];
        }
        __syncthreads();
        float di0 = 1.0f / dnm[rw + g];
        float di1 = 1.0f / dnm[rw + g + 8];
        float* dst = Og + ((size_t)bh * NN + (size_t)sp * NCHUNK + (size_t)t * 128 + rw + g) * DD;
        #pragma unroll
        for (int j = 0; j < 5; j++) {
            int jg = joff + j;
            if (jg < 8) {
                int col = jg * 8 + 2 * tg;
                *reinterpret_cast<float2*>(&dst[col]) =
                    make_float2(out[j][0] * di0, out[j][1] * di0);
                *reinterpret_cast<float2*>(&dst[(size_t)8 * DD + col]) =
                    make_float2(out[j][2] * di1, out[j][3] * di1);
            }
        }
        __syncthreads();
    }
}

// =====================================================================
// launch
// =====================================================================
extern "C" void kernel_launch(void* const* d_in, const int* in_sizes, int n_in,
                              void* d_out, int out_size)
{
    const float* q    = (const float*)d_in[0];
    const float* k    = (const float*)d_in[1];
    const float* v    = (const float*)d_in[2];
    const float* proj = (const float*)d_in[3];
    float* out = (float*)d_out;

    cudaFuncSetAttribute(ph1_kernel, cudaFuncAttributeMaxDynamicSharedMemorySize, F_TOT * 4);
    cudaFuncSetAttribute(ph2_kernel, cudaFuncAttributeMaxDynamicSharedMemorySize, P2_TOT * 4);

    ph1_kernel<<<dim3(NSPLIT, BH), 256, F_TOT * 4>>>(k, v, proj);
    reduce_kernel<<<BH, 256>>>();
    ph2_kernel<<<dim3(NSPLIT, BH), 512, P2_TOT * 4>>>(q, proj, out);
}

// round 11
// speedup vs baseline: 5.6621x; 1.3108x over previous
#include <cuda_runtime.h>
#include <cuda_fp16.h>
#include <cstdint>
#include <math.h>

// ---------------- problem constants ----------------
#define NN 4096
#define DD 64
#define MM 256
#define BH 64
#define NSPLIT 8
#define NCHUNK 512        // tokens per CTA (4 tiles of 128)
#define CW 72             // ctx width: 64 e-cols + ksum col + 7 pad (9 n8-frags)

// ---------------- scratch (no allocs allowed) ----------------
__device__ float g_ctxp[(size_t)BH * NSPLIT * MM * CW];   // partials
__device__ float g_ctx [(size_t)BH * MM * CW];            // reduced

// ---------------- helpers ----------------
__device__ __forceinline__ uint32_t pack_h2(float lo, float hi) {
    uint32_t r; asm("cvt.rn.f16x2.f32 %0, %2, %1;" : "=r"(r) : "f"(lo), "f"(hi));
    return r;
}
__device__ __forceinline__ void mma16(float c[4],
    uint32_t a0, uint32_t a1, uint32_t a2, uint32_t a3,
    uint32_t b0, uint32_t b1)
{
    asm volatile("mma.sync.aligned.m16n8k16.row.col.f32.f16.f16.f32 "
        "{%0,%1,%2,%3}, {%4,%5,%6,%7}, {%8,%9}, {%0,%1,%2,%3};"
        : "+f"(c[0]), "+f"(c[1]), "+f"(c[2]), "+f"(c[3])
        : "r"(a0), "r"(a1), "r"(a2), "r"(a3), "r"(b0), "r"(b1));
}
__device__ __forceinline__ float fast_rcp(float x) {
    float r; asm("rcp.approx.f32 %0, %1;" : "=f"(r) : "f"(x)); return r;
}
__device__ __forceinline__ float fast_ex2(float x) {
    float r; asm("ex2.approx.f32 %0, %1;" : "=f"(r) : "f"(x)); return r;
}
// Branchless gelu(x)+eps (Abramowitz-Stegun 7.1.26, abs err ~1.5e-7)
__device__ __forceinline__ float gelu_eps(float x) {
    float ax = fabsf(x);
    float t  = ax * 0.70710678118654752f;
    float k  = fast_rcp(fmaf(0.3275911f, t, 1.0f));
    float p  = fmaf(1.061405429f, k, -1.453152027f);
    p = fmaf(p, k, 1.421413741f);
    p = fmaf(p, k, -0.284496736f);
    p = fmaf(p, k, 0.254829592f);
    p = p * k;
    float e  = fast_ex2(-1.4426950408889634f * t * t);
    float h  = 0.5f * ax;
    float base = fmaf(0.5f, x, h) + 1e-6f;
    return fmaf(-h, p * e, base);
}

// ---------------- ph1 smem (u32 indices) ----------------
// Kf: 32 slots x 128 | Vf: 72 slots x 64 | Af: 8 warps x 512
// Pstage (B-frag, 8192 u32) aliases Kf+Vf (dead after Pf register load)
#define H1_KF 0
#define H1_VF 4096
#define H1_AF 8704
#define H1_TOT 12800          // 51200 bytes

// ---------------- ph2 smem (u32 indices) ----------------
#define H2_QF 0               // 4096: A-frags of Q tile
#define H2_PS 4096            // 8192: B-frags of P
#define H2_QP 12288           // 4096: A-frags of qp chunk
#define H2_CS 16384           // 9216: B-frags of ctx
#define H2_DN 25600           // 128 floats: denominators
#define H2_TOT 25728          // 102912 bytes

// =====================================================================
// Phase 1 (fp16): each warp owns m-block [32w, 32w+32).
// G1: kp = gelu(K_chunk @ P_blk^T); MMA2: ctx += kp^T @ [V | 1 | 0]
// =====================================================================
__global__ __launch_bounds__(256, 1) void ph1_kernel(
    const float* __restrict__ Kg, const float* __restrict__ Vg,
    const float* __restrict__ Pg)
{
    extern __shared__ __align__(16) uint32_t su[];
    uint32_t* Kf = su + H1_KF;
    uint32_t* Vf = su + H1_VF;
    uint32_t* Pstage = su;            // aliased
    uint32_t* Af = su + H1_AF;
    __half* Vfh = reinterpret_cast<__half*>(Vf);
    __half* Afh = reinterpret_cast<__half*>(Af);

    const int tid = threadIdx.x;
    const int w = tid >> 5, l = tid & 31;
    const int g = l >> 2, tg = l & 3;
    const int bh = blockIdx.y, sp = blockIdx.x;

    // ---- stage P [256 m][64 d] as B-frags (slot = (m>>3)*4 + k16) ----
    {
        const float4* P4 = reinterpret_cast<const float4*>(Pg);
        for (int i = tid; i < 4096; i += 256) {
            int m = i >> 4, d4 = i & 15;
            float4 x = P4[i];
            int slot = (m >> 3) * 4 + (d4 >> 2);
            int kk0 = (d4 & 3) * 4;
            int lane = (m & 7) * 4 + ((kk0 & 7) >> 1);
            int reg = kk0 >> 3;
            Pstage[slot * 64 + lane * 2 + reg] = pack_h2(x.x, x.y);
            Pstage[slot * 64 + (lane + 1) * 2 + reg] = pack_h2(x.z, x.w);
        }
    }
    __syncthreads();

    // ---- P fragments for this warp's m-block -> registers ----
    uint32_t Pf[4][4][2];
    #pragma unroll
    for (int k16 = 0; k16 < 4; k16++)
        #pragma unroll
        for (int j = 0; j < 4; j++) {
            int slot = (4 * w + j) * 4 + k16;
            uint2 b = *reinterpret_cast<const uint2*>(&Pstage[slot * 64 + l * 2]);
            Pf[k16][j][0] = b.x;
            Pf[k16][j][1] = b.y;
        }
    __syncthreads();   // Pstage dead; region reusable as Kf/Vf

    // ---- prefill Vf ksum slots (j=8): col e=64 -> 1.0, e=65..71 -> 0 ----
    for (int i = tid; i < 512; i += 256) {
        int s = i >> 6, pos = i & 63;
        int c = s >> 1, kp = s & 1;
        Vf[((c * 2 + kp) * 9 + 8) * 64 + pos] = (pos < 8) ? 0x3C003C00u : 0u;
    }

    // ---- persistent ctx accumulators ----
    float ctx[2][9][4];
    #pragma unroll
    for (int mf = 0; mf < 2; mf++)
        #pragma unroll
        for (int j = 0; j < 9; j++)
            #pragma unroll
            for (int q = 0; q < 4; q++) ctx[mf][j][q] = 0.0f;

    const float4* Kb = reinterpret_cast<const float4*>(
        Kg + ((size_t)bh * NN + (size_t)sp * NCHUNK) * DD);
    const float4* Vb = reinterpret_cast<const float4*>(
        Vg + ((size_t)bh * NN + (size_t)sp * NCHUNK) * DD);

    for (int t = 0; t < 4; t++) {
        // ---- stage K tile as A-frags, V tile as B-frags ----
        for (int i = tid; i < 2048; i += 256) {
            int n = i >> 4, d4 = i & 15;
            {   // K
                float4 x = Kb[t * 2048 + i];
                int c = n >> 5, tf = (n >> 4) & 1, r = n & 15;
                int slot = (c * 4 + (d4 >> 2)) * 2 + tf;
                int kk0 = (d4 & 3) * 4;
                int lane = (r & 7) * 4 + ((kk0 & 7) >> 1);
                int reg = (r >> 3) + 2 * (kk0 >> 3);
                Kf[slot * 128 + lane * 4 + reg] = pack_h2(x.x, x.y);
                Kf[slot * 128 + (lane + 1) * 4 + reg] = pack_h2(x.z, x.w);
            }
            {   // V
                float4 x = Vb[t * 2048 + i];
                int c = n >> 5, kp = (n >> 4) & 1, kk = n & 15;
                int tgv = (kk & 7) >> 1, regv = kk >> 3, hv = kk & 1;
                float vv[4] = { x.x, x.y, x.z, x.w };
                #pragma unroll
                for (int e4 = 0; e4 < 4; e4++) {
                    int e = 4 * d4 + e4;
                    int j = e >> 3, gp = e & 7;
                    int u32i = ((c * 2 + kp) * 9 + j) * 64 + (gp * 4 + tgv) * 2 + regv;
                    Vfh[2 * u32i + hv] = __float2half_rn(vv[e4]);
                }
            }
        }
        __syncthreads();

        for (int c = 0; c < 4; c++) {
            // ---- G1: S[2 tf][4 j][4] = K_chunk @ P_blk^T (4 k16 steps) ----
            float S[2][4][4];
            #pragma unroll
            for (int tf = 0; tf < 2; tf++)
                #pragma unroll
                for (int j = 0; j < 4; j++)
                    #pragma unroll
                    for (int q = 0; q < 4; q++) S[tf][j][q] = 0.0f;

            #pragma unroll
            for (int k16 = 0; k16 < 4; k16++) {
                #pragma unroll
                for (int tf = 0; tf < 2; tf++) {
                    uint4 av = *reinterpret_cast<const uint4*>(
                        &Kf[((c * 4 + k16) * 2 + tf) * 128 + l * 4]);
                    #pragma unroll
                    for (int j = 0; j < 4; j++)
                        mma16(S[tf][j], av.x, av.y, av.z, av.w,
                              Pf[k16][j][0], Pf[k16][j][1]);
                }
            }
            __syncwarp();

            // ---- gelu + scatter to per-warp A-frag scratch (fp16) ----
            #pragma unroll
            for (int tf = 0; tf < 2; tf++)
                #pragma unroll
                for (int j = 0; j < 4; j++) {
                    int mf = j >> 1;
                    #pragma unroll
                    for (int e = 0; e < 4; e++) {
                        float v = gelu_eps(S[tf][j][e]);
                        int reg = (j & 1) + 2 * (e >> 1);
                        int lane2 = (2 * tg + (e & 1)) * 4 + (g >> 1);
                        int idx = w * 512 + (tf * 2 + mf) * 128 + lane2 * 4 + reg;
                        Afh[2 * idx + (g & 1)] = __float2half_rn(v);
                    }
                }
            __syncwarp();

            // ---- MMA2: ctx += kp^T @ [V|1|0]  (2 k16 steps) ----
            #pragma unroll
            for (int kp = 0; kp < 2; kp++) {
                uint4 A0 = *reinterpret_cast<const uint4*>(
                    &Af[w * 512 + (kp * 2 + 0) * 128 + l * 4]);
                uint4 A1 = *reinterpret_cast<const uint4*>(
                    &Af[w * 512 + (kp * 2 + 1) * 128 + l * 4]);
                #pragma unroll
                for (int j = 0; j < 9; j++) {
                    uint2 b = *reinterpret_cast<const uint2*>(
                        &Vf[((c * 2 + kp) * 9 + j) * 64 + l * 2]);
                    mma16(ctx[0][j], A0.x, A0.y, A0.z, A0.w, b.x, b.y);
                    mma16(ctx[1][j], A1.x, A1.y, A1.z, A1.w, b.x, b.y);
                }
            }
            __syncwarp();
        }
        __syncthreads();   // before next tile's staging overwrites Kf/Vf
    }

    // ---- epilogue: write ctx partial [256][72] (f32) ----
    float* dst = g_ctxp + ((size_t)(bh * NSPLIT + sp)) * MM * CW;
    #pragma unroll
    for (int mf = 0; mf < 2; mf++) {
        int m = 32 * w + 16 * mf + g;
        #pragma unroll
        for (int j = 0; j < 9; j++) {
            int col = j * 8 + 2 * tg;
            *reinterpret_cast<float2*>(&dst[(size_t)m * CW + col]) =
                make_float2(ctx[mf][j][0], ctx[mf][j][1]);
            *reinterpret_cast<float2*>(&dst[(size_t)(m + 8) * CW + col]) =
                make_float2(ctx[mf][j][2], ctx[mf][j][3]);
        }
    }
}

// =====================================================================
// Reduce: fixed-order sum of 8 split partials (256 blocks)
// =====================================================================
__global__ __launch_bounds__(256) void reduce_kernel()
{
    const int b = blockIdx.x;           // 0..255
    const int bh = b >> 2, q = b & 3;
    const float* src = g_ctxp + (size_t)bh * NSPLIT * MM * CW + q * 4608;
    float* dst = g_ctx + (size_t)bh * MM * CW + q * 4608;
    for (int i = threadIdx.x; i < 4608; i += 256) {
        float s = 0.0f;
        #pragma unroll
        for (int sp = 0; sp < NSPLIT; sp++) s += src[(size_t)sp * MM * CW + i];
        dst[i] = s;
    }
}

// =====================================================================
// Phase 2 (fp16): qp = gelu(Q@P^T)+eps ; out = (qp@[ctx|ksum])/denom
// 512 threads: warp = (tf = w&7 token group, fh = w>>3 feature/col half)
// =====================================================================
__global__ __launch_bounds__(512, 1) void ph2_kernel(
    const float* __restrict__ Qg, const float* __restrict__ Pg,
    float* __restrict__ Og)
{
    extern __shared__ __align__(16) uint32_t su[];
    uint32_t* Qf  = su + H2_QF;
    uint32_t* Ps  = su + H2_PS;
    uint32_t* qps = su + H2_QP;
    uint32_t* Cs  = su + H2_CS;
    float* dnm = reinterpret_cast<float*>(su + H2_DN);

    const int tid = threadIdx.x;
    const int w = tid >> 5, l = tid & 31;
    const int g = l >> 2, tg = l & 3;
    const int bh = blockIdx.y, sp = blockIdx.x;

    // ---- stage P as B-frags ----
    {
        const float4* P4 = reinterpret_cast<const float4*>(Pg);
        for (int i = tid; i < 4096; i += 512) {
            int m = i >> 4, d4 = i & 15;
            float4 x = P4[i];
            int slot = (m >> 3) * 4 + (d4 >> 2);
            int kk0 = (d4 & 3) * 4;
            int lane = (m & 7) * 4 + ((kk0 & 7) >> 1);
            int reg = kk0 >> 3;
            Ps[slot * 64 + lane * 2 + reg] = pack_h2(x.x, x.y);
            Ps[slot * 64 + (lane + 1) * 2 + reg] = pack_h2(x.z, x.w);
        }
    }
    // ---- stage ctx [256 f][72 e] as B-frags (pack f-pairs) ----
    {
        const float* Cg = g_ctx + (size_t)bh * MM * CW;
        for (int i = tid; i < 9216; i += 512) {
            int e = i % 72, fp = i / 72;
            int f = fp * 2;
            float lo = Cg[f * CW + e], hi = Cg[(f + 1) * CW + e];
            int c = f >> 6, kf = (f & 63) >> 4, kk = f & 15;   // kk even
            int j = e >> 3, gp = e & 7;
            int idx = ((c * 4 + kf) * 9 + j) * 64 + (gp * 4 + ((kk & 7) >> 1)) * 2 + (kk >> 3);
            Cs[idx] = pack_h2(lo, hi);
        }
    }
    __syncthreads();

    const int tf = w & 7;          // token group (16 rows)
    const int fh = w >> 3;         // feature/col half
    const int joff = fh ? 5 : 0;
    const int jcnt = fh ? 4 : 5;

    const float4* Qb = reinterpret_cast<const float4*>(
        Qg + ((size_t)bh * NN + (size_t)sp * NCHUNK) * DD);

    for (int t = 0; t < 4; t++) {
        // ---- stage Q tile as A-frags ----
        for (int i = tid; i < 2048; i += 512) {
            int n = i >> 4, d4 = i & 15;
            float4 x = Qb[t * 2048 + i];
            int slot = (n >> 4) * 4 + (d4 >> 2);
            int kk0 = (d4 & 3) * 4;
            int r = n & 15;
            int lane = (r & 7) * 4 + ((kk0 & 7) >> 1);
            int reg = (r >> 3) + 2 * (kk0 >> 3);
            Qf[slot * 128 + lane * 4 + reg] = pack_h2(x.x, x.y);
            Qf[slot * 128 + (lane + 1) * 4 + reg] = pack_h2(x.z, x.w);
        }
        __syncthreads();

        float out[5][4];
        #pragma unroll
        for (int j = 0; j < 5; j++)
            #pragma unroll
            for (int q = 0; q < 4; q++) out[j][q] = 0.0f;

        for (int c = 0; c < 4; c++) {
            // ---- G3: S[4 j][4] = Q(tf rows) @ P^T (warp's 32 features) ----
            float S[4][4];
            #pragma unroll
            for (int j = 0; j < 4; j++)
                #pragma unroll
                for (int q = 0; q < 4; q++) S[j][q] = 0.0f;

            #pragma unroll
            for (int k16 = 0; k16 < 4; k16++) {
                uint4 av = *reinterpret_cast<const uint4*>(
                    &Qf[(tf * 4 + k16) * 128 + l * 4]);
                #pragma unroll
                for (int j = 0; j < 4; j++) {
                    int ngrp = c * 8 + fh * 4 + j;
                    uint2 b = *reinterpret_cast<const uint2*>(
                        &Ps[(ngrp * 4 + k16) * 64 + l * 2]);
                    mma16(S[j], av.x, av.y, av.z, av.w, b.x, b.y);
                }
            }
            // ---- gelu -> qps A-frags (own-lane packed stores) ----
            #pragma unroll
            for (int j = 0; j < 4; j++) {
                int kf = fh * 2 + (j >> 1);
                int base = (tf * 4 + kf) * 128 + l * 4 + 2 * (j & 1);
                qps[base]     = pack_h2(gelu_eps(S[j][0]), gelu_eps(S[j][1]));
                qps[base + 1] = pack_h2(gelu_eps(S[j][2]), gelu_eps(S[j][3]));
            }
            __syncthreads();

            // ---- G4: out += qp_chunk @ ctx_chunk (this warp's col group) ----
            #pragma unroll
            for (int kf = 0; kf < 4; kf++) {
                uint4 av = *reinterpret_cast<const uint4*>(
                    &qps[(tf * 4 + kf) * 128 + l * 4]);
                #pragma unroll
                for (int jj = 0; jj < 5; jj++) {
                    if (jj < jcnt) {
                        int jg = joff + jj;
                        uint2 b = *reinterpret_cast<const uint2*>(
                            &Cs[((c * 4 + kf) * 9 + jg) * 64 + l * 2]);
                        mma16(out[jj], av.x, av.y, av.z, av.w, b.x, b.y);
                    }
                }
            }
            __syncthreads();
        }

        // ---- epilogue: divide by denom (col 64 = fh1 jj=3, tg=0) ----
        int rw = tf * 16;
        if (fh == 1 && tg == 0) {
            dnm[rw + g] = out[3][0];
            dnm[rw + g + 8] = out[3][2];
        }
        __syncthreads();
        float di0 = 1.0f / dnm[rw + g];
        float di1 = 1.0f / dnm[rw + g + 8];
        float* dst = Og + ((size_t)bh * NN + (size_t)sp * NCHUNK + (size_t)t * 128 + rw + g) * DD;
        #pragma unroll
        for (int jj = 0; jj < 5; jj++) {
            int jg = joff + jj;
            if (jg < 8) {
                int col = jg * 8 + 2 * tg;
                *reinterpret_cast<float2*>(&dst[col]) =
                    make_float2(out[jj][0] * di0, out[jj][1] * di0);
                *reinterpret_cast<float2*>(&dst[(size_t)8 * DD + col]) =
                    make_float2(out[jj][2] * di1, out[jj][3] * di1);
            }
        }
        __syncthreads();
    }
}

// =====================================================================
// launch
// =====================================================================
extern "C" void kernel_launch(void* const* d_in, const int* in_sizes, int n_in,
                              void* d_out, int out_size)
{
    const float* q    = (const float*)d_in[0];
    const float* k    = (const float*)d_in[1];
    const float* v    = (const float*)d_in[2];
    const float* proj = (const float*)d_in[3];
    float* out = (float*)d_out;

    cudaFuncSetAttribute(ph1_kernel, cudaFuncAttributeMaxDynamicSharedMemorySize, H1_TOT * 4);
    cudaFuncSetAttribute(ph2_kernel, cudaFuncAttributeMaxDynamicSharedMemorySize, H2_TOT * 4);

    ph1_kernel<<<dim3(NSPLIT, BH), 256, H1_TOT * 4>>>(k, v, proj);
    reduce_kernel<<<BH * 4, 256>>>();
    ph2_kernel<<<dim3(NSPLIT, BH), 512, H2_TOT * 4>>>(q, proj, out);
}

// round 13
// speedup vs baseline: 6.2809x; 1.1093x over previous
#include <cuda_runtime.h>
#include <cuda_fp16.h>
#include <cstdint>
#include <math.h>

// ---------------- problem constants ----------------
#define NN 4096
#define DD 64
#define MM 256
#define BH 64
#define NSPLIT 8
#define NCHUNK 512        // tokens per CTA (4 tiles of 128)
#define CW 72             // ctx width: 64 e-cols + ksum col + 7 pad (9 n8-frags)

// ---------------- scratch (no allocs allowed) ----------------
__device__ float g_ctxp[(size_t)BH * NSPLIT * MM * CW];   // partials
__device__ float g_ctx [(size_t)BH * MM * CW];            // reduced

// ---------------- helpers ----------------
__device__ __forceinline__ uint32_t pack_h2(float lo, float hi) {
    uint32_t r; asm("cvt.rn.f16x2.f32 %0, %2, %1;" : "=r"(r) : "f"(lo), "f"(hi));
    return r;
}
__device__ __forceinline__ uint32_t movm(uint32_t x) {
    uint32_t d;
    asm volatile("movmatrix.sync.aligned.m8n8.trans.b16 %0, %1;" : "=r"(d) : "r"(x));
    return d;
}
__device__ __forceinline__ void mma16(float c[4],
    uint32_t a0, uint32_t a1, uint32_t a2, uint32_t a3,
    uint32_t b0, uint32_t b1)
{
    asm volatile("mma.sync.aligned.m16n8k16.row.col.f32.f16.f16.f32 "
        "{%0,%1,%2,%3}, {%4,%5,%6,%7}, {%8,%9}, {%0,%1,%2,%3};"
        : "+f"(c[0]), "+f"(c[1]), "+f"(c[2]), "+f"(c[3])
        : "r"(a0), "r"(a1), "r"(a2), "r"(a3), "r"(b0), "r"(b1));
}
__device__ __forceinline__ float fast_rcp(float x) {
    float r; asm("rcp.approx.f32 %0, %1;" : "=f"(r) : "f"(x)); return r;
}
__device__ __forceinline__ float fast_ex2(float x) {
    float r; asm("ex2.approx.f32 %0, %1;" : "=f"(r) : "f"(x)); return r;
}
// Branchless gelu(x)+eps (Abramowitz-Stegun 7.1.26, abs err ~1.5e-7)
__device__ __forceinline__ float gelu_eps(float x) {
    float ax = fabsf(x);
    float t  = ax * 0.70710678118654752f;
    float k  = fast_rcp(fmaf(0.3275911f, t, 1.0f));
    float p  = fmaf(1.061405429f, k, -1.453152027f);
    p = fmaf(p, k, 1.421413741f);
    p = fmaf(p, k, -0.284496736f);
    p = fmaf(p, k, 0.254829592f);
    p = p * k;
    float e  = fast_ex2(-1.4426950408889634f * t * t);
    float h  = 0.5f * ax;
    float base = fmaf(0.5f, x, h) + 1e-6f;
    return fmaf(-h, p * e, base);
}

// ---------------- ph1 smem (u32 indices) ----------------
// Kf: 32 slots x 128 | Vf: 72 slots x 64.  Pstage (8192 u32) aliases both.
#define H1_KF 0
#define H1_VF 4096
#define H1_TOT 8704           // 34816 bytes

// ---------------- ph2 smem (u32 indices) ----------------
#define H2_QF 0               // 4096: A-frags of Q tile
#define H2_PS 4096            // 8192: B-frags of P
#define H2_CS 12288           // 9216: B-frags of ctx
#define H2_RS 21504           // 9216: fh-pair reduction buffer (floats)
#define H2_TOT 30720          // 122880 bytes

// =====================================================================
// Phase 1 (fp16 + movmatrix): warp owns m-block [32w, 32w+32).
// G1: kp = gelu(K_chunk @ P_blk^T) -> registers -> movmatrix -> MMA2 A
// MMA2: ctx += kp^T @ [V | 1 | 0].  No smem round-trip for kp.
// =====================================================================
__global__ __launch_bounds__(256, 1) void ph1_kernel(
    const float* __restrict__ Kg, const float* __restrict__ Vg,
    const float* __restrict__ Pg)
{
    extern __shared__ __align__(16) uint32_t su[];
    uint32_t* Kf = su + H1_KF;
    uint32_t* Vf = su + H1_VF;
    uint32_t* Pstage = su;            // aliased; dead after Pf reg load
    __half* Vfh = reinterpret_cast<__half*>(Vf);

    const int tid = threadIdx.x;
    const int w = tid >> 5, l = tid & 31;
    const int g = l >> 2, tg = l & 3;
    const int bh = blockIdx.y, sp = blockIdx.x;

    // ---- stage P [256 m][64 d] as B-frags (slot = (m>>3)*4 + k16) ----
    {
        const float4* P4 = reinterpret_cast<const float4*>(Pg);
        for (int i = tid; i < 4096; i += 256) {
            int m = i >> 4, d4 = i & 15;
            float4 x = P4[i];
            int slot = (m >> 3) * 4 + (d4 >> 2);
            int kk0 = (d4 & 3) * 4;
            int lane = (m & 7) * 4 + ((kk0 & 7) >> 1);
            int reg = kk0 >> 3;
            Pstage[slot * 64 + lane * 2 + reg] = pack_h2(x.x, x.y);
            Pstage[slot * 64 + (lane + 1) * 2 + reg] = pack_h2(x.z, x.w);
        }
    }
    __syncthreads();

    // ---- P fragments for this warp's m-block -> registers ----
    uint32_t Pf[4][4][2];
    #pragma unroll
    for (int k16 = 0; k16 < 4; k16++)
        #pragma unroll
        for (int j = 0; j < 4; j++) {
            int slot = (4 * w + j) * 4 + k16;
            uint2 b = *reinterpret_cast<const uint2*>(&Pstage[slot * 64 + l * 2]);
            Pf[k16][j][0] = b.x;
            Pf[k16][j][1] = b.y;
        }
    __syncthreads();   // Pstage dead; region reusable as Kf/Vf

    // ---- prefill Vf ksum slots (j=8): col e=64 -> 1.0, e=65..71 -> 0 ----
    for (int i = tid; i < 512; i += 256) {
        int s = i >> 6, pos = i & 63;
        int c = s >> 1, kp = s & 1;
        Vf[((c * 2 + kp) * 9 + 8) * 64 + pos] = (pos < 8) ? 0x3C003C00u : 0u;
    }

    // ---- persistent ctx accumulators ----
    float ctx[2][9][4];
    #pragma unroll
    for (int mf = 0; mf < 2; mf++)
        #pragma unroll
        for (int j = 0; j < 9; j++)
            #pragma unroll
            for (int q = 0; q < 4; q++) ctx[mf][j][q] = 0.0f;

    const float4* Kb = reinterpret_cast<const float4*>(
        Kg + ((size_t)bh * NN + (size_t)sp * NCHUNK) * DD);
    const float4* Vb = reinterpret_cast<const float4*>(
        Vg + ((size_t)bh * NN + (size_t)sp * NCHUNK) * DD);

    for (int t = 0; t < 4; t++) {
        // ---- stage K tile as A-frags, V tile as B-frags ----
        for (int i = tid; i < 2048; i += 256) {
            int n = i >> 4, d4 = i & 15;
            {   // K
                float4 x = Kb[t * 2048 + i];
                int c = n >> 5, tf = (n >> 4) & 1, r = n & 15;
                int slot = (c * 4 + (d4 >> 2)) * 2 + tf;
                int kk0 = (d4 & 3) * 4;
                int lane = (r & 7) * 4 + ((kk0 & 7) >> 1);
                int reg = (r >> 3) + 2 * (kk0 >> 3);
                Kf[slot * 128 + lane * 4 + reg] = pack_h2(x.x, x.y);
                Kf[slot * 128 + (lane + 1) * 4 + reg] = pack_h2(x.z, x.w);
            }
            {   // V
                float4 x = Vb[t * 2048 + i];
                int c = n >> 5, kp = (n >> 4) & 1, kk = n & 15;
                int tgv = (kk & 7) >> 1, regv = kk >> 3, hv = kk & 1;
                float vv[4] = { x.x, x.y, x.z, x.w };
                #pragma unroll
                for (int e4 = 0; e4 < 4; e4++) {
                    int e = 4 * d4 + e4;
                    int j = e >> 3, gp = e & 7;
                    int u32i = ((c * 2 + kp) * 9 + j) * 64 + (gp * 4 + tgv) * 2 + regv;
                    Vfh[2 * u32i + hv] = __float2half_rn(vv[e4]);
                }
            }
        }
        __syncthreads();

        for (int c = 0; c < 4; c++) {
            // ---- G1: S[2 tf][4 j][4] = K_chunk @ P_blk^T ----
            float S[2][4][4];
            #pragma unroll
            for (int tf = 0; tf < 2; tf++)
                #pragma unroll
                for (int j = 0; j < 4; j++)
                    #pragma unroll
                    for (int q = 0; q < 4; q++) S[tf][j][q] = 0.0f;

            #pragma unroll
            for (int k16 = 0; k16 < 4; k16++) {
                #pragma unroll
                for (int tf = 0; tf < 2; tf++) {
                    uint4 av = *reinterpret_cast<const uint4*>(
                        &Kf[((c * 4 + k16) * 2 + tf) * 128 + l * 4]);
                    #pragma unroll
                    for (int j = 0; j < 4; j++)
                        mma16(S[tf][j], av.x, av.y, av.z, av.w,
                              Pf[k16][j][0], Pf[k16][j][1]);
                }
            }

            // ---- gelu + pack + in-register transpose (movmatrix) ----
            uint32_t Tlo[2][4], Thi[2][4];
            #pragma unroll
            for (int tf = 0; tf < 2; tf++)
                #pragma unroll
                for (int j = 0; j < 4; j++) {
                    uint32_t lo = pack_h2(gelu_eps(S[tf][j][0]), gelu_eps(S[tf][j][1]));
                    uint32_t hi = pack_h2(gelu_eps(S[tf][j][2]), gelu_eps(S[tf][j][3]));
                    Tlo[tf][j] = movm(lo);
                    Thi[tf][j] = movm(hi);
                }

            // ---- MMA2: ctx += kp^T @ [V|1|0]  (A straight from registers) ----
            #pragma unroll
            for (int kp = 0; kp < 2; kp++) {
                #pragma unroll
                for (int j = 0; j < 9; j++) {
                    uint2 b = *reinterpret_cast<const uint2*>(
                        &Vf[((c * 2 + kp) * 9 + j) * 64 + l * 2]);
                    mma16(ctx[0][j], Tlo[kp][0], Tlo[kp][1], Thi[kp][0], Thi[kp][1], b.x, b.y);
                    mma16(ctx[1][j], Tlo[kp][2], Tlo[kp][3], Thi[kp][2], Thi[kp][3], b.x, b.y);
                }
            }
        }
        __syncthreads();   // before next tile's staging overwrites Kf/Vf
    }

    // ---- epilogue: write ctx partial [256][72] (f32) ----
    float* dst = g_ctxp + ((size_t)(bh * NSPLIT + sp)) * MM * CW;
    #pragma unroll
    for (int mf = 0; mf < 2; mf++) {
        int m = 32 * w + 16 * mf + g;
        #pragma unroll
        for (int j = 0; j < 9; j++) {
            int col = j * 8 + 2 * tg;
            *reinterpret_cast<float2*>(&dst[(size_t)m * CW + col]) =
                make_float2(ctx[mf][j][0], ctx[mf][j][1]);
            *reinterpret_cast<float2*>(&dst[(size_t)(m + 8) * CW + col]) =
                make_float2(ctx[mf][j][2], ctx[mf][j][3]);
        }
    }
}

// =====================================================================
// Reduce: fixed-order sum of 8 split partials (256 blocks)
// =====================================================================
__global__ __launch_bounds__(256) void reduce_kernel()
{
    const int b = blockIdx.x;           // 0..255
    const int bh = b >> 2, q = b & 3;
    const float* src = g_ctxp + (size_t)bh * NSPLIT * MM * CW + q * 4608;
    float* dst = g_ctx + (size_t)bh * MM * CW + q * 4608;
    for (int i = threadIdx.x; i < 4608; i += 256) {
        float s = 0.0f;
        #pragma unroll
        for (int sp = 0; sp < NSPLIT; sp++) s += src[(size_t)sp * MM * CW + i];
        dst[i] = s;
    }
}

// =====================================================================
// Phase 2 (fp16, barrier-free chunk loop): warp (tf=w&7, fh=w>>3).
// Each warp accumulates FULL 72-col out with its own 32 features (k-split);
// qp goes straight from G3 accumulators into G4 A-frags (no smem, no sync).
// fh pairs merge partial outs once per tile.
// =====================================================================
__global__ __launch_bounds__(512, 1) void ph2_kernel(
    const float* __restrict__ Qg, const float* __restrict__ Pg,
    float* __restrict__ Og)
{
    extern __shared__ __align__(16) uint32_t su[];
    uint32_t* Qf  = su + H2_QF;
    uint32_t* Ps  = su + H2_PS;
    uint32_t* Cs  = su + H2_CS;
    float* Rs = reinterpret_cast<float*>(su + H2_RS);

    const int tid = threadIdx.x;
    const int w = tid >> 5, l = tid & 31;
    const int g = l >> 2, tg = l & 3;
    const int bh = blockIdx.y, sp = blockIdx.x;

    // ---- stage P as B-frags ----
    {
        const float4* P4 = reinterpret_cast<const float4*>(Pg);
        for (int i = tid; i < 4096; i += 512) {
            int m = i >> 4, d4 = i & 15;
            float4 x = P4[i];
            int slot = (m >> 3) * 4 + (d4 >> 2);
            int kk0 = (d4 & 3) * 4;
            int lane = (m & 7) * 4 + ((kk0 & 7) >> 1);
            int reg = kk0 >> 3;
            Ps[slot * 64 + lane * 2 + reg] = pack_h2(x.x, x.y);
            Ps[slot * 64 + (lane + 1) * 2 + reg] = pack_h2(x.z, x.w);
        }
    }
    // ---- stage ctx [256 f][72 e] as B-frags (pack f-pairs) ----
    {
        const float* Cg = g_ctx + (size_t)bh * MM * CW;
        for (int i = tid; i < 9216; i += 512) {
            int e = i % 72, fp = i / 72;
            int f = fp * 2;
            float lo = Cg[f * CW + e], hi = Cg[(f + 1) * CW + e];
            int c = f >> 6, kf = (f & 63) >> 4, kk = f & 15;   // kk even
            int j = e >> 3, gp = e & 7;
            int idx = ((c * 4 + kf) * 9 + j) * 64 + (gp * 4 + ((kk & 7) >> 1)) * 2 + (kk >> 3);
            Cs[idx] = pack_h2(lo, hi);
        }
    }
    __syncthreads();

    const int tf = w & 7;          // token group (16 rows)
    const int fh = w >> 3;         // feature half (k-split group)

    const float4* Qb = reinterpret_cast<const float4*>(
        Qg + ((size_t)bh * NN + (size_t)sp * NCHUNK) * DD);

    for (int t = 0; t < 4; t++) {
        if (t) __syncthreads();     // protect Qf/Rs reuse across tiles

        // ---- stage Q tile as A-frags ----
        for (int i = tid; i < 2048; i += 512) {
            int n = i >> 4, d4 = i & 15;
            float4 x = Qb[t * 2048 + i];
            int slot = (n >> 4) * 4 + (d4 >> 2);
            int kk0 = (d4 & 3) * 4;
            int r = n & 15;
            int lane = (r & 7) * 4 + ((kk0 & 7) >> 1);
            int reg = (r >> 3) + 2 * (kk0 >> 3);
            Qf[slot * 128 + lane * 4 + reg] = pack_h2(x.x, x.y);
            Qf[slot * 128 + (lane + 1) * 4 + reg] = pack_h2(x.z, x.w);
        }
        __syncthreads();

        float out[9][4];
        #pragma unroll
        for (int j = 0; j < 9; j++)
            #pragma unroll
            for (int q = 0; q < 4; q++) out[j][q] = 0.0f;

        for (int c = 0; c < 4; c++) {
            // ---- G3: S[4 j][4] = Q(tf rows) @ P^T (this warp's 32 feats) ----
            float S[4][4];
            #pragma unroll
            for (int j = 0; j < 4; j++)
                #pragma unroll
                for (int q = 0; q < 4; q++) S[j][q] = 0.0f;

            #pragma unroll
            for (int k16 = 0; k16 < 4; k16++) {
                uint4 av = *reinterpret_cast<const uint4*>(
                    &Qf[(tf * 4 + k16) * 128 + l * 4]);
                #pragma unroll
                for (int j = 0; j < 4; j++) {
                    int ngrp = c * 8 + fh * 4 + j;
                    uint2 b = *reinterpret_cast<const uint2*>(
                        &Ps[(ngrp * 4 + k16) * 64 + l * 2]);
                    mma16(S[j], av.x, av.y, av.z, av.w, b.x, b.y);
                }
            }

            // ---- gelu -> A-frags in registers; G4 over this warp's k16s ----
            #pragma unroll
            for (int kfl = 0; kfl < 2; kfl++) {
                int jlo = 2 * kfl, jhi = 2 * kfl + 1;
                uint32_t a0 = pack_h2(gelu_eps(S[jlo][0]), gelu_eps(S[jlo][1]));
                uint32_t a1 = pack_h2(gelu_eps(S[jlo][2]), gelu_eps(S[jlo][3]));
                uint32_t a2 = pack_h2(gelu_eps(S[jhi][0]), gelu_eps(S[jhi][1]));
                uint32_t a3 = pack_h2(gelu_eps(S[jhi][2]), gelu_eps(S[jhi][3]));
                int kf = fh * 2 + kfl;
                #pragma unroll
                for (int j = 0; j < 9; j++) {
                    uint2 b = *reinterpret_cast<const uint2*>(
                        &Cs[((c * 4 + kf) * 9 + j) * 64 + l * 2]);
                    mma16(out[j], a0, a1, a2, a3, b.x, b.y);
                }
            }
        }

        // ---- merge fh pair: fh=1 stores partials, fh=0 adds + epilogue ----
        if (fh == 1) {
            #pragma unroll
            for (int j = 0; j < 9; j++)
                *reinterpret_cast<float4*>(&Rs[((j * 8 + tf) * 32 + l) * 4]) =
                    make_float4(out[j][0], out[j][1], out[j][2], out[j][3]);
        }
        __syncthreads();
        if (fh == 0) {
            #pragma unroll
            for (int j = 0; j < 9; j++) {
                float4 r = *reinterpret_cast<const float4*>(&Rs[((j * 8 + tf) * 32 + l) * 4]);
                out[j][0] += r.x; out[j][1] += r.y; out[j][2] += r.z; out[j][3] += r.w;
            }
            // denominator (col 64 = j 8, elems 0/2 at tg==0) -> broadcast
            float d0 = __shfl_sync(0xffffffffu, out[8][0], l & ~3);
            float d1 = __shfl_sync(0xffffffffu, out[8][2], l & ~3);
            float di0 = 1.0f / d0, di1 = 1.0f / d1;
            float* dst = Og + ((size_t)bh * NN + (size_t)sp * NCHUNK
                               + (size_t)t * 128 + tf * 16 + g) * DD;
            #pragma unroll
            for (int j = 0; j < 8; j++) {
                int col = j * 8 + 2 * tg;
                *reinterpret_cast<float2*>(&dst[col]) =
                    make_float2(out[j][0] * di0, out[j][1] * di0);
                *reinterpret_cast<float2*>(&dst[(size_t)8 * DD + col]) =
                    make_float2(out[j][2] * di1, out[j][3] * di1);
            }
        }
    }
}

// =====================================================================
// launch
// =====================================================================
extern "C" void kernel_launch(void* const* d_in, const int* in_sizes, int n_in,
                              void* d_out, int out_size)
{
    const float* q    = (const float*)d_in[0];
    const float* k    = (const float*)d_in[1];
    const float* v    = (const float*)d_in[2];
    const float* proj = (const float*)d_in[3];
    float* out = (float*)d_out;

    cudaFuncSetAttribute(ph1_kernel, cudaFuncAttributeMaxDynamicSharedMemorySize, H1_TOT * 4);
    cudaFuncSetAttribute(ph2_kernel, cudaFuncAttributeMaxDynamicSharedMemorySize, H2_TOT * 4);

    ph1_kernel<<<dim3(NSPLIT, BH), 256, H1_TOT * 4>>>(k, v, proj);
    reduce_kernel<<<BH * 4, 256>>>();
    ph2_kernel<<<dim3(NSPLIT, BH), 512, H2_TOT * 4>>>(q, proj, out);
}

// round 14
// speedup vs baseline: 6.5416x; 1.0415x over previous
#include <cuda_runtime.h>
#include <cuda_fp16.h>
#include <cstdint>
#include <math.h>

// ---------------- problem constants ----------------
#define NN 4096
#define DD 64
#define MM 256
#define BH 64
#define NSPLIT 8
#define NCHUNK 512        // tokens per CTA (4 tiles of 128)
#define CW 72             // ctx width: 64 e-cols + ksum col + 7 pad (9 n8-frags)

// ---------------- scratch (no allocs allowed) ----------------
__device__ float g_ctxp[(size_t)BH * NSPLIT * MM * CW];   // partials
__device__ float g_ctx [(size_t)BH * MM * CW];            // reduced

// ---------------- helpers ----------------
__device__ __forceinline__ uint32_t pack_h2(float lo, float hi) {
    uint32_t r; asm("cvt.rn.f16x2.f32 %0, %2, %1;" : "=r"(r) : "f"(lo), "f"(hi));
    return r;
}
__device__ __forceinline__ uint32_t movm(uint32_t x) {
    uint32_t d;
    asm volatile("movmatrix.sync.aligned.m8n8.trans.b16 %0, %1;" : "=r"(d) : "r"(x));
    return d;
}
__device__ __forceinline__ void mma16(float c[4],
    uint32_t a0, uint32_t a1, uint32_t a2, uint32_t a3,
    uint32_t b0, uint32_t b1)
{
    asm volatile("mma.sync.aligned.m16n8k16.row.col.f32.f16.f16.f32 "
        "{%0,%1,%2,%3}, {%4,%5,%6,%7}, {%8,%9}, {%0,%1,%2,%3};"
        : "+f"(c[0]), "+f"(c[1]), "+f"(c[2]), "+f"(c[3])
        : "r"(a0), "r"(a1), "r"(a2), "r"(a3), "r"(b0), "r"(b1));
}
__device__ __forceinline__ float fast_rcp(float x) {
    float r; asm("rcp.approx.f32 %0, %1;" : "=f"(r) : "f"(x)); return r;
}
__device__ __forceinline__ float fast_ex2(float x) {
    float r; asm("ex2.approx.f32 %0, %1;" : "=f"(r) : "f"(x)); return r;
}
// Branchless gelu(x)+eps (Abramowitz-Stegun 7.1.26, abs err ~1.5e-7)
__device__ __forceinline__ float gelu_eps(float x) {
    float ax = fabsf(x);
    float t  = ax * 0.70710678118654752f;
    float k  = fast_rcp(fmaf(0.3275911f, t, 1.0f));
    float p  = fmaf(1.061405429f, k, -1.453152027f);
    p = fmaf(p, k, 1.421413741f);
    p = fmaf(p, k, -0.284496736f);
    p = fmaf(p, k, 0.254829592f);
    p = p * k;
    float e  = fast_ex2(-1.4426950408889634f * t * t);
    float h  = 0.5f * ax;
    float base = fmaf(0.5f, x, h) + 1e-6f;
    return fmaf(-h, p * e, base);
}

// ---------------- ph1 smem (u32 indices) ----------------
// Kf: 32 slots x 128 | Vf: 72 slots x 64.  Pstage (8192 u32) aliases both.
#define H1_KF 0
#define H1_VF 4096
#define H1_TOT 8704           // 34816 bytes

// ---------------- ph2 smem (u32 indices) ----------------
#define H2_QF 0               // 4096: A-frags of Q tile
#define H2_PS 4096            // 8192: B-frags of P
#define H2_CS 12288           // 9216: B-frags of ctx
#define H2_RS 21504           // 9216: fh-pair reduction buffer (floats)
#define H2_TOT 30720          // 122880 bytes

// =====================================================================
// Phase 1 (fp16 + movmatrix, 16 warps): warp owns m-block [16w, 16w+16).
// G1: kp = gelu(K_chunk @ P_blk^T) -> regs -> movmatrix -> MMA2 A
// MMA2: ctx += kp^T @ [V | 1 | 0].  No smem round-trip for kp.
// =====================================================================
__global__ __launch_bounds__(512, 1) void ph1_kernel(
    const float* __restrict__ Kg, const float* __restrict__ Vg,
    const float* __restrict__ Pg)
{
    extern __shared__ __align__(16) uint32_t su[];
    uint32_t* Kf = su + H1_KF;
    uint32_t* Vf = su + H1_VF;
    uint32_t* Pstage = su;            // aliased; dead after Pf reg load
    __half* Vfh = reinterpret_cast<__half*>(Vf);

    const int tid = threadIdx.x;
    const int w = tid >> 5, l = tid & 31;
    const int g = l >> 2, tg = l & 3;
    const int bh = blockIdx.y, sp = blockIdx.x;

    // ---- stage P [256 m][64 d] as B-frags (slot = (m>>3)*4 + k16) ----
    {
        const float4* P4 = reinterpret_cast<const float4*>(Pg);
        for (int i = tid; i < 4096; i += 512) {
            int m = i >> 4, d4 = i & 15;
            float4 x = P4[i];
            int slot = (m >> 3) * 4 + (d4 >> 2);
            int kk0 = (d4 & 3) * 4;
            int lane = (m & 7) * 4 + ((kk0 & 7) >> 1);
            int reg = kk0 >> 3;
            Pstage[slot * 64 + lane * 2 + reg] = pack_h2(x.x, x.y);
            Pstage[slot * 64 + (lane + 1) * 2 + reg] = pack_h2(x.z, x.w);
        }
    }
    __syncthreads();

    // ---- P fragments for this warp's 16-row m-block -> registers ----
    uint32_t Pf[4][2][2];
    #pragma unroll
    for (int k16 = 0; k16 < 4; k16++)
        #pragma unroll
        for (int j = 0; j < 2; j++) {
            int slot = (2 * w + j) * 4 + k16;
            uint2 b = *reinterpret_cast<const uint2*>(&Pstage[slot * 64 + l * 2]);
            Pf[k16][j][0] = b.x;
            Pf[k16][j][1] = b.y;
        }
    __syncthreads();   // Pstage dead; region reusable as Kf/Vf

    // ---- prefill Vf ksum slots (j=8): col e=64 -> 1.0, e=65..71 -> 0 ----
    for (int i = tid; i < 512; i += 512) {
        int s = i >> 6, pos = i & 63;
        int c = s >> 1, kp = s & 1;
        Vf[((c * 2 + kp) * 9 + 8) * 64 + pos] = (pos < 8) ? 0x3C003C00u : 0u;
    }

    // ---- persistent ctx accumulators (16 m-rows) ----
    float ctx[9][4];
    #pragma unroll
    for (int j = 0; j < 9; j++)
        #pragma unroll
        for (int q = 0; q < 4; q++) ctx[j][q] = 0.0f;

    const float4* Kb = reinterpret_cast<const float4*>(
        Kg + ((size_t)bh * NN + (size_t)sp * NCHUNK) * DD);
    const float4* Vb = reinterpret_cast<const float4*>(
        Vg + ((size_t)bh * NN + (size_t)sp * NCHUNK) * DD);

    for (int t = 0; t < 4; t++) {
        // ---- stage K tile as A-frags, V tile as B-frags ----
        for (int i = tid; i < 2048; i += 512) {
            int n = i >> 4, d4 = i & 15;
            {   // K
                float4 x = Kb[t * 2048 + i];
                int c = n >> 5, tf = (n >> 4) & 1, r = n & 15;
                int slot = (c * 4 + (d4 >> 2)) * 2 + tf;
                int kk0 = (d4 & 3) * 4;
                int lane = (r & 7) * 4 + ((kk0 & 7) >> 1);
                int reg = (r >> 3) + 2 * (kk0 >> 3);
                Kf[slot * 128 + lane * 4 + reg] = pack_h2(x.x, x.y);
                Kf[slot * 128 + (lane + 1) * 4 + reg] = pack_h2(x.z, x.w);
            }
            {   // V
                float4 x = Vb[t * 2048 + i];
                int c = n >> 5, kp = (n >> 4) & 1, kk = n & 15;
                int tgv = (kk & 7) >> 1, regv = kk >> 3, hv = kk & 1;
                float vv[4] = { x.x, x.y, x.z, x.w };
                #pragma unroll
                for (int e4 = 0; e4 < 4; e4++) {
                    int e = 4 * d4 + e4;
                    int j = e >> 3, gp = e & 7;
                    int u32i = ((c * 2 + kp) * 9 + j) * 64 + (gp * 4 + tgv) * 2 + regv;
                    Vfh[2 * u32i + hv] = __float2half_rn(vv[e4]);
                }
            }
        }
        __syncthreads();

        for (int c = 0; c < 4; c++) {
            // ---- G1: S[2 tf][2 j][4] = K_chunk @ P_blk^T ----
            float S[2][2][4];
            #pragma unroll
            for (int tf = 0; tf < 2; tf++)
                #pragma unroll
                for (int j = 0; j < 2; j++)
                    #pragma unroll
                    for (int q = 0; q < 4; q++) S[tf][j][q] = 0.0f;

            #pragma unroll
            for (int k16 = 0; k16 < 4; k16++) {
                #pragma unroll
                for (int tf = 0; tf < 2; tf++) {
                    uint4 av = *reinterpret_cast<const uint4*>(
                        &Kf[((c * 4 + k16) * 2 + tf) * 128 + l * 4]);
                    #pragma unroll
                    for (int j = 0; j < 2; j++)
                        mma16(S[tf][j], av.x, av.y, av.z, av.w,
                              Pf[k16][j][0], Pf[k16][j][1]);
                }
            }

            // ---- gelu + pack + in-register transpose (movmatrix) ----
            uint32_t Tlo[2][2], Thi[2][2];
            #pragma unroll
            for (int tf = 0; tf < 2; tf++)
                #pragma unroll
                for (int j = 0; j < 2; j++) {
                    uint32_t lo = pack_h2(gelu_eps(S[tf][j][0]), gelu_eps(S[tf][j][1]));
                    uint32_t hi = pack_h2(gelu_eps(S[tf][j][2]), gelu_eps(S[tf][j][3]));
                    Tlo[tf][j] = movm(lo);
                    Thi[tf][j] = movm(hi);
                }

            // ---- MMA2: ctx += kp^T @ [V|1|0]  (A straight from registers) ----
            #pragma unroll
            for (int kp = 0; kp < 2; kp++) {
                #pragma unroll
                for (int j = 0; j < 9; j++) {
                    uint2 b = *reinterpret_cast<const uint2*>(
                        &Vf[((c * 2 + kp) * 9 + j) * 64 + l * 2]);
                    mma16(ctx[j], Tlo[kp][0], Tlo[kp][1], Thi[kp][0], Thi[kp][1], b.x, b.y);
                }
            }
        }
        __syncthreads();   // before next tile's staging overwrites Kf/Vf
    }

    // ---- epilogue: write ctx partial [256][72] (f32) ----
    float* dst = g_ctxp + ((size_t)(bh * NSPLIT + sp)) * MM * CW;
    {
        int m = 16 * w + g;
        #pragma unroll
        for (int j = 0; j < 9; j++) {
            int col = j * 8 + 2 * tg;
            *reinterpret_cast<float2*>(&dst[(size_t)m * CW + col]) =
                make_float2(ctx[j][0], ctx[j][1]);
            *reinterpret_cast<float2*>(&dst[(size_t)(m + 8) * CW + col]) =
                make_float2(ctx[j][2], ctx[j][3]);
        }
    }
}

// =====================================================================
// Reduce: fixed-order sum of 8 split partials (256 blocks)
// =====================================================================
__global__ __launch_bounds__(256) void reduce_kernel()
{
    const int b = blockIdx.x;           // 0..255
    const int bh = b >> 2, q = b & 3;
    const float* src = g_ctxp + (size_t)bh * NSPLIT * MM * CW + q * 4608;
    float* dst = g_ctx + (size_t)bh * MM * CW + q * 4608;
    for (int i = threadIdx.x; i < 4608; i += 256) {
        float s = 0.0f;
        #pragma unroll
        for (int sp = 0; sp < NSPLIT; sp++) s += src[(size_t)sp * MM * CW + i];
        dst[i] = s;
    }
}

// =====================================================================
// Phase 2 (fp16, barrier-free chunk loop): warp (tf=w&7, fh=w>>3).
// Each warp accumulates FULL 72-col out with its own 32 features (k-split);
// qp goes straight from G3 accumulators into G4 A-frags (no smem, no sync).
// fh pairs merge partial outs once per tile.
// =====================================================================
__global__ __launch_bounds__(512, 1) void ph2_kernel(
    const float* __restrict__ Qg, const float* __restrict__ Pg,
    float* __restrict__ Og)
{
    extern __shared__ __align__(16) uint32_t su[];
    uint32_t* Qf  = su + H2_QF;
    uint32_t* Ps  = su + H2_PS;
    uint32_t* Cs  = su + H2_CS;
    float* Rs = reinterpret_cast<float*>(su + H2_RS);

    const int tid = threadIdx.x;
    const int w = tid >> 5, l = tid & 31;
    const int g = l >> 2, tg = l & 3;
    const int bh = blockIdx.y, sp = blockIdx.x;

    // ---- stage P as B-frags ----
    {
        const float4* P4 = reinterpret_cast<const float4*>(Pg);
        for (int i = tid; i < 4096; i += 512) {
            int m = i >> 4, d4 = i & 15;
            float4 x = P4[i];
            int slot = (m >> 3) * 4 + (d4 >> 2);
            int kk0 = (d4 & 3) * 4;
            int lane = (m & 7) * 4 + ((kk0 & 7) >> 1);
            int reg = kk0 >> 3;
            Ps[slot * 64 + lane * 2 + reg] = pack_h2(x.x, x.y);
            Ps[slot * 64 + (lane + 1) * 2 + reg] = pack_h2(x.z, x.w);
        }
    }
    // ---- stage ctx [256 f][72 e] as B-frags (pack f-pairs) ----
    {
        const float* Cg = g_ctx + (size_t)bh * MM * CW;
        for (int i = tid; i < 9216; i += 512) {
            int e = i % 72, fp = i / 72;
            int f = fp * 2;
            float lo = Cg[f * CW + e], hi = Cg[(f + 1) * CW + e];
            int c = f >> 6, kf = (f & 63) >> 4, kk = f & 15;   // kk even
            int j = e >> 3, gp = e & 7;
            int idx = ((c * 4 + kf) * 9 + j) * 64 + (gp * 4 + ((kk & 7) >> 1)) * 2 + (kk >> 3);
            Cs[idx] = pack_h2(lo, hi);
        }
    }
    __syncthreads();

    const int tf = w & 7;          // token group (16 rows)
    const int fh = w >> 3;         // feature half (k-split group)

    const float4* Qb = reinterpret_cast<const float4*>(
        Qg + ((size_t)bh * NN + (size_t)sp * NCHUNK) * DD);

    for (int t = 0; t < 4; t++) {
        if (t) __syncthreads();     // protect Qf/Rs reuse across tiles

        // ---- stage Q tile as A-frags ----
        for (int i = tid; i < 2048; i += 512) {
            int n = i >> 4, d4 = i & 15;
            float4 x = Qb[t * 2048 + i];
            int slot = (n >> 4) * 4 + (d4 >> 2);
            int kk0 = (d4 & 3) * 4;
            int r = n & 15;
            int lane = (r & 7) * 4 + ((kk0 & 7) >> 1);
            int reg = (r >> 3) + 2 * (kk0 >> 3);
            Qf[slot * 128 + lane * 4 + reg] = pack_h2(x.x, x.y);
            Qf[slot * 128 + (lane + 1) * 4 + reg] = pack_h2(x.z, x.w);
        }
        __syncthreads();

        float out[9][4];
        #pragma unroll
        for (int j = 0; j < 9; j++)
            #pragma unroll
            for (int q = 0; q < 4; q++) out[j][q] = 0.0f;

        for (int c = 0; c < 4; c++) {
            // ---- G3: S[4 j][4] = Q(tf rows) @ P^T (this warp's 32 feats) ----
            float S[4][4];
            #pragma unroll
            for (int j = 0; j < 4; j++)
                #pragma unroll
                for (int q = 0; q < 4; q++) S[j][q] = 0.0f;

            #pragma unroll
            for (int k16 = 0; k16 < 4; k16++) {
                uint4 av = *reinterpret_cast<const uint4*>(
                    &Qf[(tf * 4 + k16) * 128 + l * 4]);
                #pragma unroll
                for (int j = 0; j < 4; j++) {
                    int ngrp = c * 8 + fh * 4 + j;
                    uint2 b = *reinterpret_cast<const uint2*>(
                        &Ps[(ngrp * 4 + k16) * 64 + l * 2]);
                    mma16(S[j], av.x, av.y, av.z, av.w, b.x, b.y);
                }
            }

            // ---- gelu -> A-frags in registers; G4 over this warp's k16s ----
            #pragma unroll
            for (int kfl = 0; kfl < 2; kfl++) {
                int jlo = 2 * kfl, jhi = 2 * kfl + 1;
                uint32_t a0 = pack_h2(gelu_eps(S[jlo][0]), gelu_eps(S[jlo][1]));
                uint32_t a1 = pack_h2(gelu_eps(S[jlo][2]), gelu_eps(S[jlo][3]));
                uint32_t a2 = pack_h2(gelu_eps(S[jhi][0]), gelu_eps(S[jhi][1]));
                uint32_t a3 = pack_h2(gelu_eps(S[jhi][2]), gelu_eps(S[jhi][3]));
                int kf = fh * 2 + kfl;
                #pragma unroll
                for (int j = 0; j < 9; j++) {
                    uint2 b = *reinterpret_cast<const uint2*>(
                        &Cs[((c * 4 + kf) * 9 + j) * 64 + l * 2]);
                    mma16(out[j], a0, a1, a2, a3, b.x, b.y);
                }
            }
        }

        // ---- merge fh pair: fh=1 stores partials, fh=0 adds + epilogue ----
        if (fh == 1) {
            #pragma unroll
            for (int j = 0; j < 9; j++)
                *reinterpret_cast<float4*>(&Rs[((j * 8 + tf) * 32 + l) * 4]) =
                    make_float4(out[j][0], out[j][1], out[j][2], out[j][3]);
        }
        __syncthreads();
        if (fh == 0) {
            #pragma unroll
            for (int j = 0; j < 9; j++) {
                float4 r = *reinterpret_cast<const float4*>(&Rs[((j * 8 + tf) * 32 + l) * 4]);
                out[j][0] += r.x; out[j][1] += r.y; out[j][2] += r.z; out[j][3] += r.w;
            }
            // denominator (col 64 = j 8, elems 0/2 at tg==0) -> broadcast
            float d0 = __shfl_sync(0xffffffffu, out[8][0], l & ~3);
            float d1 = __shfl_sync(0xffffffffu, out[8][2], l & ~3);
            float di0 = 1.0f / d0, di1 = 1.0f / d1;
            float* dst = Og + ((size_t)bh * NN + (size_t)sp * NCHUNK
                               + (size_t)t * 128 + tf * 16 + g) * DD;
            #pragma unroll
            for (int j = 0; j < 8; j++) {
                int col = j * 8 + 2 * tg;
                *reinterpret_cast<float2*>(&dst[col]) =
                    make_float2(out[j][0] * di0, out[j][1] * di0);
                *reinterpret_cast<float2*>(&dst[(size_t)8 * DD + col]) =
                    make_float2(out[j][2] * di1, out[j][3] * di1);
            }
        }
    }
}

// =====================================================================
// launch
// =====================================================================
extern "C" void kernel_launch(void* const* d_in, const int* in_sizes, int n_in,
                              void* d_out, int out_size)
{
    const float* q    = (const float*)d_in[0];
    const float* k    = (const float*)d_in[1];
    const float* v    = (const float*)d_in[2];
    const float* proj = (const float*)d_in[3];
    float* out = (float*)d_out;

    cudaFuncSetAttribute(ph1_kernel, cudaFuncAttributeMaxDynamicSharedMemorySize, H1_TOT * 4);
    cudaFuncSetAttribute(ph2_kernel, cudaFuncAttributeMaxDynamicSharedMemorySize, H2_TOT * 4);

    ph1_kernel<<<dim3(NSPLIT, BH), 512, H1_TOT * 4>>>(k, v, proj);
    reduce_kernel<<<BH * 4, 256>>>();
    ph2_kernel<<<dim3(NSPLIT, BH), 512, H2_TOT * 4>>>(q, proj, out);
}

// round 15
// speedup vs baseline: 7.2317x; 1.1055x over previous
#include <cuda_runtime.h>
#include <cuda_fp16.h>
#include <cstdint>
#include <math.h>

// ---------------- problem constants ----------------
#define NN 4096
#define DD 64
#define MM 256
#define BH 64
#define NSPLIT 8
#define NCHUNK 512        // tokens per (sp) split
#define CW 72             // ctx width: 64 e-cols + ksum col + 7 pad (9 n8-frags)

// ---------------- scratch (no allocs allowed) ----------------
__device__ float g_ctxp[(size_t)BH * NSPLIT * MM * CW];   // partials
__device__ float g_ctx [(size_t)BH * MM * CW];            // reduced

// ---------------- helpers ----------------
__device__ __forceinline__ uint32_t pack_h2(float lo, float hi) {
    uint32_t r; asm("cvt.rn.f16x2.f32 %0, %2, %1;" : "=r"(r) : "f"(lo), "f"(hi));
    return r;
}
__device__ __forceinline__ uint32_t movm(uint32_t x) {
    uint32_t d;
    asm volatile("movmatrix.sync.aligned.m8n8.trans.b16 %0, %1;" : "=r"(d) : "r"(x));
    return d;
}
__device__ __forceinline__ void mma16(float c[4],
    uint32_t a0, uint32_t a1, uint32_t a2, uint32_t a3,
    uint32_t b0, uint32_t b1)
{
    asm volatile("mma.sync.aligned.m16n8k16.row.col.f32.f16.f16.f32 "
        "{%0,%1,%2,%3}, {%4,%5,%6,%7}, {%8,%9}, {%0,%1,%2,%3};"
        : "+f"(c[0]), "+f"(c[1]), "+f"(c[2]), "+f"(c[3])
        : "r"(a0), "r"(a1), "r"(a2), "r"(a3), "r"(b0), "r"(b1));
}
__device__ __forceinline__ float fast_rcp(float x) {
    float r; asm("rcp.approx.f32 %0, %1;" : "=f"(r) : "f"(x)); return r;
}
__device__ __forceinline__ float fast_ex2(float x) {
    float r; asm("ex2.approx.f32 %0, %1;" : "=f"(r) : "f"(x)); return r;
}
// Branchless gelu(x)+eps (Abramowitz-Stegun 7.1.26, abs err ~1.5e-7)
__device__ __forceinline__ float gelu_eps(float x) {
    float ax = fabsf(x);
    float t  = ax * 0.70710678118654752f;
    float k  = fast_rcp(fmaf(0.3275911f, t, 1.0f));
    float p  = fmaf(1.061405429f, k, -1.453152027f);
    p = fmaf(p, k, 1.421413741f);
    p = fmaf(p, k, -0.284496736f);
    p = fmaf(p, k, 0.254829592f);
    p = p * k;
    float e  = fast_ex2(-1.4426950408889634f * t * t);
    float h  = 0.5f * ax;
    float base = fmaf(0.5f, x, h) + 1e-6f;
    return fmaf(-h, p * e, base);
}

// ---------------- ph1 smem (u32 indices) ----------------
// Kf: 32 slots x 128 | Vf: 72 slots x 64.  Pstage (4096 u32) aliases Kf.
#define H1_KF 0
#define H1_VF 4096
#define H1_TOT 8704           // 34816 bytes

// ---------------- ph2 smem (u32 indices) ----------------
#define H2_QF 0               // 2048: A-frags of Q tile (64 tokens)
#define H2_PS 2048            // 8192: B-frags of P
#define H2_CS 10240           // 9216: B-frags of ctx
#define H2_RS 19456           // 4608: fh-pair reduction buffer (floats)
#define H2_TOT 24064          // 96256 bytes

// =====================================================================
// Phase 1 (fp16 + movmatrix, 256 thr, 2 CTAs/SM): CTA owns m-half mh;
// warp owns m-block [128*mh + 16w, +16).
// =====================================================================
__global__ __launch_bounds__(256, 2) void ph1_kernel(
    const float* __restrict__ Kg, const float* __restrict__ Vg,
    const float* __restrict__ Pg)
{
    extern __shared__ __align__(16) uint32_t su[];
    uint32_t* Kf = su + H1_KF;
    uint32_t* Vf = su + H1_VF;
    uint32_t* Pstage = su;            // aliases Kf; dead after Pf reg load
    __half* Vfh = reinterpret_cast<__half*>(Vf);

    const int tid = threadIdx.x;
    const int w = tid >> 5, l = tid & 31;
    const int g = l >> 2, tg = l & 3;
    const int bh = blockIdx.y, sp = blockIdx.x, mh = blockIdx.z;

    // ---- stage this CTA's P half [128 m][64 d] as B-frags ----
    {
        const float4* P4 = reinterpret_cast<const float4*>(Pg) + mh * 2048;
        for (int i = tid; i < 2048; i += 256) {
            int mloc = i >> 4, d4 = i & 15;
            float4 x = P4[i];
            int slot = (mloc >> 3) * 4 + (d4 >> 2);
            int kk0 = (d4 & 3) * 4;
            int lane = (mloc & 7) * 4 + ((kk0 & 7) >> 1);
            int reg = kk0 >> 3;
            Pstage[slot * 64 + lane * 2 + reg] = pack_h2(x.x, x.y);
            Pstage[slot * 64 + (lane + 1) * 2 + reg] = pack_h2(x.z, x.w);
        }
    }
    __syncthreads();

    // ---- P fragments for this warp's 16-row m-block -> registers ----
    uint32_t Pf[4][2][2];
    #pragma unroll
    for (int k16 = 0; k16 < 4; k16++)
        #pragma unroll
        for (int j = 0; j < 2; j++) {
            int slot = (2 * w + j) * 4 + k16;
            uint2 b = *reinterpret_cast<const uint2*>(&Pstage[slot * 64 + l * 2]);
            Pf[k16][j][0] = b.x;
            Pf[k16][j][1] = b.y;
        }
    __syncthreads();   // Pstage dead; region reusable as Kf

    // ---- prefill Vf ksum slots (j=8): col e=64 -> 1.0, e=65..71 -> 0 ----
    for (int i = tid; i < 512; i += 256) {
        int s = i >> 6, pos = i & 63;
        int c = s >> 1, kp = s & 1;
        Vf[((c * 2 + kp) * 9 + 8) * 64 + pos] = (pos < 8) ? 0x3C003C00u : 0u;
    }

    // ---- persistent ctx accumulators (16 m-rows) ----
    float ctx[9][4];
    #pragma unroll
    for (int j = 0; j < 9; j++)
        #pragma unroll
        for (int q = 0; q < 4; q++) ctx[j][q] = 0.0f;

    const float4* Kb = reinterpret_cast<const float4*>(
        Kg + ((size_t)bh * NN + (size_t)sp * NCHUNK) * DD);
    const float4* Vb = reinterpret_cast<const float4*>(
        Vg + ((size_t)bh * NN + (size_t)sp * NCHUNK) * DD);

    for (int t = 0; t < 4; t++) {
        // ---- stage K tile as A-frags, V tile as B-frags ----
        for (int i = tid; i < 2048; i += 256) {
            int n = i >> 4, d4 = i & 15;
            {   // K
                float4 x = Kb[t * 2048 + i];
                int c = n >> 5, tf = (n >> 4) & 1, r = n & 15;
                int slot = (c * 4 + (d4 >> 2)) * 2 + tf;
                int kk0 = (d4 & 3) * 4;
                int lane = (r & 7) * 4 + ((kk0 & 7) >> 1);
                int reg = (r >> 3) + 2 * (kk0 >> 3);
                Kf[slot * 128 + lane * 4 + reg] = pack_h2(x.x, x.y);
                Kf[slot * 128 + (lane + 1) * 4 + reg] = pack_h2(x.z, x.w);
            }
            {   // V
                float4 x = Vb[t * 2048 + i];
                int c = n >> 5, kp = (n >> 4) & 1, kk = n & 15;
                int tgv = (kk & 7) >> 1, regv = kk >> 3, hv = kk & 1;
                float vv[4] = { x.x, x.y, x.z, x.w };
                #pragma unroll
                for (int e4 = 0; e4 < 4; e4++) {
                    int e = 4 * d4 + e4;
                    int j = e >> 3, gp = e & 7;
                    int u32i = ((c * 2 + kp) * 9 + j) * 64 + (gp * 4 + tgv) * 2 + regv;
                    Vfh[2 * u32i + hv] = __float2half_rn(vv[e4]);
                }
            }
        }
        __syncthreads();

        for (int c = 0; c < 4; c++) {
            // ---- G1: S[2 tf][2 j][4] = K_chunk @ P_blk^T ----
            float S[2][2][4];
            #pragma unroll
            for (int tf = 0; tf < 2; tf++)
                #pragma unroll
                for (int j = 0; j < 2; j++)
                    #pragma unroll
                    for (int q = 0; q < 4; q++) S[tf][j][q] = 0.0f;

            #pragma unroll
            for (int k16 = 0; k16 < 4; k16++) {
                #pragma unroll
                for (int tf = 0; tf < 2; tf++) {
                    uint4 av = *reinterpret_cast<const uint4*>(
                        &Kf[((c * 4 + k16) * 2 + tf) * 128 + l * 4]);
                    #pragma unroll
                    for (int j = 0; j < 2; j++)
                        mma16(S[tf][j], av.x, av.y, av.z, av.w,
                              Pf[k16][j][0], Pf[k16][j][1]);
                }
            }

            // ---- gelu + pack + in-register transpose (movmatrix) ----
            uint32_t Tlo[2][2], Thi[2][2];
            #pragma unroll
            for (int tf = 0; tf < 2; tf++)
                #pragma unroll
                for (int j = 0; j < 2; j++) {
                    uint32_t lo = pack_h2(gelu_eps(S[tf][j][0]), gelu_eps(S[tf][j][1]));
                    uint32_t hi = pack_h2(gelu_eps(S[tf][j][2]), gelu_eps(S[tf][j][3]));
                    Tlo[tf][j] = movm(lo);
                    Thi[tf][j] = movm(hi);
                }

            // ---- MMA2: ctx += kp^T @ [V|1|0] ----
            #pragma unroll
            for (int kp = 0; kp < 2; kp++) {
                #pragma unroll
                for (int j = 0; j < 9; j++) {
                    uint2 b = *reinterpret_cast<const uint2*>(
                        &Vf[((c * 2 + kp) * 9 + j) * 64 + l * 2]);
                    mma16(ctx[j], Tlo[kp][0], Tlo[kp][1], Thi[kp][0], Thi[kp][1], b.x, b.y);
                }
            }
        }
        __syncthreads();   // before next tile's staging overwrites Kf/Vf
    }

    // ---- epilogue: write ctx partial rows [128mh+16w .. +16) ----
    float* dst = g_ctxp + ((size_t)(bh * NSPLIT + sp)) * MM * CW;
    {
        int m = mh * 128 + 16 * w + g;
        #pragma unroll
        for (int j = 0; j < 9; j++) {
            int col = j * 8 + 2 * tg;
            *reinterpret_cast<float2*>(&dst[(size_t)m * CW + col]) =
                make_float2(ctx[j][0], ctx[j][1]);
            *reinterpret_cast<float2*>(&dst[(size_t)(m + 8) * CW + col]) =
                make_float2(ctx[j][2], ctx[j][3]);
        }
    }
}

// =====================================================================
// Reduce: fixed-order sum of 8 split partials (256 blocks)
// =====================================================================
__global__ __launch_bounds__(256) void reduce_kernel()
{
    const int b = blockIdx.x;           // 0..255
    const int bh = b >> 2, q = b & 3;
    const float* src = g_ctxp + (size_t)bh * NSPLIT * MM * CW + q * 4608;
    float* dst = g_ctx + (size_t)bh * MM * CW + q * 4608;
    for (int i = threadIdx.x; i < 4608; i += 256) {
        float s = 0.0f;
        #pragma unroll
        for (int sp = 0; sp < NSPLIT; sp++) s += src[(size_t)sp * MM * CW + i];
        dst[i] = s;
    }
}

// =====================================================================
// Phase 2 (fp16, 256 thr, 2 CTAs/SM): CTA owns token-half th (256 tokens,
// 4 tiles x 64). Warp (tf=w&3 token group, fh=w>>2 feature half, k-split).
// qp never touches smem; chunk loop barrier-free.
// =====================================================================
__global__ __launch_bounds__(256, 2) void ph2_kernel(
    const float* __restrict__ Qg, const float* __restrict__ Pg,
    float* __restrict__ Og)
{
    extern __shared__ __align__(16) uint32_t su[];
    uint32_t* Qf  = su + H2_QF;
    uint32_t* Ps  = su + H2_PS;
    uint32_t* Cs  = su + H2_CS;
    float* Rs = reinterpret_cast<float*>(su + H2_RS);

    const int tid = threadIdx.x;
    const int w = tid >> 5, l = tid & 31;
    const int g = l >> 2, tg = l & 3;
    const int bh = blockIdx.y, sp = blockIdx.x, th = blockIdx.z;

    // ---- stage P as B-frags ----
    {
        const float4* P4 = reinterpret_cast<const float4*>(Pg);
        for (int i = tid; i < 4096; i += 256) {
            int m = i >> 4, d4 = i & 15;
            float4 x = P4[i];
            int slot = (m >> 3) * 4 + (d4 >> 2);
            int kk0 = (d4 & 3) * 4;
            int lane = (m & 7) * 4 + ((kk0 & 7) >> 1);
            int reg = kk0 >> 3;
            Ps[slot * 64 + lane * 2 + reg] = pack_h2(x.x, x.y);
            Ps[slot * 64 + (lane + 1) * 2 + reg] = pack_h2(x.z, x.w);
        }
    }
    // ---- stage ctx [256 f][72 e] as B-frags (pack f-pairs) ----
    {
        const float* Cg = g_ctx + (size_t)bh * MM * CW;
        for (int i = tid; i < 9216; i += 256) {
            int e = i % 72, fp = i / 72;
            int f = fp * 2;
            float lo = Cg[f * CW + e], hi = Cg[(f + 1) * CW + e];
            int c = f >> 6, kf = (f & 63) >> 4, kk = f & 15;   // kk even
            int j = e >> 3, gp = e & 7;
            int idx = ((c * 4 + kf) * 9 + j) * 64 + (gp * 4 + ((kk & 7) >> 1)) * 2 + (kk >> 3);
            Cs[idx] = pack_h2(lo, hi);
        }
    }
    __syncthreads();

    const int tf = w & 3;          // token group (16 rows in 64-token tile)
    const int fh = w >> 2;         // feature half (k-split group)

    const float4* Qb = reinterpret_cast<const float4*>(
        Qg + ((size_t)bh * NN + (size_t)sp * NCHUNK + (size_t)th * 256) * DD);

    for (int t = 0; t < 4; t++) {
        if (t) __syncthreads();     // protect Qf/Rs reuse across tiles

        // ---- stage Q tile (64 tokens) as A-frags ----
        for (int i = tid; i < 1024; i += 256) {
            int n = i >> 4, d4 = i & 15;
            float4 x = Qb[t * 1024 + i];
            int slot = (n >> 4) * 4 + (d4 >> 2);
            int kk0 = (d4 & 3) * 4;
            int r = n & 15;
            int lane = (r & 7) * 4 + ((kk0 & 7) >> 1);
            int reg = (r >> 3) + 2 * (kk0 >> 3);
            Qf[slot * 128 + lane * 4 + reg] = pack_h2(x.x, x.y);
            Qf[slot * 128 + (lane + 1) * 4 + reg] = pack_h2(x.z, x.w);
        }
        __syncthreads();

        float out[9][4];
        #pragma unroll
        for (int j = 0; j < 9; j++)
            #pragma unroll
            for (int q = 0; q < 4; q++) out[j][q] = 0.0f;

        for (int c = 0; c < 4; c++) {
            // ---- G3: S[4 j][4] = Q(tf rows) @ P^T (this warp's 32 feats) ----
            float S[4][4];
            #pragma unroll
            for (int j = 0; j < 4; j++)
                #pragma unroll
                for (int q = 0; q < 4; q++) S[j][q] = 0.0f;

            #pragma unroll
            for (int k16 = 0; k16 < 4; k16++) {
                uint4 av = *reinterpret_cast<const uint4*>(
                    &Qf[(tf * 4 + k16) * 128 + l * 4]);
                #pragma unroll
                for (int j = 0; j < 4; j++) {
                    int ngrp = c * 8 + fh * 4 + j;
                    uint2 b = *reinterpret_cast<const uint2*>(
                        &Ps[(ngrp * 4 + k16) * 64 + l * 2]);
                    mma16(S[j], av.x, av.y, av.z, av.w, b.x, b.y);
                }
            }

            // ---- gelu -> A-frags in registers; G4 over this warp's k16s ----
            #pragma unroll
            for (int kfl = 0; kfl < 2; kfl++) {
                int jlo = 2 * kfl, jhi = 2 * kfl + 1;
                uint32_t a0 = pack_h2(gelu_eps(S[jlo][0]), gelu_eps(S[jlo][1]));
                uint32_t a1 = pack_h2(gelu_eps(S[jlo][2]), gelu_eps(S[jlo][3]));
                uint32_t a2 = pack_h2(gelu_eps(S[jhi][0]), gelu_eps(S[jhi][1]));
                uint32_t a3 = pack_h2(gelu_eps(S[jhi][2]), gelu_eps(S[jhi][3]));
                int kf = fh * 2 + kfl;
                #pragma unroll
                for (int j = 0; j < 9; j++) {
                    uint2 b = *reinterpret_cast<const uint2*>(
                        &Cs[((c * 4 + kf) * 9 + j) * 64 + l * 2]);
                    mma16(out[j], a0, a1, a2, a3, b.x, b.y);
                }
            }
        }

        // ---- merge fh pair: fh=1 stores partials, fh=0 adds + epilogue ----
        if (fh == 1) {
            #pragma unroll
            for (int j = 0; j < 9; j++)
                *reinterpret_cast<float4*>(&Rs[((j * 4 + tf) * 32 + l) * 4]) =
                    make_float4(out[j][0], out[j][1], out[j][2], out[j][3]);
        }
        __syncthreads();
        if (fh == 0) {
            #pragma unroll
            for (int j = 0; j < 9; j++) {
                float4 r = *reinterpret_cast<const float4*>(&Rs[((j * 4 + tf) * 32 + l) * 4]);
                out[j][0] += r.x; out[j][1] += r.y; out[j][2] += r.z; out[j][3] += r.w;
            }
            // denominator (col 64 = j 8, elems 0/2 at tg==0) -> broadcast
            float d0 = __shfl_sync(0xffffffffu, out[8][0], l & ~3);
            float d1 = __shfl_sync(0xffffffffu, out[8][2], l & ~3);
            float di0 = 1.0f / d0, di1 = 1.0f / d1;
            float* dst = Og + ((size_t)bh * NN + (size_t)sp * NCHUNK
                               + (size_t)th * 256 + (size_t)t * 64 + tf * 16 + g) * DD;
            #pragma unroll
            for (int j = 0; j < 8; j++) {
                int col = j * 8 + 2 * tg;
                *reinterpret_cast<float2*>(&dst[col]) =
                    make_float2(out[j][0] * di0, out[j][1] * di0);
                *reinterpret_cast<float2*>(&dst[(size_t)8 * DD + col]) =
                    make_float2(out[j][2] * di1, out[j][3] * di1);
            }
        }
    }
}

// =====================================================================
// launch
// =====================================================================
extern "C" void kernel_launch(void* const* d_in, const int* in_sizes, int n_in,
                              void* d_out, int out_size)
{
    const float* q    = (const float*)d_in[0];
    const float* k    = (const float*)d_in[1];
    const float* v    = (const float*)d_in[2];
    const float* proj = (const float*)d_in[3];
    float* out = (float*)d_out;

    cudaFuncSetAttribute(ph1_kernel, cudaFuncAttributeMaxDynamicSharedMemorySize, H1_TOT * 4);
    cudaFuncSetAttribute(ph2_kernel, cudaFuncAttributeMaxDynamicSharedMemorySize, H2_TOT * 4);

    ph1_kernel<<<dim3(NSPLIT, BH, 2), 256, H1_TOT * 4>>>(k, v, proj);
    reduce_kernel<<<BH * 4, 256>>>();
    ph2_kernel<<<dim3(NSPLIT, BH, 2), 256, H2_TOT * 4>>>(q, proj, out);
}

// round 16
// speedup vs baseline: 9.3325x; 1.2905x over previous
#include <cuda_runtime.h>
#include <cuda_fp16.h>
#include <cstdint>
#include <math.h>

// ---------------- problem constants ----------------
#define NN 4096
#define DD 64
#define MM 256
#define BH 64
#define NSPLIT 8
#define NCHUNK 512        // tokens per (sp) split
#define CW 72             // ctx width: 64 e-cols + ksum col + 7 pad (9 n8-frags)

// ---------------- scratch (no allocs allowed) ----------------
__device__ float g_ctxp[(size_t)BH * NSPLIT * MM * CW];   // partials
__device__ float g_ctx [(size_t)BH * MM * CW];            // reduced

// ---------------- helpers ----------------
__device__ __forceinline__ uint32_t pack_h2(float lo, float hi) {
    uint32_t r; asm("cvt.rn.f16x2.f32 %0, %2, %1;" : "=r"(r) : "f"(lo), "f"(hi));
    return r;
}
__device__ __forceinline__ uint32_t movm(uint32_t x) {
    uint32_t d;
    asm volatile("movmatrix.sync.aligned.m8n8.trans.b16 %0, %1;" : "=r"(d) : "r"(x));
    return d;
}
__device__ __forceinline__ void mma16(float c[4],
    uint32_t a0, uint32_t a1, uint32_t a2, uint32_t a3,
    uint32_t b0, uint32_t b1)
{
    asm volatile("mma.sync.aligned.m16n8k16.row.col.f32.f16.f16.f32 "
        "{%0,%1,%2,%3}, {%4,%5,%6,%7}, {%8,%9}, {%0,%1,%2,%3};"
        : "+f"(c[0]), "+f"(c[1]), "+f"(c[2]), "+f"(c[3])
        : "r"(a0), "r"(a1), "r"(a2), "r"(a3), "r"(b0), "r"(b1));
}
// ---- packed fp16x2 ops ----
__device__ __forceinline__ uint32_t h2fma(uint32_t a, uint32_t b, uint32_t c) {
    uint32_t d; asm("fma.rn.f16x2 %0, %1, %2, %3;" : "=r"(d) : "r"(a), "r"(b), "r"(c)); return d;
}
__device__ __forceinline__ uint32_t h2mul(uint32_t a, uint32_t b) {
    uint32_t d; asm("mul.f16x2 %0, %1, %2;" : "=r"(d) : "r"(a), "r"(b)); return d;
}
__device__ __forceinline__ uint32_t h2add(uint32_t a, uint32_t b) {
    uint32_t d; asm("add.f16x2 %0, %1, %2;" : "=r"(d) : "r"(a), "r"(b)); return d;
}
__device__ __forceinline__ uint32_t h2tanh(uint32_t a) {
    uint32_t d; asm("tanh.approx.f16x2 %0, %1;" : "=r"(d) : "r"(a)); return d;
}
// Packed gelu(x)+eps, tanh form: 0.5x(1+tanh(0.79788(x+0.044715x^3))) + eps
__device__ __forceinline__ uint32_t gelu_eps_h2(uint32_t x) {
    const uint32_t C0 = 0x3A623A62u;  // 0.797885 (fp16)
    const uint32_t C1 = 0x28912891u;  // 0.0356774 (= 0.797885*0.044715)
    const uint32_t H  = 0x38003800u;  // 0.5
    const uint32_t E  = 0x00110011u;  // ~1.013e-6 (fp16 subnormal)
    uint32_t xx  = h2mul(x, x);
    uint32_t a   = h2fma(xx, C1, C0);
    uint32_t arg = h2mul(x, a);
    uint32_t th  = h2tanh(arg);
    uint32_t hx  = h2mul(x, H);
    uint32_t r   = h2fma(hx, th, hx);
    return h2add(r, E);
}

// ---------------- ph1 smem (u32 indices) ----------------
// Kf: 32 slots x 128 | Vf: 72 slots x 66 (padded).  Pstage (4096) aliases Kf.
#define VSTR 66
#define H1_KF 0
#define H1_VF 4096
#define H1_TOT (4096 + 72 * VSTR)     // 8848 u32 = 35392 bytes

// ---------------- ph2 smem (u32 indices) ----------------
#define H2_QF 0               // 2048: A-frags of Q tile (64 tokens)
#define H2_PS 2048            // 8192: B-frags of P
#define H2_CS 10240           // 9216: B-frags of ctx
#define H2_RS 19456           // 4608: fh-pair reduction buffer (floats)
#define H2_TOT 24064          // 96256 bytes

// =====================================================================
// Phase 1 (fp16 + movmatrix, 256 thr, 2 CTAs/SM): CTA owns m-half mh;
// warp owns m-block [128*mh + 16w, +16).
// =====================================================================
__global__ __launch_bounds__(256, 2) void ph1_kernel(
    const float* __restrict__ Kg, const float* __restrict__ Vg,
    const float* __restrict__ Pg)
{
    extern __shared__ __align__(16) uint32_t su[];
    uint32_t* Kf = su + H1_KF;
    uint32_t* Vf = su + H1_VF;
    uint32_t* Pstage = su;            // aliases Kf; dead after Pf reg load

    const int tid = threadIdx.x;
    const int w = tid >> 5, l = tid & 31;
    const int g = l >> 2, tg = l & 3;
    const int bh = blockIdx.y, sp = blockIdx.x, mh = blockIdx.z;

    // ---- stage this CTA's P half [128 m][64 d] as B-frags ----
    {
        const float4* P4 = reinterpret_cast<const float4*>(Pg) + mh * 2048;
        for (int i = tid; i < 2048; i += 256) {
            int mloc = i >> 4, d4 = i & 15;
            float4 x = P4[i];
            int slot = (mloc >> 3) * 4 + (d4 >> 2);
            int kk0 = (d4 & 3) * 4;
            int lane = (mloc & 7) * 4 + ((kk0 & 7) >> 1);
            int reg = kk0 >> 3;
            Pstage[slot * 64 + lane * 2 + reg] = pack_h2(x.x, x.y);
            Pstage[slot * 64 + (lane + 1) * 2 + reg] = pack_h2(x.z, x.w);
        }
    }
    __syncthreads();

    // ---- P fragments for this warp's 16-row m-block -> registers ----
    uint32_t Pf[4][2][2];
    #pragma unroll
    for (int k16 = 0; k16 < 4; k16++)
        #pragma unroll
        for (int j = 0; j < 2; j++) {
            int slot = (2 * w + j) * 4 + k16;
            uint2 b = *reinterpret_cast<const uint2*>(&Pstage[slot * 64 + l * 2]);
            Pf[k16][j][0] = b.x;
            Pf[k16][j][1] = b.y;
        }
    __syncthreads();   // Pstage dead; region reusable as Kf

    // ---- prefill Vf ksum slots (j=8): col e=64 -> 1.0, e=65..71 -> 0 ----
    for (int i = tid; i < 512; i += 256) {
        int s = i >> 6, pos = i & 63;
        int c = s >> 1, kp = s & 1;
        Vf[((c * 2 + kp) * 9 + 8) * VSTR + pos] = (pos < 8) ? 0x3C003C00u : 0u;
    }

    // ---- persistent ctx accumulators (16 m-rows) ----
    float ctx[9][4];
    #pragma unroll
    for (int j = 0; j < 9; j++)
        #pragma unroll
        for (int q = 0; q < 4; q++) ctx[j][q] = 0.0f;

    const float4* Kb = reinterpret_cast<const float4*>(
        Kg + ((size_t)bh * NN + (size_t)sp * NCHUNK) * DD);
    const float4* Vb = reinterpret_cast<const float4*>(
        Vg + ((size_t)bh * NN + (size_t)sp * NCHUNK) * DD);

    for (int t = 0; t < 4; t++) {
        // ---- stage K tile as A-frags ----
        for (int i = tid; i < 2048; i += 256) {
            int n = i >> 4, d4 = i & 15;
            float4 x = Kb[t * 2048 + i];
            int c = n >> 5, tf = (n >> 4) & 1, r = n & 15;
            int slot = (c * 4 + (d4 >> 2)) * 2 + tf;
            int kk0 = (d4 & 3) * 4;
            int lane = (r & 7) * 4 + ((kk0 & 7) >> 1);
            int reg = (r >> 3) + 2 * (kk0 >> 3);
            Kf[slot * 128 + lane * 4 + reg] = pack_h2(x.x, x.y);
            Kf[slot * 128 + (lane + 1) * 4 + reg] = pack_h2(x.z, x.w);
        }
        // ---- stage V tile as B-frags (token-pair loads, whole-u32 stores) ----
        for (int i = tid; i < 1024; i += 256) {
            int p = i >> 4, d4 = i & 15;
            int c = p >> 4, kp = (p >> 3) & 1, kk2 = p & 7;   // token-pair idx
            int n0 = c * 32 + kp * 16 + kk2 * 2;
            float4 xa = Vb[t * 2048 + n0 * 16 + d4];
            float4 xb = Vb[t * 2048 + (n0 + 1) * 16 + d4];
            int tgv = kk2 & 3, regv = kk2 >> 2;
            float va[4] = { xa.x, xa.y, xa.z, xa.w };
            float vb2[4] = { xb.x, xb.y, xb.z, xb.w };
            #pragma unroll
            for (int e4 = 0; e4 < 4; e4++) {
                int e = 4 * d4 + e4;
                int j = e >> 3, gp = e & 7;
                Vf[((c * 2 + kp) * 9 + j) * VSTR + (gp * 4 + tgv) * 2 + regv] =
                    pack_h2(va[e4], vb2[e4]);
            }
        }
        __syncthreads();

        for (int c = 0; c < 4; c++) {
            // ---- G1: S[2 tf][2 j][4] = K_chunk @ P_blk^T ----
            float S[2][2][4];
            #pragma unroll
            for (int tf = 0; tf < 2; tf++)
                #pragma unroll
                for (int j = 0; j < 2; j++)
                    #pragma unroll
                    for (int q = 0; q < 4; q++) S[tf][j][q] = 0.0f;

            #pragma unroll
            for (int k16 = 0; k16 < 4; k16++) {
                #pragma unroll
                for (int tf = 0; tf < 2; tf++) {
                    uint4 av = *reinterpret_cast<const uint4*>(
                        &Kf[((c * 4 + k16) * 2 + tf) * 128 + l * 4]);
                    #pragma unroll
                    for (int j = 0; j < 2; j++)
                        mma16(S[tf][j], av.x, av.y, av.z, av.w,
                              Pf[k16][j][0], Pf[k16][j][1]);
                }
            }

            // ---- pack + packed gelu + in-register transpose ----
            uint32_t Tlo[2][2], Thi[2][2];
            #pragma unroll
            for (int tf = 0; tf < 2; tf++)
                #pragma unroll
                for (int j = 0; j < 2; j++) {
                    uint32_t lo = gelu_eps_h2(pack_h2(S[tf][j][0], S[tf][j][1]));
                    uint32_t hi = gelu_eps_h2(pack_h2(S[tf][j][2], S[tf][j][3]));
                    Tlo[tf][j] = movm(lo);
                    Thi[tf][j] = movm(hi);
                }

            // ---- MMA2: ctx += kp^T @ [V|1|0] ----
            #pragma unroll
            for (int kp = 0; kp < 2; kp++) {
                #pragma unroll
                for (int j = 0; j < 9; j++) {
                    uint2 b = *reinterpret_cast<const uint2*>(
                        &Vf[((c * 2 + kp) * 9 + j) * VSTR + l * 2]);
                    mma16(ctx[j], Tlo[kp][0], Tlo[kp][1], Thi[kp][0], Thi[kp][1], b.x, b.y);
                }
            }
        }
        __syncthreads();   // before next tile's staging overwrites Kf/Vf
    }

    // ---- epilogue: write ctx partial rows [128mh+16w .. +16) ----
    float* dst = g_ctxp + ((size_t)(bh * NSPLIT + sp)) * MM * CW;
    {
        int m = mh * 128 + 16 * w + g;
        #pragma unroll
        for (int j = 0; j < 9; j++) {
            int col = j * 8 + 2 * tg;
            *reinterpret_cast<float2*>(&dst[(size_t)m * CW + col]) =
                make_float2(ctx[j][0], ctx[j][1]);
            *reinterpret_cast<float2*>(&dst[(size_t)(m + 8) * CW + col]) =
                make_float2(ctx[j][2], ctx[j][3]);
        }
    }
}

// =====================================================================
// Reduce: fixed-order sum of 8 split partials (256 blocks)
// =====================================================================
__global__ __launch_bounds__(256) void reduce_kernel()
{
    const int b = blockIdx.x;           // 0..255
    const int bh = b >> 2, q = b & 3;
    const float* src = g_ctxp + (size_t)bh * NSPLIT * MM * CW + q * 4608;
    float* dst = g_ctx + (size_t)bh * MM * CW + q * 4608;
    for (int i = threadIdx.x; i < 4608; i += 256) {
        float s = 0.0f;
        #pragma unroll
        for (int sp = 0; sp < NSPLIT; sp++) s += src[(size_t)sp * MM * CW + i];
        dst[i] = s;
    }
}

// =====================================================================
// Phase 2 (fp16, 256 thr, 2 CTAs/SM): CTA owns token-half th (256 tokens,
// 4 tiles x 64). Warp (tf=w&3 token group, fh=w>>2 feature half, k-split).
// qp never touches smem; chunk loop barrier-free.
// =====================================================================
__global__ __launch_bounds__(256, 2) void ph2_kernel(
    const float* __restrict__ Qg, const float* __restrict__ Pg,
    float* __restrict__ Og)
{
    extern __shared__ __align__(16) uint32_t su[];
    uint32_t* Qf  = su + H2_QF;
    uint32_t* Ps  = su + H2_PS;
    uint32_t* Cs  = su + H2_CS;
    float* Rs = reinterpret_cast<float*>(su + H2_RS);

    const int tid = threadIdx.x;
    const int w = tid >> 5, l = tid & 31;
    const int g = l >> 2, tg = l & 3;
    const int bh = blockIdx.y, sp = blockIdx.x, th = blockIdx.z;

    // ---- stage P as B-frags ----
    {
        const float4* P4 = reinterpret_cast<const float4*>(Pg);
        for (int i = tid; i < 4096; i += 256) {
            int m = i >> 4, d4 = i & 15;
            float4 x = P4[i];
            int slot = (m >> 3) * 4 + (d4 >> 2);
            int kk0 = (d4 & 3) * 4;
            int lane = (m & 7) * 4 + ((kk0 & 7) >> 1);
            int reg = kk0 >> 3;
            Ps[slot * 64 + lane * 2 + reg] = pack_h2(x.x, x.y);
            Ps[slot * 64 + (lane + 1) * 2 + reg] = pack_h2(x.z, x.w);
        }
    }
    // ---- stage ctx [256 f][72 e] as B-frags (pack f-pairs) ----
    {
        const float* Cg = g_ctx + (size_t)bh * MM * CW;
        for (int i = tid; i < 9216; i += 256) {
            int e = i % 72, fp = i / 72;
            int f = fp * 2;
            float lo = Cg[f * CW + e], hi = Cg[(f + 1) * CW + e];
            int c = f >> 6, kf = (f & 63) >> 4, kk = f & 15;   // kk even
            int j = e >> 3, gp = e & 7;
            int idx = ((c * 4 + kf) * 9 + j) * 64 + (gp * 4 + ((kk & 7) >> 1)) * 2 + (kk >> 3);
            Cs[idx] = pack_h2(lo, hi);
        }
    }
    __syncthreads();

    const int tf = w & 3;          // token group (16 rows in 64-token tile)
    const int fh = w >> 2;         // feature half (k-split group)

    const float4* Qb = reinterpret_cast<const float4*>(
        Qg + ((size_t)bh * NN + (size_t)sp * NCHUNK + (size_t)th * 256) * DD);

    for (int t = 0; t < 4; t++) {
        if (t) __syncthreads();     // protect Qf/Rs reuse across tiles

        // ---- stage Q tile (64 tokens) as A-frags ----
        for (int i = tid; i < 1024; i += 256) {
            int n = i >> 4, d4 = i & 15;
            float4 x = Qb[t * 1024 + i];
            int slot = (n >> 4) * 4 + (d4 >> 2);
            int kk0 = (d4 & 3) * 4;
            int r = n & 15;
            int lane = (r & 7) * 4 + ((kk0 & 7) >> 1);
            int reg = (r >> 3) + 2 * (kk0 >> 3);
            Qf[slot * 128 + lane * 4 + reg] = pack_h2(x.x, x.y);
            Qf[slot * 128 + (lane + 1) * 4 + reg] = pack_h2(x.z, x.w);
        }
        __syncthreads();

        float out[9][4];
        #pragma unroll
        for (int j = 0; j < 9; j++)
            #pragma unroll
            for (int q = 0; q < 4; q++) out[j][q] = 0.0f;

        for (int c = 0; c < 4; c++) {
            // ---- G3: S[4 j][4] = Q(tf rows) @ P^T (this warp's 32 feats) ----
            float S[4][4];
            #pragma unroll
            for (int j = 0; j < 4; j++)
                #pragma unroll
                for (int q = 0; q < 4; q++) S[j][q] = 0.0f;

            #pragma unroll
            for (int k16 = 0; k16 < 4; k16++) {
                uint4 av = *reinterpret_cast<const uint4*>(
                    &Qf[(tf * 4 + k16) * 128 + l * 4]);
                #pragma unroll
                for (int j = 0; j < 4; j++) {
                    int ngrp = c * 8 + fh * 4 + j;
                    uint2 b = *reinterpret_cast<const uint2*>(
                        &Ps[(ngrp * 4 + k16) * 64 + l * 2]);
                    mma16(S[j], av.x, av.y, av.z, av.w, b.x, b.y);
                }
            }

            // ---- packed gelu -> A-frags in registers; G4 over warp's k16s ----
            #pragma unroll
            for (int kfl = 0; kfl < 2; kfl++) {
                int jlo = 2 * kfl, jhi = 2 * kfl + 1;
                uint32_t a0 = gelu_eps_h2(pack_h2(S[jlo][0], S[jlo][1]));
                uint32_t a1 = gelu_eps_h2(pack_h2(S[jlo][2], S[jlo][3]));
                uint32_t a2 = gelu_eps_h2(pack_h2(S[jhi][0], S[jhi][1]));
                uint32_t a3 = gelu_eps_h2(pack_h2(S[jhi][2], S[jhi][3]));
                int kf = fh * 2 + kfl;
                #pragma unroll
                for (int j = 0; j < 9; j++) {
                    uint2 b = *reinterpret_cast<const uint2*>(
                        &Cs[((c * 4 + kf) * 9 + j) * 64 + l * 2]);
                    mma16(out[j], a0, a1, a2, a3, b.x, b.y);
                }
            }
        }

        // ---- merge fh pair: fh=1 stores partials, fh=0 adds + epilogue ----
        if (fh == 1) {
            #pragma unroll
            for (int j = 0; j < 9; j++)
                *reinterpret_cast<float4*>(&Rs[((j * 4 + tf) * 32 + l) * 4]) =
                    make_float4(out[j][0], out[j][1], out[j][2], out[j][3]);
        }
        __syncthreads();
        if (fh == 0) {
            #pragma unroll
            for (int j = 0; j < 9; j++) {
                float4 r = *reinterpret_cast<const float4*>(&Rs[((j * 4 + tf) * 32 + l) * 4]);
                out[j][0] += r.x; out[j][1] += r.y; out[j][2] += r.z; out[j][3] += r.w;
            }
            // denominator (col 64 = j 8, elems 0/2 at tg==0) -> broadcast
            float d0 = __shfl_sync(0xffffffffu, out[8][0], l & ~3);
            float d1 = __shfl_sync(0xffffffffu, out[8][2], l & ~3);
            float di0 = 1.0f / d0, di1 = 1.0f / d1;
            float* dst = Og + ((size_t)bh * NN + (size_t)sp * NCHUNK
                               + (size_t)th * 256 + (size_t)t * 64 + tf * 16 + g) * DD;
            #pragma unroll
            for (int j = 0; j < 8; j++) {
                int col = j * 8 + 2 * tg;
                *reinterpret_cast<float2*>(&dst[col]) =
                    make_float2(out[j][0] * di0, out[j][1] * di0);
                *reinterpret_cast<float2*>(&dst[(size_t)8 * DD + col]) =
                    make_float2(out[j][2] * di1, out[j][3] * di1);
            }
        }
    }
}

// =====================================================================
// launch
// =====================================================================
extern "C" void kernel_launch(void* const* d_in, const int* in_sizes, int n_in,
                              void* d_out, int out_size)
{
    const float* q    = (const float*)d_in[0];
    const float* k    = (const float*)d_in[1];
    const float* v    = (const float*)d_in[2];
    const float* proj = (const float*)d_in[3];
    float* out = (float*)d_out;

    cudaFuncSetAttribute(ph1_kernel, cudaFuncAttributeMaxDynamicSharedMemorySize, H1_TOT * 4);
    cudaFuncSetAttribute(ph2_kernel, cudaFuncAttributeMaxDynamicSharedMemorySize, H2_TOT * 4);

    ph1_kernel<<<dim3(NSPLIT, BH, 2), 256, H1_TOT * 4>>>(k, v, proj);
    reduce_kernel<<<BH * 4, 256>>>();
    ph2_kernel<<<dim3(NSPLIT, BH, 2), 256, H2_TOT * 4>>>(q, proj, out);
}

// round 17
// speedup vs baseline: 12.0445x; 1.2906x over previous
#include <cuda_runtime.h>
#include <cuda_fp16.h>
#include <cstdint>
#include <math.h>

// ---------------- problem constants ----------------
#define NN 4096
#define DD 64
#define MM 256
#define BH 64
#define NSPLIT 8
#define NCHUNK 512        // tokens per (sp) split
#define CW 72             // ctx width: 64 e-cols + ksum col + 7 pad (9 n8-frags)

// ---------------- scratch (no allocs allowed) ----------------
__device__ float g_ctxp[(size_t)BH * NSPLIT * MM * CW];   // partials
__device__ float g_ctx [(size_t)BH * MM * CW];            // reduced

// ---------------- helpers ----------------
__device__ __forceinline__ uint32_t pack_h2(float lo, float hi) {
    uint32_t r; asm("cvt.rn.f16x2.f32 %0, %2, %1;" : "=r"(r) : "f"(lo), "f"(hi));
    return r;
}
__device__ __forceinline__ uint32_t movm(uint32_t x) {
    uint32_t d;
    asm volatile("movmatrix.sync.aligned.m8n8.trans.b16 %0, %1;" : "=r"(d) : "r"(x));
    return d;
}
__device__ __forceinline__ void mma16(float c[4],
    uint32_t a0, uint32_t a1, uint32_t a2, uint32_t a3,
    uint32_t b0, uint32_t b1)
{
    asm volatile("mma.sync.aligned.m16n8k16.row.col.f32.f16.f16.f32 "
        "{%0,%1,%2,%3}, {%4,%5,%6,%7}, {%8,%9}, {%0,%1,%2,%3};"
        : "+f"(c[0]), "+f"(c[1]), "+f"(c[2]), "+f"(c[3])
        : "r"(a0), "r"(a1), "r"(a2), "r"(a3), "r"(b0), "r"(b1));
}
// ---- packed fp16x2 ops ----
__device__ __forceinline__ uint32_t h2fma(uint32_t a, uint32_t b, uint32_t c) {
    uint32_t d; asm("fma.rn.f16x2 %0, %1, %2, %3;" : "=r"(d) : "r"(a), "r"(b), "r"(c)); return d;
}
__device__ __forceinline__ uint32_t h2mul(uint32_t a, uint32_t b) {
    uint32_t d; asm("mul.f16x2 %0, %1, %2;" : "=r"(d) : "r"(a), "r"(b)); return d;
}
__device__ __forceinline__ uint32_t h2add(uint32_t a, uint32_t b) {
    uint32_t d; asm("add.f16x2 %0, %1, %2;" : "=r"(d) : "r"(a), "r"(b)); return d;
}
__device__ __forceinline__ uint32_t h2tanh(uint32_t a) {
    uint32_t d; asm("tanh.approx.f16x2 %0, %1;" : "=r"(d) : "r"(a)); return d;
}
// Packed gelu(x)+eps, tanh form: 0.5x(1+tanh(0.79788(x+0.044715x^3))) + eps
__device__ __forceinline__ uint32_t gelu_eps_h2(uint32_t x) {
    const uint32_t C0 = 0x3A623A62u;  // 0.797885 (fp16)
    const uint32_t C1 = 0x28912891u;  // 0.0356774 (= 0.797885*0.044715)
    const uint32_t H  = 0x38003800u;  // 0.5
    const uint32_t E  = 0x00110011u;  // ~1.013e-6 (fp16 subnormal)
    uint32_t xx  = h2mul(x, x);
    uint32_t a   = h2fma(xx, C1, C0);
    uint32_t arg = h2mul(x, a);
    uint32_t th  = h2tanh(arg);
    uint32_t hx  = h2mul(x, H);
    uint32_t r   = h2fma(hx, th, hx);
    return h2add(r, E);
}
// ---- cp.async ----
__device__ __forceinline__ void cp_async16(uint32_t saddr, const void* gptr) {
    asm volatile("cp.async.cg.shared.global [%0], [%1], 16;" :: "r"(saddr), "l"(gptr) : "memory");
}
#define CP_COMMIT() asm volatile("cp.async.commit_group;" ::: "memory")
#define CP_WAIT0()  asm volatile("cp.async.wait_group 0;" ::: "memory")

// ---------------- ph1 smem (u32 indices) ----------------
// RawK 8192 | RawV 8192 | Kf 4096 (aliased by Pstage) | Vf 72*66
#define VSTR 66
#define H1_RAWK 0
#define H1_RAWV 8192
#define H1_KF   16384
#define H1_VF   20480
#define H1_TOT  (20480 + 72 * VSTR)   // 25232 u32 = 100928 bytes

// ---------------- ph2 smem (u32 indices) ----------------
#define H2_QF 0               // 2048: A-frags of Q tile (64 tokens)
#define H2_PS 2048            // 8192: B-frags of P
#define H2_CS 10240           // 9216: B-frags of ctx
#define H2_RS 19456           // 4608: fh-pair reduction buffer (floats)
#define H2_TOT 24064          // 96256 bytes

// =====================================================================
// Phase 1 (fp16 + movmatrix + cp.async pipeline, 256 thr, 2 CTAs/SM):
// CTA owns m-half mh; warp owns m-block [128*mh + 16w, +16).
// Tile t+1 gmem traffic overlaps tile t compute.
// =====================================================================
__global__ __launch_bounds__(256, 2) void ph1_kernel(
    const float* __restrict__ Kg, const float* __restrict__ Vg,
    const float* __restrict__ Pg)
{
    extern __shared__ __align__(16) uint32_t su[];
    uint32_t* Kf = su + H1_KF;
    uint32_t* Vf = su + H1_VF;
    uint32_t* Pstage = su + H1_KF;    // aliases Kf; dead after Pf reg load
    const float4* RawK4 = reinterpret_cast<const float4*>(su + H1_RAWK);
    const float4* RawV4 = reinterpret_cast<const float4*>(su + H1_RAWV);
    const uint32_t sbase = (uint32_t)__cvta_generic_to_shared(su);
    const uint32_t rawkB = sbase + H1_RAWK * 4;
    const uint32_t rawvB = sbase + H1_RAWV * 4;

    const int tid = threadIdx.x;
    const int w = tid >> 5, l = tid & 31;
    const int g = l >> 2, tg = l & 3;
    const int bh = blockIdx.y, sp = blockIdx.x, mh = blockIdx.z;

    const float4* Kb = reinterpret_cast<const float4*>(
        Kg + ((size_t)bh * NN + (size_t)sp * NCHUNK) * DD);
    const float4* Vb = reinterpret_cast<const float4*>(
        Vg + ((size_t)bh * NN + (size_t)sp * NCHUNK) * DD);

    // ---- kick tile 0 loads (overlap with P staging) ----
    #pragma unroll
    for (int k2 = 0; k2 < 8; k2++) {
        int idx = k2 * 256 + tid;
        cp_async16(rawkB + idx * 16, Kb + idx);
        cp_async16(rawvB + idx * 16, Vb + idx);
    }
    CP_COMMIT();

    // ---- stage this CTA's P half [128 m][64 d] as B-frags ----
    {
        const float4* P4 = reinterpret_cast<const float4*>(Pg) + mh * 2048;
        for (int i = tid; i < 2048; i += 256) {
            int mloc = i >> 4, d4 = i & 15;
            float4 x = P4[i];
            int slot = (mloc >> 3) * 4 + (d4 >> 2);
            int kk0 = (d4 & 3) * 4;
            int lane = (mloc & 7) * 4 + ((kk0 & 7) >> 1);
            int reg = kk0 >> 3;
            Pstage[slot * 64 + lane * 2 + reg] = pack_h2(x.x, x.y);
            Pstage[slot * 64 + (lane + 1) * 2 + reg] = pack_h2(x.z, x.w);
        }
    }
    __syncthreads();

    // ---- P fragments for this warp's 16-row m-block -> registers ----
    uint32_t Pf[4][2][2];
    #pragma unroll
    for (int k16 = 0; k16 < 4; k16++)
        #pragma unroll
        for (int j = 0; j < 2; j++) {
            int slot = (2 * w + j) * 4 + k16;
            uint2 b = *reinterpret_cast<const uint2*>(&Pstage[slot * 64 + l * 2]);
            Pf[k16][j][0] = b.x;
            Pf[k16][j][1] = b.y;
        }

    // ---- prefill Vf ksum slots (j=8): col e=64 -> 1.0, e=65..71 -> 0 ----
    for (int i = tid; i < 512; i += 256) {
        int s = i >> 6, pos = i & 63;
        int c = s >> 1, kp = s & 1;
        Vf[((c * 2 + kp) * 9 + 8) * VSTR + pos] = (pos < 8) ? 0x3C003C00u : 0u;
    }
    __syncthreads();   // Pstage reads done; Kf region free for conversion

    // ---- persistent ctx accumulators (16 m-rows) ----
    float ctx[9][4];
    #pragma unroll
    for (int j = 0; j < 9; j++)
        #pragma unroll
        for (int q = 0; q < 4; q++) ctx[j][q] = 0.0f;

    for (int t = 0; t < 4; t++) {
        CP_WAIT0();
        __syncthreads();   // raw tile ready everywhere; prev compute done

        // ---- convert raw K -> A-frags ----
        #pragma unroll
        for (int k2 = 0; k2 < 8; k2++) {
            int i = k2 * 256 + tid;
            int n = i >> 4, d4 = i & 15;
            float4 x = RawK4[i];
            int c = n >> 5, tf = (n >> 4) & 1, r = n & 15;
            int slot = (c * 4 + (d4 >> 2)) * 2 + tf;
            int kk0 = (d4 & 3) * 4;
            int lane = (r & 7) * 4 + ((kk0 & 7) >> 1);
            int reg = (r >> 3) + 2 * (kk0 >> 3);
            Kf[slot * 128 + lane * 4 + reg] = pack_h2(x.x, x.y);
            Kf[slot * 128 + (lane + 1) * 4 + reg] = pack_h2(x.z, x.w);
        }
        // ---- convert raw V -> B-frags (token-pair reads) ----
        #pragma unroll
        for (int k2 = 0; k2 < 4; k2++) {
            int i = k2 * 256 + tid;
            int p = i >> 4, d4 = i & 15;
            int c = p >> 4, kp = (p >> 3) & 1, kk2 = p & 7;
            int n0 = c * 32 + kp * 16 + kk2 * 2;
            float4 xa = RawV4[n0 * 16 + d4];
            float4 xb = RawV4[(n0 + 1) * 16 + d4];
            int tgv = kk2 & 3, regv = kk2 >> 2;
            float va[4] = { xa.x, xa.y, xa.z, xa.w };
            float vb2[4] = { xb.x, xb.y, xb.z, xb.w };
            #pragma unroll
            for (int e4 = 0; e4 < 4; e4++) {
                int e = 4 * d4 + e4;
                int j = e >> 3, gp = e & 7;
                Vf[((c * 2 + kp) * 9 + j) * VSTR + (gp * 4 + tgv) * 2 + regv] =
                    pack_h2(va[e4], vb2[e4]);
            }
        }
        __syncthreads();   // frags ready; raw consumed

        // ---- kick tile t+1 loads (overlap with compute below) ----
        if (t < 3) {
            #pragma unroll
            for (int k2 = 0; k2 < 8; k2++) {
                int idx = k2 * 256 + tid;
                cp_async16(rawkB + idx * 16, Kb + (t + 1) * 2048 + idx);
                cp_async16(rawvB + idx * 16, Vb + (t + 1) * 2048 + idx);
            }
            CP_COMMIT();
        }

        for (int c = 0; c < 4; c++) {
            // ---- G1: S[2 tf][2 j][4] = K_chunk @ P_blk^T ----
            float S[2][2][4];
            #pragma unroll
            for (int tf = 0; tf < 2; tf++)
                #pragma unroll
                for (int j = 0; j < 2; j++)
                    #pragma unroll
                    for (int q = 0; q < 4; q++) S[tf][j][q] = 0.0f;

            #pragma unroll
            for (int k16 = 0; k16 < 4; k16++) {
                #pragma unroll
                for (int tf = 0; tf < 2; tf++) {
                    uint4 av = *reinterpret_cast<const uint4*>(
                        &Kf[((c * 4 + k16) * 2 + tf) * 128 + l * 4]);
                    #pragma unroll
                    for (int j = 0; j < 2; j++)
                        mma16(S[tf][j], av.x, av.y, av.z, av.w,
                              Pf[k16][j][0], Pf[k16][j][1]);
                }
            }

            // ---- pack + packed gelu + in-register transpose ----
            uint32_t Tlo[2][2], Thi[2][2];
            #pragma unroll
            for (int tf = 0; tf < 2; tf++)
                #pragma unroll
                for (int j = 0; j < 2; j++) {
                    uint32_t lo = gelu_eps_h2(pack_h2(S[tf][j][0], S[tf][j][1]));
                    uint32_t hi = gelu_eps_h2(pack_h2(S[tf][j][2], S[tf][j][3]));
                    Tlo[tf][j] = movm(lo);
                    Thi[tf][j] = movm(hi);
                }

            // ---- MMA2: ctx += kp^T @ [V|1|0] ----
            #pragma unroll
            for (int kp = 0; kp < 2; kp++) {
                #pragma unroll
                for (int j = 0; j < 9; j++) {
                    uint2 b = *reinterpret_cast<const uint2*>(
                        &Vf[((c * 2 + kp) * 9 + j) * VSTR + l * 2]);
                    mma16(ctx[j], Tlo[kp][0], Tlo[kp][1], Thi[kp][0], Thi[kp][1], b.x, b.y);
                }
            }
        }
    }

    // ---- epilogue: write ctx partial rows [128mh+16w .. +16) ----
    float* dst = g_ctxp + ((size_t)(bh * NSPLIT + sp)) * MM * CW;
    {
        int m = mh * 128 + 16 * w + g;
        #pragma unroll
        for (int j = 0; j < 9; j++) {
            int col = j * 8 + 2 * tg;
            *reinterpret_cast<float2*>(&dst[(size_t)m * CW + col]) =
                make_float2(ctx[j][0], ctx[j][1]);
            *reinterpret_cast<float2*>(&dst[(size_t)(m + 8) * CW + col]) =
                make_float2(ctx[j][2], ctx[j][3]);
        }
    }
}

// =====================================================================
// Reduce: fixed-order sum of 8 split partials (256 blocks)
// =====================================================================
__global__ __launch_bounds__(256) void reduce_kernel()
{
    const int b = blockIdx.x;           // 0..255
    const int bh = b >> 2, q = b & 3;
    const float* src = g_ctxp + (size_t)bh * NSPLIT * MM * CW + q * 4608;
    float* dst = g_ctx + (size_t)bh * MM * CW + q * 4608;
    for (int i = threadIdx.x; i < 4608; i += 256) {
        float s = 0.0f;
        #pragma unroll
        for (int sp = 0; sp < NSPLIT; sp++) s += src[(size_t)sp * MM * CW + i];
        dst[i] = s;
    }
}

// =====================================================================
// Phase 2 (fp16, 256 thr, 2 CTAs/SM, register-prefetched Q): CTA owns
// token-half th (256 tokens, 4 tiles x 64). Warp (tf=w&3, fh=w>>2 k-split).
// =====================================================================
__global__ __launch_bounds__(256, 2) void ph2_kernel(
    const float* __restrict__ Qg, const float* __restrict__ Pg,
    float* __restrict__ Og)
{
    extern __shared__ __align__(16) uint32_t su[];
    uint32_t* Qf  = su + H2_QF;
    uint32_t* Ps  = su + H2_PS;
    uint32_t* Cs  = su + H2_CS;
    float* Rs = reinterpret_cast<float*>(su + H2_RS);

    const int tid = threadIdx.x;
    const int w = tid >> 5, l = tid & 31;
    const int g = l >> 2, tg = l & 3;
    const int bh = blockIdx.y, sp = blockIdx.x, th = blockIdx.z;

    const float4* Qb = reinterpret_cast<const float4*>(
        Qg + ((size_t)bh * NN + (size_t)sp * NCHUNK + (size_t)th * 256) * DD);

    // ---- prefetch Q tile 0 into registers (overlaps staging below) ----
    float4 qpre[4];
    #pragma unroll
    for (int k2 = 0; k2 < 4; k2++) qpre[k2] = Qb[k2 * 256 + tid];

    // ---- stage P as B-frags ----
    {
        const float4* P4 = reinterpret_cast<const float4*>(Pg);
        for (int i = tid; i < 4096; i += 256) {
            int m = i >> 4, d4 = i & 15;
            float4 x = P4[i];
            int slot = (m >> 3) * 4 + (d4 >> 2);
            int kk0 = (d4 & 3) * 4;
            int lane = (m & 7) * 4 + ((kk0 & 7) >> 1);
            int reg = kk0 >> 3;
            Ps[slot * 64 + lane * 2 + reg] = pack_h2(x.x, x.y);
            Ps[slot * 64 + (lane + 1) * 2 + reg] = pack_h2(x.z, x.w);
        }
    }
    // ---- stage ctx [256 f][72 e] as B-frags (pack f-pairs) ----
    {
        const float* Cg = g_ctx + (size_t)bh * MM * CW;
        for (int i = tid; i < 9216; i += 256) {
            int e = i % 72, fp = i / 72;
            int f = fp * 2;
            float lo = Cg[f * CW + e], hi = Cg[(f + 1) * CW + e];
            int c = f >> 6, kf = (f & 63) >> 4, kk = f & 15;   // kk even
            int j = e >> 3, gp = e & 7;
            int idx = ((c * 4 + kf) * 9 + j) * 64 + (gp * 4 + ((kk & 7) >> 1)) * 2 + (kk >> 3);
            Cs[idx] = pack_h2(lo, hi);
        }
    }
    __syncthreads();

    const int tf = w & 3;          // token group (16 rows in 64-token tile)
    const int fh = w >> 2;         // feature half (k-split group)

    for (int t = 0; t < 4; t++) {
        if (t) __syncthreads();     // protect Qf/Rs reuse across tiles

        // ---- stage prefetched Q tile as A-frags ----
        #pragma unroll
        for (int k2 = 0; k2 < 4; k2++) {
            int i = k2 * 256 + tid;
            int n = i >> 4, d4 = i & 15;
            float4 x = qpre[k2];
            int slot = (n >> 4) * 4 + (d4 >> 2);
            int kk0 = (d4 & 3) * 4;
            int r = n & 15;
            int lane = (r & 7) * 4 + ((kk0 & 7) >> 1);
            int reg = (r >> 3) + 2 * (kk0 >> 3);
            Qf[slot * 128 + lane * 4 + reg] = pack_h2(x.x, x.y);
            Qf[slot * 128 + (lane + 1) * 4 + reg] = pack_h2(x.z, x.w);
        }
        __syncthreads();

        // ---- prefetch next Q tile (LDGs retire during compute) ----
        if (t < 3) {
            #pragma unroll
            for (int k2 = 0; k2 < 4; k2++)
                qpre[k2] = Qb[(t + 1) * 1024 + k2 * 256 + tid];
        }

        float out[9][4];
        #pragma unroll
        for (int j = 0; j < 9; j++)
            #pragma unroll
            for (int q = 0; q < 4; q++) out[j][q] = 0.0f;

        for (int c = 0; c < 4; c++) {
            // ---- G3: S[4 j][4] = Q(tf rows) @ P^T (this warp's 32 feats) ----
            float S[4][4];
            #pragma unroll
            for (int j = 0; j < 4; j++)
                #pragma unroll
                for (int q = 0; q < 4; q++) S[j][q] = 0.0f;

            #pragma unroll
            for (int k16 = 0; k16 < 4; k16++) {
                uint4 av = *reinterpret_cast<const uint4*>(
                    &Qf[(tf * 4 + k16) * 128 + l * 4]);
                #pragma unroll
                for (int j = 0; j < 4; j++) {
                    int ngrp = c * 8 + fh * 4 + j;
                    uint2 b = *reinterpret_cast<const uint2*>(
                        &Ps[(ngrp * 4 + k16) * 64 + l * 2]);
                    mma16(S[j], av.x, av.y, av.z, av.w, b.x, b.y);
                }
            }

            // ---- packed gelu -> A-frags in registers; G4 over warp's k16s ----
            #pragma unroll
            for (int kfl = 0; kfl < 2; kfl++) {
                int jlo = 2 * kfl, jhi = 2 * kfl + 1;
                uint32_t a0 = gelu_eps_h2(pack_h2(S[jlo][0], S[jlo][1]));
                uint32_t a1 = gelu_eps_h2(pack_h2(S[jlo][2], S[jlo][3]));
                uint32_t a2 = gelu_eps_h2(pack_h2(S[jhi][0], S[jhi][1]));
                uint32_t a3 = gelu_eps_h2(pack_h2(S[jhi][2], S[jhi][3]));
                int kf = fh * 2 + kfl;
                #pragma unroll
                for (int j = 0; j < 9; j++) {
                    uint2 b = *reinterpret_cast<const uint2*>(
                        &Cs[((c * 4 + kf) * 9 + j) * 64 + l * 2]);
                    mma16(out[j], a0, a1, a2, a3, b.x, b.y);
                }
            }
        }

        // ---- merge fh pair: fh=1 stores partials, fh=0 adds + epilogue ----
        if (fh == 1) {
            #pragma unroll
            for (int j = 0; j < 9; j++)
                *reinterpret_cast<float4*>(&Rs[((j * 4 + tf) * 32 + l) * 4]) =
                    make_float4(out[j][0], out[j][1], out[j][2], out[j][3]);
        }
        __syncthreads();
        if (fh == 0) {
            #pragma unroll
            for (int j = 0; j < 9; j++) {
                float4 r = *reinterpret_cast<const float4*>(&Rs[((j * 4 + tf) * 32 + l) * 4]);
                out[j][0] += r.x; out[j][1] += r.y; out[j][2] += r.z; out[j][3] += r.w;
            }
            // denominator (col 64 = j 8, elems 0/2 at tg==0) -> broadcast
            float d0 = __shfl_sync(0xffffffffu, out[8][0], l & ~3);
            float d1 = __shfl_sync(0xffffffffu, out[8][2], l & ~3);
            float di0 = 1.0f / d0, di1 = 1.0f / d1;
            float* dst = Og + ((size_t)bh * NN + (size_t)sp * NCHUNK
                               + (size_t)th * 256 + (size_t)t * 64 + tf * 16 + g) * DD;
            #pragma unroll
            for (int j = 0; j < 8; j++) {
                int col = j * 8 + 2 * tg;
                *reinterpret_cast<float2*>(&dst[col]) =
                    make_float2(out[j][0] * di0, out[j][1] * di0);
                *reinterpret_cast<float2*>(&dst[(size_t)8 * DD + col]) =
                    make_float2(out[j][2] * di1, out[j][3] * di1);
            }
        }
    }
}

// =====================================================================
// launch
// =====================================================================
extern "C" void kernel_launch(void* const* d_in, const int* in_sizes, int n_in,
                              void* d_out, int out_size)
{
    const float* q    = (const float*)d_in[0];
    const float* k    = (const float*)d_in[1];
    const float* v    = (const float*)d_in[2];
    const float* proj = (const float*)d_in[3];
    float* out = (float*)d_out;

    cudaFuncSetAttribute(ph1_kernel, cudaFuncAttributeMaxDynamicSharedMemorySize, H1_TOT * 4);
    cudaFuncSetAttribute(ph2_kernel, cudaFuncAttributeMaxDynamicSharedMemorySize, H2_TOT * 4);

    ph1_kernel<<<dim3(NSPLIT, BH, 2), 256, H1_TOT * 4>>>(k, v, proj);
    reduce_kernel<<<BH * 4, 256>>>();
    ph2_kernel<<<dim3(NSPLIT, BH, 2), 256, H2_TOT * 4>>>(q, proj, out);
}